// round 7
// baseline (speedup 1.0000x reference)
#include <cuda_runtime.h>
#include <cuda_fp16.h>
#include <cstdint>

// Problem constants
constexpr int CB  = 2;     // batch
constexpr int CL  = 4096;  // seq len
constexpr int CDM = 768;   // d_model
constexpr int CDI = 1536;  // d_inner
constexpr int CN  = 16;    // state dim
constexpr int CR  = 48;    // dt rank
constexpr int CK  = 4;     // conv width
constexpr int CPROJ = CR + 2*CN; // 80

// ---------------------------------------------------------------------------
// Scratch (device globals; no runtime allocation allowed)
// ---------------------------------------------------------------------------
__device__ float g_xz[CB * 2 * CDI * CL];        // (b, e, l)
__device__ float g_dbl[2][CB * CL * CPROJ];      // per dir, (b*L, 80): dt|B|C
__device__ float g_delta[2][CB * CL * CDI];      // per dir, post-softplus
__device__ float g_y[2][CB * CL * CDI];          // per dir, scan out (+D*x)

// fp16 operands for tensor GEMMs
__device__ __half g_hid_h[CB*CL*CDM], g_hid_l[CB*CL*CDM];  // hidden hi/lo (split side)
__device__ __half g_w1[2*CDI*CDM];                          // in_proj W (single)
__device__ __half g_w2[CDM*CDI];                            // out_proj W (single)
__device__ __half g_wx[2][128*CDI];                         // xproj W padded 80->128 (single)
__device__ __half g_xth[2][CB*CL*CDI], g_xtl[2][CB*CL*CDI]; // conv out hi/lo (split side)
__device__ __half g_cmb_h[CB*CL*CDI],  g_cmb_l[CB*CL*CDI];  // gated sum hi/lo (split side)

// ---------------------------------------------------------------------------
// PTX helpers
// ---------------------------------------------------------------------------
__device__ __forceinline__ uint32_t smem_u32(const void* p) {
    uint32_t a;
    asm("{ .reg .u64 t; cvta.to.shared.u64 t, %1; cvt.u32.u64 %0, t; }" : "=r"(a) : "l"(p));
    return a;
}
__device__ __forceinline__ uint32_t sw128(uint32_t b) { return b ^ ((b >> 3) & 0x70); }

__device__ __forceinline__ void ldsm4(uint32_t addr, uint32_t r[4]) {
    asm volatile("ldmatrix.sync.aligned.m8n8.x4.shared.b16 {%0,%1,%2,%3}, [%4];"
        : "=r"(r[0]), "=r"(r[1]), "=r"(r[2]), "=r"(r[3]) : "r"(addr));
}
__device__ __forceinline__ void mma_f16(float* d, const uint32_t* a, uint32_t b0, uint32_t b1) {
    asm volatile("mma.sync.aligned.m16n8k16.row.col.f32.f16.f16.f32 "
        "{%0,%1,%2,%3}, {%4,%5,%6,%7}, {%8,%9}, {%0,%1,%2,%3};"
        : "+f"(d[0]), "+f"(d[1]), "+f"(d[2]), "+f"(d[3])
        : "r"(a[0]), "r"(a[1]), "r"(a[2]), "r"(a[3]), "r"(b0), "r"(b1));
}
__device__ __forceinline__ void cp16(uint32_t s, const void* g) {
    asm volatile("cp.async.ca.shared.global [%0], [%1], 16;" :: "r"(s), "l"(g));
}

// ---------------------------------------------------------------------------
// 2-term fp16 tensor GEMM:  C[m,n] = sum_k A[m,k]*B[n,k]  (fp32 out)
// Exactly one operand side is split (hi+lo fp16); the other is single fp16.
// CTA tile 128x128, BK=64, 2-stage cp.async ring, 96KB smem -> 2 CTA/SM.
// Stage (48KB): A-hi 16K | split-lo 16K | B-hi 16K.
// ---------------------------------------------------------------------------
constexpr int GF_STAGE = 49152;
constexpr int GF_SMEM  = 2 * GF_STAGE;   // 98304 B

template <int SPLIT_A>
__global__ void __launch_bounds__(256, 2) gemm_f16_kernel(
    const __half* __restrict__ Ah, const __half* __restrict__ Xl,  // Xl = Al or Bl
    const __half* __restrict__ Bh,
    float* __restrict__ C, int Nout, int Kd,
    long long strideA, long long strideB, long long strideC, int NC)
{
    extern __shared__ __align__(1024) char smem[];
    const uint32_t su = smem_u32(smem);
    Ah += (size_t)blockIdx.z * strideA;
    Bh += (size_t)blockIdx.z * strideB;
    Xl += (size_t)blockIdx.z * (SPLIT_A ? strideA : strideB);
    C  += (size_t)blockIdx.z * strideC;
    const int bm = blockIdx.y * 128;
    const int bn = blockIdx.x * 128;
    const int tid  = threadIdx.x;
    const int wid  = tid >> 5;
    const int lane = tid & 31;

    const int prow = tid >> 3;          // 0..31 -> x4 gives 128 rows
    const int pkc  = tid & 7;           // 16B chunk within 128B row
    auto issue = [&](int c) {
        const uint32_t sb = su + (uint32_t)(c & 1) * GF_STAGE;
        const int k0 = c * 64;
#pragma unroll
        for (int i = 0; i < 4; ++i) {
            const int row = prow + i * 32;
            const uint32_t off = sw128((uint32_t)(row * 128 + pkc * 16));
            const size_t ga = (size_t)(bm + row) * Kd + k0 + pkc * 8;
            const size_t gb = (size_t)(bn + row) * Kd + k0 + pkc * 8;
            cp16(sb + off,         Ah + ga);
            cp16(sb + 16384 + off, Xl + (SPLIT_A ? ga : gb));
            cp16(sb + 32768 + off, Bh + gb);
        }
        asm volatile("cp.async.commit_group;" ::: "memory");
    };

    // warp tiling: 4x2 warps, warp tile 32 (m) x 64 (n)
    const int m0 = (wid & 3) * 32;
    const int n0 = (wid >> 2) * 64;
    const int g    = lane >> 3;
    const int lr   = lane & 7;
    const int lrow = (g & 1) * 8 + lr;
    const int lkb  = (g >> 1) * 16;

    float acc[2][8][4] = {};

    issue(0); issue(1);

    for (int c = 0; c < NC; ++c) {
        asm volatile("cp.async.wait_group 1;" ::: "memory");
        __syncthreads();
        const uint32_t sb = su + (uint32_t)(c & 1) * GF_STAGE;
#pragma unroll
        for (int kk = 0; kk < 4; ++kk) {
            uint32_t ah[2][4], al[2][4];
#pragma unroll
            for (int mt = 0; mt < 2; ++mt) {
                uint32_t off = sw128((uint32_t)((m0 + mt*16 + lrow) * 128 + kk*32 + lkb));
                ldsm4(sb + off, ah[mt]);
                if (SPLIT_A) ldsm4(sb + 16384 + off, al[mt]);
            }
#pragma unroll
            for (int np = 0; np < 4; ++np) {
                uint32_t boff = sw128((uint32_t)((n0 + np*16 + lrow) * 128 + kk*32 + lkb));
                uint32_t bh[4], bl[4];
                ldsm4(sb + 32768 + boff, bh);
                if (!SPLIT_A) ldsm4(sb + 16384 + boff, bl);
#pragma unroll
                for (int mt = 0; mt < 2; ++mt) {
                    if (SPLIT_A) {
                        mma_f16(acc[mt][2*np],   ah[mt], bh[0], bh[2]);
                        mma_f16(acc[mt][2*np],   al[mt], bh[0], bh[2]);
                        mma_f16(acc[mt][2*np+1], ah[mt], bh[1], bh[3]);
                        mma_f16(acc[mt][2*np+1], al[mt], bh[1], bh[3]);
                    } else {
                        mma_f16(acc[mt][2*np],   ah[mt], bh[0], bh[2]);
                        mma_f16(acc[mt][2*np],   ah[mt], bl[0], bl[2]);
                        mma_f16(acc[mt][2*np+1], ah[mt], bh[1], bh[3]);
                        mma_f16(acc[mt][2*np+1], ah[mt], bl[1], bl[3]);
                    }
                }
            }
        }
        __syncthreads();
        if (c + 2 < NC) issue(c + 2);
        else asm volatile("cp.async.commit_group;" ::: "memory");
    }

    // epilogue
    const int er = lane >> 2;
    const int ec = (lane & 3) * 2;
#pragma unroll
    for (int mt = 0; mt < 2; ++mt) {
#pragma unroll
        for (int nt = 0; nt < 8; ++nt) {
            const int row = bm + m0 + mt*16 + er;
            const int col = bn + n0 + nt*8 + ec;
            if (col < Nout) {
                float2 lo = { acc[mt][nt][0], acc[mt][nt][1] };
                float2 hi = { acc[mt][nt][2], acc[mt][nt][3] };
                *(float2*)(C + (size_t)row * Nout + col)       = lo;
                *(float2*)(C + (size_t)(row + 8) * Nout + col) = hi;
            }
        }
    }
}

// ---------------------------------------------------------------------------
// fp32 -> fp16 hi/lo splitter and single-fp16 converter (grid-stride, float4)
// ---------------------------------------------------------------------------
__global__ void split2_kernel(const float* __restrict__ s,
                              __half* __restrict__ h, __half* __restrict__ l, int n4)
{
    for (int i = blockIdx.x * blockDim.x + threadIdx.x; i < n4;
         i += gridDim.x * blockDim.x) {
        float4 v = ((const float4*)s)[i];
        __half hx = __float2half_rn(v.x), hy = __float2half_rn(v.y);
        __half hz = __float2half_rn(v.z), hw = __float2half_rn(v.w);
        __half lx = __float2half_rn(v.x - __half2float(hx));
        __half ly = __float2half_rn(v.y - __half2float(hy));
        __half lz = __float2half_rn(v.z - __half2float(hz));
        __half lw = __float2half_rn(v.w - __half2float(hw));
        __half2 h01 = __halves2half2(hx, hy), h23 = __halves2half2(hz, hw);
        __half2 l01 = __halves2half2(lx, ly), l23 = __halves2half2(lz, lw);
        ((uint2*)h)[i] = make_uint2(*(uint32_t*)&h01, *(uint32_t*)&h23);
        ((uint2*)l)[i] = make_uint2(*(uint32_t*)&l01, *(uint32_t*)&l23);
    }
}

__global__ void tof16_kernel(const float* __restrict__ s, __half* __restrict__ h, int n4)
{
    for (int i = blockIdx.x * blockDim.x + threadIdx.x; i < n4;
         i += gridDim.x * blockDim.x) {
        float4 v = ((const float4*)s)[i];
        __half2 h01 = __halves2half2(__float2half_rn(v.x), __float2half_rn(v.y));
        __half2 h23 = __halves2half2(__float2half_rn(v.z), __float2half_rn(v.w));
        ((uint2*)h)[i] = make_uint2(*(uint32_t*)&h01, *(uint32_t*)&h23);
    }
}

// xproj weights: pad 80 -> 128 rows (zeros), single fp16, both dirs.
__global__ void padw_kernel(const float* __restrict__ wf, const float* __restrict__ wb)
{
    const int total4 = 2 * 128 * CDI / 4;
    for (int i = blockIdx.x * blockDim.x + threadIdx.x; i < total4;
         i += gridDim.x * blockDim.x) {
        int e = i * 4;
        int dir = e / (128 * CDI);
        int rem = e - dir * 128 * CDI;
        int row = rem / CDI;
        int k   = rem - row * CDI;
        float4 v = {0.f, 0.f, 0.f, 0.f};
        const float* W = dir ? wb : wf;
        if (row < CPROJ) v = *(const float4*)(W + (size_t)row * CDI + k);
        __half2 h01 = __halves2half2(__float2half_rn(v.x), __float2half_rn(v.y));
        __half2 h23 = __halves2half2(__float2half_rn(v.z), __float2half_rn(v.w));
        ((uint2*)&g_wx[0][0])[i] = make_uint2(*(uint32_t*)&h01, *(uint32_t*)&h23);
    }
}

// ---------------------------------------------------------------------------
// Depthwise causal conv (K=4) + bias + SiLU, transpose to (b,t,d).
// ---------------------------------------------------------------------------
__global__ void __launch_bounds__(256) conv_silu_kernel(
    const float* __restrict__ cw_f, const float* __restrict__ cb_f,
    const float* __restrict__ cw_b, const float* __restrict__ cb_b)
{
    const int t0 = blockIdx.x * 128;
    const int d0 = blockIdx.y * 32;
    const int b   = blockIdx.z & 1;
    const int dir = blockIdx.z >> 1;

    __shared__ float xs[32][133];

    const float* xbase = g_xz + ((size_t)b * (2*CDI) + d0) * CL;
    const int base = (dir == 0) ? (t0 - 3) : (CL - 128 - t0);

    const int lane = threadIdx.x & 31;
    const int wy   = threadIdx.x >> 5;
    for (int d = wy; d < 32; d += 8) {
        const float* row = xbase + (size_t)d * CL;
        for (int i = lane; i < 131; i += 32) {
            int u = base + i;
            xs[d][i] = (u >= 0 && u < CL) ? row[u] : 0.f;
        }
    }
    __syncthreads();

    const int d  = threadIdx.x & 31;
    const int sg = threadIdx.x >> 5;
    const float* cw = dir ? cw_b : cw_f;
    const float* cb = dir ? cb_b : cb_f;
    const float w0 = cw[(d0+d)*CK + 0];
    const float w1 = cw[(d0+d)*CK + 1];
    const float w2 = cw[(d0+d)*CK + 2];
    const float w3 = cw[(d0+d)*CK + 3];
    const float bias = cb[d0+d];

    __half* oh = g_xth[dir] + (size_t)b * CL * CDI;
    __half* ol = g_xtl[dir] + (size_t)b * CL * CDI;
#pragma unroll
    for (int q = 0; q < 16; ++q) {
        int s = sg + 8*q;
        float v;
        if (dir == 0) {
            v = w0*xs[d][s] + w1*xs[d][s+1] + w2*xs[d][s+2] + w3*xs[d][s+3] + bias;
        } else {
            v = w3*xs[d][127-s] + w2*xs[d][127-s+1] + w1*xs[d][127-s+2] + w0*xs[d][127-s+3] + bias;
        }
        float sv = v / (1.f + __expf(-v));
        size_t idx = (size_t)(t0 + s) * CDI + d0 + d;
        __half hb = __float2half_rn(sv);
        oh[idx] = hb;
        ol[idx] = __float2half_rn(sv - __half2float(hb));
    }
}

// ---------------------------------------------------------------------------
// dtproj + softplus (round-5 version — no software pipeline; regs stay ~66)
// ---------------------------------------------------------------------------
__device__ __forceinline__ float softplus_f(float v) {
    return (v > 20.f) ? v : log1pf(__expf(v));
}

__global__ void __launch_bounds__(256) dtproj_kernel(
    const float* __restrict__ dtw_f, const float* __restrict__ dtb_f,
    const float* __restrict__ dtw_b, const float* __restrict__ dtb_b)
{
    const int dir = blockIdx.z;
    const float* W    = dir ? dtw_b : dtw_f;
    const float* bias = dir ? dtb_b : dtb_f;
    const float* DT = g_dbl[dir];
    float* O = g_delta[dir];

    const int r0 = blockIdx.x * 64;
    const int d0 = blockIdx.y * 128;

    __shared__ __align__(16) float Ts[48][64];
    __shared__ __align__(16) float Ws2[48][128];

    const int tid = threadIdx.x;
#pragma unroll
    for (int p = 0; p < 3; ++p) {
        int q = tid + p*256;
        int rr = q / 12, kk = (q % 12) * 4;
        float4 v = *(const float4*)(DT + (size_t)(r0+rr)*CPROJ + kk);
        Ts[kk+0][rr]=v.x; Ts[kk+1][rr]=v.y; Ts[kk+2][rr]=v.z; Ts[kk+3][rr]=v.w;
    }
#pragma unroll
    for (int p = 0; p < 6; ++p) {
        int q = tid + p*256;
        int dd = q / 12, kk = (q % 12) * 4;
        float4 v = *(const float4*)(W + (size_t)(d0+dd)*CR + kk);
        Ws2[kk+0][dd]=v.x; Ws2[kk+1][dd]=v.y; Ws2[kk+2][dd]=v.z; Ws2[kk+3][dd]=v.w;
    }
    __syncthreads();

    const int tx = tid & 31;
    const int ty = tid >> 5;
    float acc[8][4] = {};
#pragma unroll
    for (int k = 0; k < 48; ++k) {
        float4 a0 = *(const float4*)&Ts[k][ty*8];
        float4 a1 = *(const float4*)&Ts[k][ty*8+4];
        float a[8] = {a0.x,a0.y,a0.z,a0.w,a1.x,a1.y,a1.z,a1.w};
        float4 w = *(const float4*)&Ws2[k][tx*4];
        float ww[4] = {w.x, w.y, w.z, w.w};
#pragma unroll
        for (int i = 0; i < 8; ++i)
#pragma unroll
            for (int j = 0; j < 4; ++j)
                acc[i][j] = fmaf(a[i], ww[j], acc[i][j]);
    }

    const int tx4 = tx*4;
    float b0 = bias[d0+tx4+0], b1 = bias[d0+tx4+1], b2 = bias[d0+tx4+2], b3 = bias[d0+tx4+3];
#pragma unroll
    for (int i = 0; i < 8; ++i) {
        float4 v;
        v.x = softplus_f(acc[i][0] + b0);
        v.y = softplus_f(acc[i][1] + b1);
        v.z = softplus_f(acc[i][2] + b2);
        v.w = softplus_f(acc[i][3] + b3);
        *(float4*)(O + (size_t)(r0 + ty*8 + i)*CDI + d0 + tx4) = v;
    }
}

// ---------------------------------------------------------------------------
// Selective scan (warp = 2 channels x 16 states).
// Packed staging: sdd = (dt, dt*x) float2, sbc = (B, C) float2, sxD = x*D.
// Inner step: 2x LDS.64 + exp + 2 flops + 4 shfl-add + predicated D-add/store.
// ---------------------------------------------------------------------------
__global__ void __launch_bounds__(256) scan_kernel(
    const float* __restrict__ Alog_f, const float* __restrict__ Dv_f,
    const float* __restrict__ Alog_b, const float* __restrict__ Dv_b)
{
    const int dir = blockIdx.z;
    const int b   = blockIdx.y;
    const int d0  = blockIdx.x * 16;

    const float* Alog = dir ? Alog_b : Alog_f;
    const float* Dvec = dir ? Dv_b   : Dv_f;
    const float* delta = g_delta[dir] + (size_t)b * CL * CDI;
    const __half* xth  = g_xth[dir]   + (size_t)b * CL * CDI;
    const __half* xtl  = g_xtl[dir]   + (size_t)b * CL * CDI;
    const float* dbl   = g_dbl[dir]   + (size_t)b * CL * CPROJ;
    float* yout        = g_y[dir]     + (size_t)b * CL * CDI;

    __shared__ __align__(16) float2 sdd[64][16];   // (dt, dt*x)
    __shared__ __align__(16) float2 sbc[64][16];   // (B, C)
    __shared__ __align__(16) float  sxD[64][16];   // x * D[d]

    const int tid  = threadIdx.x;
    const int lane = tid & 31;
    const int wid  = tid >> 5;
    const int half = lane >> 4;
    const int n    = lane & 15;
    const int ch   = wid*2 + half;
    const int d    = d0 + ch;

    const float Aval = -__expf(Alog[d*CN + n]);
    float h = 0.f;

    const int li = tid >> 2;          // staging row 0..63
    const int lj = (tid & 3) * 4;     // staging cols 0,4,8,12

    // per-staging-thread D values (loaded once)
    float rDv[4];
#pragma unroll
    for (int j = 0; j < 4; ++j) rDv[j] = Dvec[d0 + lj + j];

    float4 rd, rB, rC, rx;
    auto LD = [&](int t0) {
        rd = *(const float4*)(delta + (size_t)(t0+li)*CDI + d0 + lj);
        uint2 xh = *(const uint2*)(xth + (size_t)(t0+li)*CDI + d0 + lj);
        uint2 xl = *(const uint2*)(xtl + (size_t)(t0+li)*CDI + d0 + lj);
        __half2 h01 = *(__half2*)&xh.x, h23 = *(__half2*)&xh.y;
        __half2 l01 = *(__half2*)&xl.x, l23 = *(__half2*)&xl.y;
        float2 fh01 = __half22float2(h01), fh23 = __half22float2(h23);
        float2 fl01 = __half22float2(l01), fl23 = __half22float2(l23);
        rx.x = fh01.x + fl01.x; rx.y = fh01.y + fl01.y;
        rx.z = fh23.x + fl23.x; rx.w = fh23.y + fl23.y;
        rB = *(const float4*)(dbl + (size_t)(t0+li)*CPROJ + CR + lj);
        rC = *(const float4*)(dbl + (size_t)(t0+li)*CPROJ + CR + CN + lj);
    };
    LD(0);

    const int NCH = CL / 64;
    for (int c = 0; c < NCH; ++c) {
        __syncthreads();
        {
            float dt4[4] = {rd.x, rd.y, rd.z, rd.w};
            float x4[4]  = {rx.x, rx.y, rx.z, rx.w};
            float B4[4]  = {rB.x, rB.y, rB.z, rB.w};
            float C4[4]  = {rC.x, rC.y, rC.z, rC.w};
#pragma unroll
            for (int j = 0; j < 4; ++j) {
                sdd[li][lj+j] = make_float2(dt4[j], dt4[j] * x4[j]);
                sbc[li][lj+j] = make_float2(B4[j], C4[j]);
                sxD[li][lj+j] = x4[j] * rDv[j];
            }
        }
        __syncthreads();
        if (c + 1 < NCH) LD((c+1) * 64);

        const int tbase = c * 64;
#pragma unroll 8
        for (int s = 0; s < 64; ++s) {
            float2 ddt = sdd[s][ch];
            float2 bc  = sbc[s][n];
            float a = __expf(ddt.x * Aval);
            h = fmaf(a, h, ddt.y * bc.x);
            float p = h * bc.y;
            p += __shfl_xor_sync(0xffffffffu, p, 8);
            p += __shfl_xor_sync(0xffffffffu, p, 4);
            p += __shfl_xor_sync(0xffffffffu, p, 2);
            p += __shfl_xor_sync(0xffffffffu, p, 1);
            if (n == 0)
                yout[(size_t)(tbase + s)*CDI + d] = p + sxD[s][ch];
        }
    }
}

// ---------------------------------------------------------------------------
// Gate + direction merge -> fp16 hi/lo comb (out_proj split operand)
// ---------------------------------------------------------------------------
__global__ void __launch_bounds__(256) combine_kernel()
{
    const int l0 = blockIdx.x * 32;
    const int d0 = blockIdx.y * 32;
    const int b  = blockIdx.z;

    __shared__ float zs[32][33];
    const int lane = threadIdx.x & 31;
    const int wy   = threadIdx.x >> 5;

    const float* zbase = g_xz + ((size_t)b * (2*CDI) + CDI + d0) * CL;
    for (int dd = wy; dd < 32; dd += 8)
        zs[dd][lane] = zbase[(size_t)dd * CL + l0 + lane];
    __syncthreads();

#pragma unroll
    for (int q = 0; q < 4; ++q) {
        int lr = wy + 8*q;
        int l = l0 + lr;
        size_t idx  = ((size_t)b*CL + l)*CDI + d0 + lane;
        size_t idxr = ((size_t)b*CL + (CL-1-l))*CDI + d0 + lane;
        float yf = g_y[0][idx];
        float yb = g_y[1][idxr];
        float zv = zs[lane][lr];
        float s = zv / (1.f + __expf(-zv));
        float cv = (yf + yb) * s;
        __half hb = __float2half_rn(cv);
        g_cmb_h[idx] = hb;
        g_cmb_l[idx] = __float2half_rn(cv - __half2float(hb));
    }
}

// ---------------------------------------------------------------------------
// Launcher
// ---------------------------------------------------------------------------
extern "C" void kernel_launch(void* const* d_in, const int* in_sizes, int n_in,
                              void* d_out, int out_size)
{
    (void)in_sizes; (void)n_in; (void)out_size;

    const float* hidden  = (const float*)d_in[0];
    const float* in_w    = (const float*)d_in[1];
    const float* conv_w  = (const float*)d_in[2];
    const float* conv_b  = (const float*)d_in[3];
    const float* xproj_w = (const float*)d_in[4];
    const float* dtw     = (const float*)d_in[5];
    const float* dtb     = (const float*)d_in[6];
    const float* A_log   = (const float*)d_in[7];
    const float* Dv      = (const float*)d_in[8];
    const float* conv_w2 = (const float*)d_in[9];
    const float* conv_b2 = (const float*)d_in[10];
    const float* xproj_w2= (const float*)d_in[11];
    const float* dtw2    = (const float*)d_in[12];
    const float* dtb2    = (const float*)d_in[13];
    const float* A_log2  = (const float*)d_in[14];
    const float* Dv2     = (const float*)d_in[15];
    const float* out_w   = (const float*)d_in[16];

    void *p_xz, *p_dbl;
    void *p_hid_h, *p_hid_l, *p_w1, *p_w2, *p_wx, *p_xth, *p_xtl, *p_cmb_h, *p_cmb_l;
    cudaGetSymbolAddress(&p_xz, g_xz);
    cudaGetSymbolAddress(&p_dbl, g_dbl);
    cudaGetSymbolAddress(&p_hid_h, g_hid_h);
    cudaGetSymbolAddress(&p_hid_l, g_hid_l);
    cudaGetSymbolAddress(&p_w1, g_w1);
    cudaGetSymbolAddress(&p_w2, g_w2);
    cudaGetSymbolAddress(&p_wx, g_wx);
    cudaGetSymbolAddress(&p_xth, g_xth);
    cudaGetSymbolAddress(&p_xtl, g_xtl);
    cudaGetSymbolAddress(&p_cmb_h, g_cmb_h);
    cudaGetSymbolAddress(&p_cmb_l, g_cmb_l);

    cudaFuncSetAttribute(gemm_f16_kernel<0>,
                         cudaFuncAttributeMaxDynamicSharedMemorySize, GF_SMEM);
    cudaFuncSetAttribute(gemm_f16_kernel<1>,
                         cudaFuncAttributeMaxDynamicSharedMemorySize, GF_SMEM);

    // 0) operand packing
    split2_kernel<<<1024, 256>>>(hidden, (__half*)p_hid_h, (__half*)p_hid_l, CB*CL*CDM/4);
    tof16_kernel<<<512, 256>>>(in_w, (__half*)p_w1, 2*CDI*CDM/4);
    tof16_kernel<<<512, 256>>>(out_w, (__half*)p_w2, CDM*CDI/4);
    padw_kernel<<<512, 256>>>(xproj_w, xproj_w2);

    // 1) in_proj: A = w1 (single), B = hidden (split).  M=3072, N=4096, K=768
    gemm_f16_kernel<0><<<dim3(CL/128, (2*CDI)/128, CB), 256, GF_SMEM>>>(
        (const __half*)p_w1, (const __half*)p_hid_l, (const __half*)p_hid_h,
        (float*)p_xz, CL, CDM,
        0, (long long)CL * CDM, (long long)(2*CDI) * CL, CDM / 64);

    // 2) conv + SiLU + transpose -> fp16 hi/lo xt
    conv_silu_kernel<<<dim3(CL/128, CDI/32, 2*CB), 256>>>(
        conv_w, conv_b, conv_w2, conv_b2);

    // 3) xproj: A = xt (split), B = wx (single).  M=8192 rows, N=80(pad128), K=1536
    gemm_f16_kernel<1><<<dim3(1, (CB*CL)/128, 2), 256, GF_SMEM>>>(
        (const __half*)p_xth, (const __half*)p_xtl, (const __half*)p_wx,
        (float*)p_dbl, CPROJ, CDI,
        (long long)CB*CL*CDI, (long long)128*CDI, (long long)CB*CL*CPROJ, CDI / 64);

    // 4) dtproj + softplus -> delta
    dtproj_kernel<<<dim3((CB*CL)/64, CDI/128, 2), 256>>>(dtw, dtb, dtw2, dtb2);

    // 5) selective scan
    scan_kernel<<<dim3(CDI/16, CB, 2), 256>>>(A_log, Dv, A_log2, Dv2);

    // 6) gate + direction merge -> fp16 hi/lo comb
    combine_kernel<<<dim3(CL/32, CDI/32, CB), 256>>>();

    // 7) out_proj: A = comb (split), B = w2 (single).  M=8192, N=768, K=1536
    gemm_f16_kernel<1><<<dim3(CDM/128, (CB*CL)/128, 1), 256, GF_SMEM>>>(
        (const __half*)p_cmb_h, (const __half*)p_cmb_l, (const __half*)p_w2,
        (float*)d_out, CDM, CDI,
        0, 0, 0, CDI / 64);
}

// round 8
// speedup vs baseline: 1.1062x; 1.1062x over previous
#include <cuda_runtime.h>
#include <cuda_fp16.h>
#include <cstdint>

// Problem constants
constexpr int CB  = 2;     // batch
constexpr int CL  = 4096;  // seq len
constexpr int CDM = 768;   // d_model
constexpr int CDI = 1536;  // d_inner
constexpr int CN  = 16;    // state dim
constexpr int CR  = 48;    // dt rank
constexpr int CK  = 4;     // conv width
constexpr int CPROJ = CR + 2*CN; // 80

// ---------------------------------------------------------------------------
// Scratch (device globals; no runtime allocation allowed)
// ---------------------------------------------------------------------------
__device__ float g_xz[CB * 2 * CDI * CL];        // (b, e, l)
__device__ float g_dbl[2][CB * CL * CPROJ];      // per dir, (b*L, 80): dt|B|C
__device__ float g_delta[2][CB * CL * CDI];      // per dir, post-softplus
__device__ float g_y[2][CB * CL * CDI];          // per dir, scan out (+D*x)

// fp16 operands for tensor GEMMs
__device__ __half g_hid_h[CB*CL*CDM], g_hid_l[CB*CL*CDM];  // hidden hi/lo (split side)
__device__ __half g_w1[2*CDI*CDM];                          // in_proj W (single)
__device__ __half g_w2[CDM*CDI];                            // out_proj W (single)
__device__ __half g_wx[2][128*CDI];                         // xproj W padded 80->128 (single)
__device__ __half g_xth[2][CB*CL*CDI], g_xtl[2][CB*CL*CDI]; // conv out hi/lo (split side)
__device__ __half g_cmb_h[CB*CL*CDI],  g_cmb_l[CB*CL*CDI];  // gated sum hi/lo (split side)

// ---------------------------------------------------------------------------
// PTX helpers
// ---------------------------------------------------------------------------
__device__ __forceinline__ uint32_t smem_u32(const void* p) {
    uint32_t a;
    asm("{ .reg .u64 t; cvta.to.shared.u64 t, %1; cvt.u32.u64 %0, t; }" : "=r"(a) : "l"(p));
    return a;
}
__device__ __forceinline__ uint32_t sw128(uint32_t b) { return b ^ ((b >> 3) & 0x70); }

__device__ __forceinline__ void ldsm4(uint32_t addr, uint32_t r[4]) {
    asm volatile("ldmatrix.sync.aligned.m8n8.x4.shared.b16 {%0,%1,%2,%3}, [%4];"
        : "=r"(r[0]), "=r"(r[1]), "=r"(r[2]), "=r"(r[3]) : "r"(addr));
}
__device__ __forceinline__ void mma_f16(float* d, const uint32_t* a, uint32_t b0, uint32_t b1) {
    asm volatile("mma.sync.aligned.m16n8k16.row.col.f32.f16.f16.f32 "
        "{%0,%1,%2,%3}, {%4,%5,%6,%7}, {%8,%9}, {%0,%1,%2,%3};"
        : "+f"(d[0]), "+f"(d[1]), "+f"(d[2]), "+f"(d[3])
        : "r"(a[0]), "r"(a[1]), "r"(a[2]), "r"(a[3]), "r"(b0), "r"(b1));
}
__device__ __forceinline__ void cp16(uint32_t s, const void* g) {
    asm volatile("cp.async.ca.shared.global [%0], [%1], 16;" :: "r"(s), "l"(g));
}

// ---------------------------------------------------------------------------
// 2-term fp16 tensor GEMM:  C[m,n] = sum_k A[m,k]*B[n,k]  (fp32 out)
// Exactly one operand side is split (hi+lo fp16); the other is single fp16.
// CTA tile 128x128, BK=64, 2-stage cp.async ring, 96KB smem -> 2 CTA/SM.
// Stage (48KB): A-hi 16K | split-lo 16K | B-hi 16K.
// ---------------------------------------------------------------------------
constexpr int GF_STAGE = 49152;
constexpr int GF_SMEM  = 2 * GF_STAGE;   // 98304 B

template <int SPLIT_A>
__global__ void __launch_bounds__(256, 2) gemm_f16_kernel(
    const __half* __restrict__ Ah, const __half* __restrict__ Xl,  // Xl = Al or Bl
    const __half* __restrict__ Bh,
    float* __restrict__ C, int Nout, int Kd,
    long long strideA, long long strideB, long long strideC, int NC)
{
    extern __shared__ __align__(1024) char smem[];
    const uint32_t su = smem_u32(smem);
    Ah += (size_t)blockIdx.z * strideA;
    Bh += (size_t)blockIdx.z * strideB;
    Xl += (size_t)blockIdx.z * (SPLIT_A ? strideA : strideB);
    C  += (size_t)blockIdx.z * strideC;
    const int bm = blockIdx.y * 128;
    const int bn = blockIdx.x * 128;
    const int tid  = threadIdx.x;
    const int wid  = tid >> 5;
    const int lane = tid & 31;

    const int prow = tid >> 3;          // 0..31 -> x4 gives 128 rows
    const int pkc  = tid & 7;           // 16B chunk within 128B row
    auto issue = [&](int c) {
        const uint32_t sb = su + (uint32_t)(c & 1) * GF_STAGE;
        const int k0 = c * 64;
#pragma unroll
        for (int i = 0; i < 4; ++i) {
            const int row = prow + i * 32;
            const uint32_t off = sw128((uint32_t)(row * 128 + pkc * 16));
            const size_t ga = (size_t)(bm + row) * Kd + k0 + pkc * 8;
            const size_t gb = (size_t)(bn + row) * Kd + k0 + pkc * 8;
            cp16(sb + off,         Ah + ga);
            cp16(sb + 16384 + off, Xl + (SPLIT_A ? ga : gb));
            cp16(sb + 32768 + off, Bh + gb);
        }
        asm volatile("cp.async.commit_group;" ::: "memory");
    };

    // warp tiling: 4x2 warps, warp tile 32 (m) x 64 (n)
    const int m0 = (wid & 3) * 32;
    const int n0 = (wid >> 2) * 64;
    const int g    = lane >> 3;
    const int lr   = lane & 7;
    const int lrow = (g & 1) * 8 + lr;
    const int lkb  = (g >> 1) * 16;

    float acc[2][8][4] = {};

    issue(0); issue(1);

    for (int c = 0; c < NC; ++c) {
        asm volatile("cp.async.wait_group 1;" ::: "memory");
        __syncthreads();
        const uint32_t sb = su + (uint32_t)(c & 1) * GF_STAGE;
#pragma unroll
        for (int kk = 0; kk < 4; ++kk) {
            uint32_t ah[2][4], al[2][4];
#pragma unroll
            for (int mt = 0; mt < 2; ++mt) {
                uint32_t off = sw128((uint32_t)((m0 + mt*16 + lrow) * 128 + kk*32 + lkb));
                ldsm4(sb + off, ah[mt]);
                if (SPLIT_A) ldsm4(sb + 16384 + off, al[mt]);
            }
#pragma unroll
            for (int np = 0; np < 4; ++np) {
                uint32_t boff = sw128((uint32_t)((n0 + np*16 + lrow) * 128 + kk*32 + lkb));
                uint32_t bh[4], bl[4];
                ldsm4(sb + 32768 + boff, bh);
                if (!SPLIT_A) ldsm4(sb + 16384 + boff, bl);
#pragma unroll
                for (int mt = 0; mt < 2; ++mt) {
                    if (SPLIT_A) {
                        mma_f16(acc[mt][2*np],   ah[mt], bh[0], bh[2]);
                        mma_f16(acc[mt][2*np],   al[mt], bh[0], bh[2]);
                        mma_f16(acc[mt][2*np+1], ah[mt], bh[1], bh[3]);
                        mma_f16(acc[mt][2*np+1], al[mt], bh[1], bh[3]);
                    } else {
                        mma_f16(acc[mt][2*np],   ah[mt], bh[0], bh[2]);
                        mma_f16(acc[mt][2*np],   ah[mt], bl[0], bl[2]);
                        mma_f16(acc[mt][2*np+1], ah[mt], bh[1], bh[3]);
                        mma_f16(acc[mt][2*np+1], ah[mt], bl[1], bl[3]);
                    }
                }
            }
        }
        __syncthreads();
        if (c + 2 < NC) issue(c + 2);
        else asm volatile("cp.async.commit_group;" ::: "memory");
    }

    // epilogue
    const int er = lane >> 2;
    const int ec = (lane & 3) * 2;
#pragma unroll
    for (int mt = 0; mt < 2; ++mt) {
#pragma unroll
        for (int nt = 0; nt < 8; ++nt) {
            const int row = bm + m0 + mt*16 + er;
            const int col = bn + n0 + nt*8 + ec;
            if (col < Nout) {
                float2 lo = { acc[mt][nt][0], acc[mt][nt][1] };
                float2 hi = { acc[mt][nt][2], acc[mt][nt][3] };
                *(float2*)(C + (size_t)row * Nout + col)       = lo;
                *(float2*)(C + (size_t)(row + 8) * Nout + col) = hi;
            }
        }
    }
}

// ---------------------------------------------------------------------------
// fp32 -> fp16 hi/lo splitter and single-fp16 converter (grid-stride, float4)
// ---------------------------------------------------------------------------
__global__ void split2_kernel(const float* __restrict__ s,
                              __half* __restrict__ h, __half* __restrict__ l, int n4)
{
    for (int i = blockIdx.x * blockDim.x + threadIdx.x; i < n4;
         i += gridDim.x * blockDim.x) {
        float4 v = ((const float4*)s)[i];
        __half hx = __float2half_rn(v.x), hy = __float2half_rn(v.y);
        __half hz = __float2half_rn(v.z), hw = __float2half_rn(v.w);
        __half lx = __float2half_rn(v.x - __half2float(hx));
        __half ly = __float2half_rn(v.y - __half2float(hy));
        __half lz = __float2half_rn(v.z - __half2float(hz));
        __half lw = __float2half_rn(v.w - __half2float(hw));
        __half2 h01 = __halves2half2(hx, hy), h23 = __halves2half2(hz, hw);
        __half2 l01 = __halves2half2(lx, ly), l23 = __halves2half2(lz, lw);
        ((uint2*)h)[i] = make_uint2(*(uint32_t*)&h01, *(uint32_t*)&h23);
        ((uint2*)l)[i] = make_uint2(*(uint32_t*)&l01, *(uint32_t*)&l23);
    }
}

__global__ void tof16_kernel(const float* __restrict__ s, __half* __restrict__ h, int n4)
{
    for (int i = blockIdx.x * blockDim.x + threadIdx.x; i < n4;
         i += gridDim.x * blockDim.x) {
        float4 v = ((const float4*)s)[i];
        __half2 h01 = __halves2half2(__float2half_rn(v.x), __float2half_rn(v.y));
        __half2 h23 = __halves2half2(__float2half_rn(v.z), __float2half_rn(v.w));
        ((uint2*)h)[i] = make_uint2(*(uint32_t*)&h01, *(uint32_t*)&h23);
    }
}

// xproj weights: pad 80 -> 128 rows (zeros), single fp16, both dirs.
__global__ void padw_kernel(const float* __restrict__ wf, const float* __restrict__ wb)
{
    const int total4 = 2 * 128 * CDI / 4;
    for (int i = blockIdx.x * blockDim.x + threadIdx.x; i < total4;
         i += gridDim.x * blockDim.x) {
        int e = i * 4;
        int dir = e / (128 * CDI);
        int rem = e - dir * 128 * CDI;
        int row = rem / CDI;
        int k   = rem - row * CDI;
        float4 v = {0.f, 0.f, 0.f, 0.f};
        const float* W = dir ? wb : wf;
        if (row < CPROJ) v = *(const float4*)(W + (size_t)row * CDI + k);
        __half2 h01 = __halves2half2(__float2half_rn(v.x), __float2half_rn(v.y));
        __half2 h23 = __halves2half2(__float2half_rn(v.z), __float2half_rn(v.w));
        ((uint2*)&g_wx[0][0])[i] = make_uint2(*(uint32_t*)&h01, *(uint32_t*)&h23);
    }
}

// ---------------------------------------------------------------------------
// Depthwise causal conv (K=4) + bias + SiLU, transpose to (b,t,d).
// MERGED DIRECTIONS: one block loads x[t0-3 .. t0+130] once and computes
//   forward outputs  t  in [t0, t0+128)            (needs x[t0-3 .. t0+130])
//   backward outputs t' in [L-128-t0, L-t0)        (needs x[t0   .. t0+130])
// Halves global x reads and block count vs per-dir blocks.
// ---------------------------------------------------------------------------
__global__ void __launch_bounds__(256) conv_silu_kernel(
    const float* __restrict__ cw_f, const float* __restrict__ cb_f,
    const float* __restrict__ cw_b, const float* __restrict__ cb_b)
{
    const int t0 = blockIdx.x * 128;
    const int d0 = blockIdx.y * 32;
    const int b  = blockIdx.z;

    __shared__ float xs[32][135];   // 134 used; stride 135 (odd) -> conflict-free

    const float* xbase = g_xz + ((size_t)b * (2*CDI) + d0) * CL;
    const int base = t0 - 3;

    const int lane = threadIdx.x & 31;
    const int wy   = threadIdx.x >> 5;
    for (int d = wy; d < 32; d += 8) {
        const float* row = xbase + (size_t)d * CL;
        for (int i = lane; i < 134; i += 32) {
            int u = base + i;
            xs[d][i] = (u >= 0 && u < CL) ? row[u] : 0.f;
        }
    }
    __syncthreads();

    const int d  = threadIdx.x & 31;
    const int sg = threadIdx.x >> 5;
    const float wf0 = cw_f[(d0+d)*CK + 0];
    const float wf1 = cw_f[(d0+d)*CK + 1];
    const float wf2 = cw_f[(d0+d)*CK + 2];
    const float wf3 = cw_f[(d0+d)*CK + 3];
    const float bf  = cb_f[d0+d];
    const float wb0 = cw_b[(d0+d)*CK + 0];
    const float wb1 = cw_b[(d0+d)*CK + 1];
    const float wb2 = cw_b[(d0+d)*CK + 2];
    const float wb3 = cw_b[(d0+d)*CK + 3];
    const float bb  = cb_b[d0+d];

    __half* ohf = g_xth[0] + (size_t)b * CL * CDI;
    __half* olf = g_xtl[0] + (size_t)b * CL * CDI;
    __half* ohb = g_xth[1] + (size_t)b * CL * CDI;
    __half* olb = g_xtl[1] + (size_t)b * CL * CDI;
    const int tb0 = CL - 128 - t0;    // backward output tile base
#pragma unroll
    for (int q = 0; q < 16; ++q) {
        int s = sg + 8*q;
        // forward: t = t0+s, window xs[s..s+3]
        {
            float v = wf0*xs[d][s] + wf1*xs[d][s+1] + wf2*xs[d][s+2] + wf3*xs[d][s+3] + bf;
            float sv = v / (1.f + __expf(-v));
            size_t idx = (size_t)(t0 + s) * CDI + d0 + d;
            __half hb = __float2half_rn(sv);
            ohf[idx] = hb;
            olf[idx] = __float2half_rn(sv - __half2float(hb));
        }
        // backward: t' = tb0+s, needs x[L-1-t'+k] = xs[130-s+k], k=0..3
        {
            float v = wb3*xs[d][130-s] + wb2*xs[d][131-s] + wb1*xs[d][132-s]
                    + wb0*xs[d][133-s] + bb;
            float sv = v / (1.f + __expf(-v));
            size_t idx = (size_t)(tb0 + s) * CDI + d0 + d;
            __half hb = __float2half_rn(sv);
            ohb[idx] = hb;
            olb[idx] = __float2half_rn(sv - __half2float(hb));
        }
    }
}

// ---------------------------------------------------------------------------
// dtproj + softplus (round-5 structure; minBlocks=4 caps regs at 64 -> 4 CTA/SM)
// ---------------------------------------------------------------------------
__device__ __forceinline__ float softplus_f(float v) {
    return (v > 20.f) ? v : log1pf(__expf(v));
}

__global__ void __launch_bounds__(256, 4) dtproj_kernel(
    const float* __restrict__ dtw_f, const float* __restrict__ dtb_f,
    const float* __restrict__ dtw_b, const float* __restrict__ dtb_b)
{
    const int dir = blockIdx.z;
    const float* W    = dir ? dtw_b : dtw_f;
    const float* bias = dir ? dtb_b : dtb_f;
    const float* DT = g_dbl[dir];
    float* O = g_delta[dir];

    const int r0 = blockIdx.x * 64;
    const int d0 = blockIdx.y * 128;

    __shared__ __align__(16) float Ts[48][64];
    __shared__ __align__(16) float Ws2[48][128];

    const int tid = threadIdx.x;
#pragma unroll
    for (int p = 0; p < 3; ++p) {
        int q = tid + p*256;
        int rr = q / 12, kk = (q % 12) * 4;
        float4 v = *(const float4*)(DT + (size_t)(r0+rr)*CPROJ + kk);
        Ts[kk+0][rr]=v.x; Ts[kk+1][rr]=v.y; Ts[kk+2][rr]=v.z; Ts[kk+3][rr]=v.w;
    }
#pragma unroll
    for (int p = 0; p < 6; ++p) {
        int q = tid + p*256;
        int dd = q / 12, kk = (q % 12) * 4;
        float4 v = *(const float4*)(W + (size_t)(d0+dd)*CR + kk);
        Ws2[kk+0][dd]=v.x; Ws2[kk+1][dd]=v.y; Ws2[kk+2][dd]=v.z; Ws2[kk+3][dd]=v.w;
    }
    __syncthreads();

    const int tx = tid & 31;
    const int ty = tid >> 5;
    float acc[8][4] = {};
#pragma unroll
    for (int k = 0; k < 48; ++k) {
        float4 a0 = *(const float4*)&Ts[k][ty*8];
        float4 a1 = *(const float4*)&Ts[k][ty*8+4];
        float a[8] = {a0.x,a0.y,a0.z,a0.w,a1.x,a1.y,a1.z,a1.w};
        float4 w = *(const float4*)&Ws2[k][tx*4];
        float ww[4] = {w.x, w.y, w.z, w.w};
#pragma unroll
        for (int i = 0; i < 8; ++i)
#pragma unroll
            for (int j = 0; j < 4; ++j)
                acc[i][j] = fmaf(a[i], ww[j], acc[i][j]);
    }

    const int tx4 = tx*4;
    float b0 = bias[d0+tx4+0], b1 = bias[d0+tx4+1], b2 = bias[d0+tx4+2], b3 = bias[d0+tx4+3];
#pragma unroll
    for (int i = 0; i < 8; ++i) {
        float4 v;
        v.x = softplus_f(acc[i][0] + b0);
        v.y = softplus_f(acc[i][1] + b1);
        v.z = softplus_f(acc[i][2] + b2);
        v.w = softplus_f(acc[i][3] + b3);
        *(float4*)(O + (size_t)(r0 + ty*8 + i)*CDI + d0 + tx4) = v;
    }
}

// ---------------------------------------------------------------------------
// Selective scan (round-5 version: 4 scalar arrays, deep load batching)
// ---------------------------------------------------------------------------
__global__ void __launch_bounds__(256) scan_kernel(
    const float* __restrict__ Alog_f, const float* __restrict__ Dv_f,
    const float* __restrict__ Alog_b, const float* __restrict__ Dv_b)
{
    const int dir = blockIdx.z;
    const int b   = blockIdx.y;
    const int d0  = blockIdx.x * 16;

    const float* Alog = dir ? Alog_b : Alog_f;
    const float* Dvec = dir ? Dv_b   : Dv_f;
    const float* delta = g_delta[dir] + (size_t)b * CL * CDI;
    const __half* xth  = g_xth[dir]   + (size_t)b * CL * CDI;
    const __half* xtl  = g_xtl[dir]   + (size_t)b * CL * CDI;
    const float* dbl   = g_dbl[dir]   + (size_t)b * CL * CPROJ;
    float* yout        = g_y[dir]     + (size_t)b * CL * CDI;

    __shared__ __align__(16) float sd[64][16];
    __shared__ __align__(16) float sx[64][16];
    __shared__ __align__(16) float sB[64][16];
    __shared__ __align__(16) float sC[64][16];

    const int tid  = threadIdx.x;
    const int lane = tid & 31;
    const int wid  = tid >> 5;
    const int half = lane >> 4;
    const int n    = lane & 15;
    const int ch   = wid*2 + half;
    const int d    = d0 + ch;

    const float Aval = -__expf(Alog[d*CN + n]);
    const float Dval = Dvec[d];
    float h = 0.f;

    const int li = tid >> 2;
    const int lj = (tid & 3) * 4;

    float4 rd, rB, rC, rx;
    auto LD = [&](int t0) {
        rd = *(const float4*)(delta + (size_t)(t0+li)*CDI + d0 + lj);
        uint2 xh = *(const uint2*)(xth + (size_t)(t0+li)*CDI + d0 + lj);
        uint2 xl = *(const uint2*)(xtl + (size_t)(t0+li)*CDI + d0 + lj);
        __half2 h01 = *(__half2*)&xh.x, h23 = *(__half2*)&xh.y;
        __half2 l01 = *(__half2*)&xl.x, l23 = *(__half2*)&xl.y;
        float2 fh01 = __half22float2(h01), fh23 = __half22float2(h23);
        float2 fl01 = __half22float2(l01), fl23 = __half22float2(l23);
        rx.x = fh01.x + fl01.x; rx.y = fh01.y + fl01.y;
        rx.z = fh23.x + fl23.x; rx.w = fh23.y + fl23.y;
        rB = *(const float4*)(dbl + (size_t)(t0+li)*CPROJ + CR + lj);
        rC = *(const float4*)(dbl + (size_t)(t0+li)*CPROJ + CR + CN + lj);
    };
    LD(0);

    const int NCH = CL / 64;
    for (int c = 0; c < NCH; ++c) {
        __syncthreads();
        *(float4*)&sd[li][lj] = rd;
        *(float4*)&sx[li][lj] = rx;
        *(float4*)&sB[li][lj] = rB;
        *(float4*)&sC[li][lj] = rC;
        __syncthreads();
        if (c + 1 < NCH) LD((c+1) * 64);

        const int tbase = c * 64;
#pragma unroll 8
        for (int s = 0; s < 64; ++s) {
            float dt = sd[s][ch];
            float xv = sx[s][ch];
            float Bv = sB[s][n];
            float Cv = sC[s][n];
            float a = __expf(dt * Aval);
            h = fmaf(a, h, dt * xv * Bv);
            float p = h * Cv;
            p += __shfl_xor_sync(0xffffffffu, p, 8);
            p += __shfl_xor_sync(0xffffffffu, p, 4);
            p += __shfl_xor_sync(0xffffffffu, p, 2);
            p += __shfl_xor_sync(0xffffffffu, p, 1);
            if (n == 0)
                yout[(size_t)(tbase + s)*CDI + d] = p + xv * Dval;
        }
    }
}

// ---------------------------------------------------------------------------
// Gate + direction merge -> fp16 hi/lo comb (out_proj split operand)
// ---------------------------------------------------------------------------
__global__ void __launch_bounds__(256) combine_kernel()
{
    const int l0 = blockIdx.x * 32;
    const int d0 = blockIdx.y * 32;
    const int b  = blockIdx.z;

    __shared__ float zs[32][33];
    const int lane = threadIdx.x & 31;
    const int wy   = threadIdx.x >> 5;

    const float* zbase = g_xz + ((size_t)b * (2*CDI) + CDI + d0) * CL;
    for (int dd = wy; dd < 32; dd += 8)
        zs[dd][lane] = zbase[(size_t)dd * CL + l0 + lane];
    __syncthreads();

#pragma unroll
    for (int q = 0; q < 4; ++q) {
        int lr = wy + 8*q;
        int l = l0 + lr;
        size_t idx  = ((size_t)b*CL + l)*CDI + d0 + lane;
        size_t idxr = ((size_t)b*CL + (CL-1-l))*CDI + d0 + lane;
        float yf = g_y[0][idx];
        float yb = g_y[1][idxr];
        float zv = zs[lane][lr];
        float s = zv / (1.f + __expf(-zv));
        float cv = (yf + yb) * s;
        __half hb = __float2half_rn(cv);
        g_cmb_h[idx] = hb;
        g_cmb_l[idx] = __float2half_rn(cv - __half2float(hb));
    }
}

// ---------------------------------------------------------------------------
// Launcher
// ---------------------------------------------------------------------------
extern "C" void kernel_launch(void* const* d_in, const int* in_sizes, int n_in,
                              void* d_out, int out_size)
{
    (void)in_sizes; (void)n_in; (void)out_size;

    const float* hidden  = (const float*)d_in[0];
    const float* in_w    = (const float*)d_in[1];
    const float* conv_w  = (const float*)d_in[2];
    const float* conv_b  = (const float*)d_in[3];
    const float* xproj_w = (const float*)d_in[4];
    const float* dtw     = (const float*)d_in[5];
    const float* dtb     = (const float*)d_in[6];
    const float* A_log   = (const float*)d_in[7];
    const float* Dv      = (const float*)d_in[8];
    const float* conv_w2 = (const float*)d_in[9];
    const float* conv_b2 = (const float*)d_in[10];
    const float* xproj_w2= (const float*)d_in[11];
    const float* dtw2    = (const float*)d_in[12];
    const float* dtb2    = (const float*)d_in[13];
    const float* A_log2  = (const float*)d_in[14];
    const float* Dv2     = (const float*)d_in[15];
    const float* out_w   = (const float*)d_in[16];

    void *p_xz, *p_dbl;
    void *p_hid_h, *p_hid_l, *p_w1, *p_w2, *p_wx, *p_xth, *p_xtl, *p_cmb_h, *p_cmb_l;
    cudaGetSymbolAddress(&p_xz, g_xz);
    cudaGetSymbolAddress(&p_dbl, g_dbl);
    cudaGetSymbolAddress(&p_hid_h, g_hid_h);
    cudaGetSymbolAddress(&p_hid_l, g_hid_l);
    cudaGetSymbolAddress(&p_w1, g_w1);
    cudaGetSymbolAddress(&p_w2, g_w2);
    cudaGetSymbolAddress(&p_wx, g_wx);
    cudaGetSymbolAddress(&p_xth, g_xth);
    cudaGetSymbolAddress(&p_xtl, g_xtl);
    cudaGetSymbolAddress(&p_cmb_h, g_cmb_h);
    cudaGetSymbolAddress(&p_cmb_l, g_cmb_l);

    cudaFuncSetAttribute(gemm_f16_kernel<0>,
                         cudaFuncAttributeMaxDynamicSharedMemorySize, GF_SMEM);
    cudaFuncSetAttribute(gemm_f16_kernel<1>,
                         cudaFuncAttributeMaxDynamicSharedMemorySize, GF_SMEM);

    // 0) operand packing
    split2_kernel<<<1024, 256>>>(hidden, (__half*)p_hid_h, (__half*)p_hid_l, CB*CL*CDM/4);
    tof16_kernel<<<512, 256>>>(in_w, (__half*)p_w1, 2*CDI*CDM/4);
    tof16_kernel<<<512, 256>>>(out_w, (__half*)p_w2, CDM*CDI/4);
    padw_kernel<<<512, 256>>>(xproj_w, xproj_w2);

    // 1) in_proj: A = w1 (single), B = hidden (split).  M=3072, N=4096, K=768
    gemm_f16_kernel<0><<<dim3(CL/128, (2*CDI)/128, CB), 256, GF_SMEM>>>(
        (const __half*)p_w1, (const __half*)p_hid_l, (const __half*)p_hid_h,
        (float*)p_xz, CL, CDM,
        0, (long long)CL * CDM, (long long)(2*CDI) * CL, CDM / 64);

    // 2) conv + SiLU + transpose (both dirs per block) -> fp16 hi/lo xt
    conv_silu_kernel<<<dim3(CL/128, CDI/32, CB), 256>>>(
        conv_w, conv_b, conv_w2, conv_b2);

    // 3) xproj: A = xt (split), B = wx (single).  M=8192 rows, N=80(pad128), K=1536
    gemm_f16_kernel<1><<<dim3(1, (CB*CL)/128, 2), 256, GF_SMEM>>>(
        (const __half*)p_xth, (const __half*)p_xtl, (const __half*)p_wx,
        (float*)p_dbl, CPROJ, CDI,
        (long long)CB*CL*CDI, (long long)128*CDI, (long long)CB*CL*CPROJ, CDI / 64);

    // 4) dtproj + softplus -> delta
    dtproj_kernel<<<dim3((CB*CL)/64, CDI/128, 2), 256>>>(dtw, dtb, dtw2, dtb2);

    // 5) selective scan
    scan_kernel<<<dim3(CDI/16, CB, 2), 256>>>(A_log, Dv, A_log2, Dv2);

    // 6) gate + direction merge -> fp16 hi/lo comb
    combine_kernel<<<dim3(CL/32, CDI/32, CB), 256>>>();

    // 7) out_proj: A = comb (split), B = w2 (single).  M=8192, N=768, K=1536
    gemm_f16_kernel<1><<<dim3(CDM/128, (CB*CL)/128, 1), 256, GF_SMEM>>>(
        (const __half*)p_cmb_h, (const __half*)p_cmb_l, (const __half*)p_w2,
        (float*)d_out, CDM, CDI,
        0, 0, 0, CDI / 64);
}

// round 9
// speedup vs baseline: 1.1326x; 1.0239x over previous
#include <cuda_runtime.h>
#include <cuda_fp16.h>
#include <cstdint>

// Problem constants
constexpr int CB  = 2;     // batch
constexpr int CL  = 4096;  // seq len
constexpr int CDM = 768;   // d_model
constexpr int CDI = 1536;  // d_inner
constexpr int CN  = 16;    // state dim
constexpr int CR  = 48;    // dt rank
constexpr int CK  = 4;     // conv width
constexpr int CPROJ = CR + 2*CN; // 80
constexpr int CRP = 64;    // dt rank padded for MMA K

// ---------------------------------------------------------------------------
// Scratch (device globals; no runtime allocation allowed)
// ---------------------------------------------------------------------------
__device__ float g_xz[CB * 2 * CDI * CL];        // (b, e, l)
__device__ float g_dbl[2][CB * CL * CPROJ];      // per dir, (b*L, 80): only B|C cols used
__device__ float g_delta[2][CB * CL * CDI];      // per dir, post-softplus
__device__ float g_y[2][CB * CL * CDI];          // per dir, scan out (+D*x)

// fp16 operands for tensor GEMMs
__device__ __half g_hid_h[CB*CL*CDM], g_hid_l[CB*CL*CDM];  // hidden hi/lo (split side)
__device__ __half g_w1[2*CDI*CDM];                          // in_proj W (single)
__device__ __half g_w2[CDM*CDI];                            // out_proj W (single)
__device__ __half g_wx[2][128*CDI];                         // xproj W padded 80->128 (single)
__device__ __half g_xth[2][CB*CL*CDI], g_xtl[2][CB*CL*CDI]; // conv out hi/lo (split side)
__device__ __half g_cmb_h[CB*CL*CDI],  g_cmb_l[CB*CL*CDI];  // gated sum hi/lo (split side)
__device__ __half g_dt_h[2][CB*CL*CRP], g_dt_l[2][CB*CL*CRP]; // dt rows padded 48->64, hi/lo
__device__ __half g_wdt_h[2][CDI*CRP],  g_wdt_l[2][CDI*CRP];  // dtproj W padded, hi/lo

// ---------------------------------------------------------------------------
// PTX helpers
// ---------------------------------------------------------------------------
__device__ __forceinline__ uint32_t smem_u32(const void* p) {
    uint32_t a;
    asm("{ .reg .u64 t; cvta.to.shared.u64 t, %1; cvt.u32.u64 %0, t; }" : "=r"(a) : "l"(p));
    return a;
}
__device__ __forceinline__ uint32_t sw128(uint32_t b) { return b ^ ((b >> 3) & 0x70); }

__device__ __forceinline__ void ldsm4(uint32_t addr, uint32_t r[4]) {
    asm volatile("ldmatrix.sync.aligned.m8n8.x4.shared.b16 {%0,%1,%2,%3}, [%4];"
        : "=r"(r[0]), "=r"(r[1]), "=r"(r[2]), "=r"(r[3]) : "r"(addr));
}
__device__ __forceinline__ void mma_f16(float* d, const uint32_t* a, uint32_t b0, uint32_t b1) {
    asm volatile("mma.sync.aligned.m16n8k16.row.col.f32.f16.f16.f32 "
        "{%0,%1,%2,%3}, {%4,%5,%6,%7}, {%8,%9}, {%0,%1,%2,%3};"
        : "+f"(d[0]), "+f"(d[1]), "+f"(d[2]), "+f"(d[3])
        : "r"(a[0]), "r"(a[1]), "r"(a[2]), "r"(a[3]), "r"(b0), "r"(b1));
}
__device__ __forceinline__ void cp16(uint32_t s, const void* g) {
    asm volatile("cp.async.ca.shared.global [%0], [%1], 16;" :: "r"(s), "l"(g));
}

// ---------------------------------------------------------------------------
// 2-term fp16 tensor GEMM:  C[m,n] = sum_k A[m,k]*B[n,k]  (fp32 out)
// MODE 0: plain fp32 store with col<Nout guard.
// MODE 1 (xproj): cols<64 -> dt fp16 hi/lo (value if col<48 else 0) into
//                 dtH/dtL [row*64+col]; cols 48..79 -> fp32 dbl store.
// ---------------------------------------------------------------------------
constexpr int GF_STAGE = 49152;
constexpr int GF_SMEM  = 2 * GF_STAGE;   // 98304 B

template <int SPLIT_A, int MODE>
__global__ void __launch_bounds__(256, 2) gemm_f16_kernel(
    const __half* __restrict__ Ah, const __half* __restrict__ Xl,  // Xl = Al or Bl
    const __half* __restrict__ Bh,
    float* __restrict__ C, int Nout, int Kd,
    long long strideA, long long strideB, long long strideC, int NC,
    __half* __restrict__ dtH, __half* __restrict__ dtL)
{
    extern __shared__ __align__(1024) char smem[];
    const uint32_t su = smem_u32(smem);
    Ah += (size_t)blockIdx.z * strideA;
    Bh += (size_t)blockIdx.z * strideB;
    Xl += (size_t)blockIdx.z * (SPLIT_A ? strideA : strideB);
    C  += (size_t)blockIdx.z * strideC;
    const int bm = blockIdx.y * 128;
    const int bn = blockIdx.x * 128;
    const int tid  = threadIdx.x;
    const int wid  = tid >> 5;
    const int lane = tid & 31;

    const int prow = tid >> 3;          // 0..31 -> x4 gives 128 rows
    const int pkc  = tid & 7;           // 16B chunk within 128B row
    auto issue = [&](int c) {
        const uint32_t sb = su + (uint32_t)(c & 1) * GF_STAGE;
        const int k0 = c * 64;
#pragma unroll
        for (int i = 0; i < 4; ++i) {
            const int row = prow + i * 32;
            const uint32_t off = sw128((uint32_t)(row * 128 + pkc * 16));
            const size_t ga = (size_t)(bm + row) * Kd + k0 + pkc * 8;
            const size_t gb = (size_t)(bn + row) * Kd + k0 + pkc * 8;
            cp16(sb + off,         Ah + ga);
            cp16(sb + 16384 + off, Xl + (SPLIT_A ? ga : gb));
            cp16(sb + 32768 + off, Bh + gb);
        }
        asm volatile("cp.async.commit_group;" ::: "memory");
    };

    // warp tiling: 4x2 warps, warp tile 32 (m) x 64 (n)
    const int m0 = (wid & 3) * 32;
    const int n0 = (wid >> 2) * 64;
    const int g    = lane >> 3;
    const int lr   = lane & 7;
    const int lrow = (g & 1) * 8 + lr;
    const int lkb  = (g >> 1) * 16;

    float acc[2][8][4] = {};

    issue(0); issue(1);

    for (int c = 0; c < NC; ++c) {
        asm volatile("cp.async.wait_group 1;" ::: "memory");
        __syncthreads();
        const uint32_t sb = su + (uint32_t)(c & 1) * GF_STAGE;
#pragma unroll
        for (int kk = 0; kk < 4; ++kk) {
            uint32_t ah[2][4], al[2][4];
#pragma unroll
            for (int mt = 0; mt < 2; ++mt) {
                uint32_t off = sw128((uint32_t)((m0 + mt*16 + lrow) * 128 + kk*32 + lkb));
                ldsm4(sb + off, ah[mt]);
                if (SPLIT_A) ldsm4(sb + 16384 + off, al[mt]);
            }
#pragma unroll
            for (int np = 0; np < 4; ++np) {
                uint32_t boff = sw128((uint32_t)((n0 + np*16 + lrow) * 128 + kk*32 + lkb));
                uint32_t bh[4], bl[4];
                ldsm4(sb + 32768 + boff, bh);
                if (!SPLIT_A) ldsm4(sb + 16384 + boff, bl);
#pragma unroll
                for (int mt = 0; mt < 2; ++mt) {
                    if (SPLIT_A) {
                        mma_f16(acc[mt][2*np],   ah[mt], bh[0], bh[2]);
                        mma_f16(acc[mt][2*np],   al[mt], bh[0], bh[2]);
                        mma_f16(acc[mt][2*np+1], ah[mt], bh[1], bh[3]);
                        mma_f16(acc[mt][2*np+1], al[mt], bh[1], bh[3]);
                    } else {
                        mma_f16(acc[mt][2*np],   ah[mt], bh[0], bh[2]);
                        mma_f16(acc[mt][2*np],   ah[mt], bl[0], bl[2]);
                        mma_f16(acc[mt][2*np+1], ah[mt], bh[1], bh[3]);
                        mma_f16(acc[mt][2*np+1], ah[mt], bl[1], bl[3]);
                    }
                }
            }
        }
        __syncthreads();
        if (c + 2 < NC) issue(c + 2);
        else asm volatile("cp.async.commit_group;" ::: "memory");
    }

    // epilogue
    const int er = lane >> 2;
    const int ec = (lane & 3) * 2;
    if (MODE == 0) {
#pragma unroll
        for (int mt = 0; mt < 2; ++mt) {
#pragma unroll
            for (int nt = 0; nt < 8; ++nt) {
                const int row = bm + m0 + mt*16 + er;
                const int col = bn + n0 + nt*8 + ec;
                if (col < Nout) {
                    float2 lo = { acc[mt][nt][0], acc[mt][nt][1] };
                    float2 hi = { acc[mt][nt][2], acc[mt][nt][3] };
                    *(float2*)(C + (size_t)row * Nout + col)       = lo;
                    *(float2*)(C + (size_t)(row + 8) * Nout + col) = hi;
                }
            }
        }
    } else {
        __half* dH = dtH + (size_t)blockIdx.z * ((size_t)CB*CL*CRP);
        __half* dL = dtL + (size_t)blockIdx.z * ((size_t)CB*CL*CRP);
#pragma unroll
        for (int mt = 0; mt < 2; ++mt) {
#pragma unroll
            for (int nt = 0; nt < 8; ++nt) {
                const int row0 = bm + m0 + mt*16 + er;
                const int col  = bn + n0 + nt*8 + ec;
#pragma unroll
                for (int rr = 0; rr < 2; ++rr) {
                    const int row = row0 + rr*8;
#pragma unroll
                    for (int e = 0; e < 2; ++e) {
                        const int cc = col + e;
                        const float v = acc[mt][nt][rr*2+e];
                        if (cc < CRP) {
                            float dv = (cc < CR) ? v : 0.f;
                            __half hb = __float2half_rn(dv);
                            dH[(size_t)row * CRP + cc] = hb;
                            dL[(size_t)row * CRP + cc] =
                                __float2half_rn(dv - __half2float(hb));
                        }
                        if (cc >= CR && cc < CPROJ)
                            C[(size_t)row * Nout + cc] = v;
                    }
                }
            }
        }
    }
}

// ---------------------------------------------------------------------------
// dtproj tensor GEMM: delta[row,d] = softplus(sum_r dt[row,r]*W[d,r] + bias[d])
// Single K-chunk (K=64 padded), 3-term split (dth*Wh + dtl*Wh + dth*Wl).
// 128x128 tile, 64KB smem: dtH 16K | dtL 16K | WH 16K | WL 16K.
// ---------------------------------------------------------------------------
__device__ __forceinline__ float softplus_f(float v) {
    return (v > 20.f) ? v : log1pf(__expf(v));
}

__global__ void __launch_bounds__(256) dtgemm_kernel(
    const float* __restrict__ bias_f, const float* __restrict__ bias_b)
{
    extern __shared__ __align__(1024) char smem[];
    const uint32_t su = smem_u32(smem);
    const int dir = blockIdx.z;
    const __half* Ah = &g_dt_h[dir][0];
    const __half* Al = &g_dt_l[dir][0];
    const __half* Bh = &g_wdt_h[dir][0];
    const __half* Bl = &g_wdt_l[dir][0];
    const float* bias = dir ? bias_b : bias_f;
    float* C = &g_delta[dir][0];

    const int bm = blockIdx.y * 128;   // rows
    const int bn = blockIdx.x * 128;   // d channels
    const int tid  = threadIdx.x;
    const int wid  = tid >> 5;
    const int lane = tid & 31;

    const int prow = tid >> 3;
    const int pkc  = tid & 7;
#pragma unroll
    for (int i = 0; i < 4; ++i) {
        const int row = prow + i * 32;
        const uint32_t off = sw128((uint32_t)(row * 128 + pkc * 16));
        const size_t ga = (size_t)(bm + row) * CRP + pkc * 8;
        const size_t gb = (size_t)(bn + row) * CRP + pkc * 8;
        cp16(su + off,         Ah + ga);
        cp16(su + 16384 + off, Al + ga);
        cp16(su + 32768 + off, Bh + gb);
        cp16(su + 49152 + off, Bl + gb);
    }
    asm volatile("cp.async.commit_group;" ::: "memory");
    asm volatile("cp.async.wait_group 0;" ::: "memory");
    __syncthreads();

    const int m0 = (wid & 3) * 32;
    const int n0 = (wid >> 2) * 64;
    const int g    = lane >> 3;
    const int lr   = lane & 7;
    const int lrow = (g & 1) * 8 + lr;
    const int lkb  = (g >> 1) * 16;

    float acc[2][8][4] = {};
#pragma unroll
    for (int kk = 0; kk < 4; ++kk) {
        uint32_t ah[2][4], al[2][4];
#pragma unroll
        for (int mt = 0; mt < 2; ++mt) {
            uint32_t off = sw128((uint32_t)((m0 + mt*16 + lrow) * 128 + kk*32 + lkb));
            ldsm4(su + off,         ah[mt]);
            ldsm4(su + 16384 + off, al[mt]);
        }
#pragma unroll
        for (int np = 0; np < 4; ++np) {
            uint32_t boff = sw128((uint32_t)((n0 + np*16 + lrow) * 128 + kk*32 + lkb));
            uint32_t bh[4], bl[4];
            ldsm4(su + 32768 + boff, bh);
            ldsm4(su + 49152 + boff, bl);
#pragma unroll
            for (int mt = 0; mt < 2; ++mt) {
                mma_f16(acc[mt][2*np],   ah[mt], bh[0], bh[2]);
                mma_f16(acc[mt][2*np],   al[mt], bh[0], bh[2]);
                mma_f16(acc[mt][2*np],   ah[mt], bl[0], bl[2]);
                mma_f16(acc[mt][2*np+1], ah[mt], bh[1], bh[3]);
                mma_f16(acc[mt][2*np+1], al[mt], bh[1], bh[3]);
                mma_f16(acc[mt][2*np+1], ah[mt], bl[1], bl[3]);
            }
        }
    }

    const int er = lane >> 2;
    const int ec = (lane & 3) * 2;
#pragma unroll
    for (int mt = 0; mt < 2; ++mt) {
#pragma unroll
        for (int nt = 0; nt < 8; ++nt) {
            const int row = bm + m0 + mt*16 + er;
            const int col = bn + n0 + nt*8 + ec;
            const float b0 = bias[col], b1 = bias[col+1];
            float2 lo = { softplus_f(acc[mt][nt][0] + b0),
                          softplus_f(acc[mt][nt][1] + b1) };
            float2 hi = { softplus_f(acc[mt][nt][2] + b0),
                          softplus_f(acc[mt][nt][3] + b1) };
            *(float2*)(C + (size_t)row * CDI + col)       = lo;
            *(float2*)(C + (size_t)(row + 8) * CDI + col) = hi;
        }
    }
}

// ---------------------------------------------------------------------------
// fp32 -> fp16 hi/lo splitter and single-fp16 converter (grid-stride, float4)
// ---------------------------------------------------------------------------
__global__ void split2_kernel(const float* __restrict__ s,
                              __half* __restrict__ h, __half* __restrict__ l, int n4)
{
    for (int i = blockIdx.x * blockDim.x + threadIdx.x; i < n4;
         i += gridDim.x * blockDim.x) {
        float4 v = ((const float4*)s)[i];
        __half hx = __float2half_rn(v.x), hy = __float2half_rn(v.y);
        __half hz = __float2half_rn(v.z), hw = __float2half_rn(v.w);
        __half lx = __float2half_rn(v.x - __half2float(hx));
        __half ly = __float2half_rn(v.y - __half2float(hy));
        __half lz = __float2half_rn(v.z - __half2float(hz));
        __half lw = __float2half_rn(v.w - __half2float(hw));
        __half2 h01 = __halves2half2(hx, hy), h23 = __halves2half2(hz, hw);
        __half2 l01 = __halves2half2(lx, ly), l23 = __halves2half2(lz, lw);
        ((uint2*)h)[i] = make_uint2(*(uint32_t*)&h01, *(uint32_t*)&h23);
        ((uint2*)l)[i] = make_uint2(*(uint32_t*)&l01, *(uint32_t*)&l23);
    }
}

__global__ void tof16_kernel(const float* __restrict__ s, __half* __restrict__ h, int n4)
{
    for (int i = blockIdx.x * blockDim.x + threadIdx.x; i < n4;
         i += gridDim.x * blockDim.x) {
        float4 v = ((const float4*)s)[i];
        __half2 h01 = __halves2half2(__float2half_rn(v.x), __float2half_rn(v.y));
        __half2 h23 = __halves2half2(__float2half_rn(v.z), __float2half_rn(v.w));
        ((uint2*)h)[i] = make_uint2(*(uint32_t*)&h01, *(uint32_t*)&h23);
    }
}

// xproj weights: pad 80 -> 128 rows (zeros), single fp16, both dirs.
__global__ void padw_kernel(const float* __restrict__ wf, const float* __restrict__ wb)
{
    const int total4 = 2 * 128 * CDI / 4;
    for (int i = blockIdx.x * blockDim.x + threadIdx.x; i < total4;
         i += gridDim.x * blockDim.x) {
        int e = i * 4;
        int dir = e / (128 * CDI);
        int rem = e - dir * 128 * CDI;
        int row = rem / CDI;
        int k   = rem - row * CDI;
        float4 v = {0.f, 0.f, 0.f, 0.f};
        const float* W = dir ? wb : wf;
        if (row < CPROJ) v = *(const float4*)(W + (size_t)row * CDI + k);
        __half2 h01 = __halves2half2(__float2half_rn(v.x), __float2half_rn(v.y));
        __half2 h23 = __halves2half2(__float2half_rn(v.z), __float2half_rn(v.w));
        ((uint2*)&g_wx[0][0])[i] = make_uint2(*(uint32_t*)&h01, *(uint32_t*)&h23);
    }
}

// dtproj weights: pad K 48 -> 64 (zeros), split to fp16 hi/lo, both dirs.
__global__ void padwd_kernel(const float* __restrict__ wf, const float* __restrict__ wb)
{
    const int total4 = 2 * CDI * CRP / 4;
    for (int i = blockIdx.x * blockDim.x + threadIdx.x; i < total4;
         i += gridDim.x * blockDim.x) {
        int e = i * 4;
        int dir = e / (CDI * CRP);
        int rem = e - dir * CDI * CRP;
        int row = rem / CRP;
        int k   = rem - row * CRP;
        float4 v = {0.f, 0.f, 0.f, 0.f};
        const float* W = dir ? wb : wf;
        if (k < CR) v = *(const float4*)(W + (size_t)row * CR + k);
        __half hx = __float2half_rn(v.x), hy = __float2half_rn(v.y);
        __half hz = __float2half_rn(v.z), hw = __float2half_rn(v.w);
        __half lx = __float2half_rn(v.x - __half2float(hx));
        __half ly = __float2half_rn(v.y - __half2float(hy));
        __half lz = __float2half_rn(v.z - __half2float(hz));
        __half lw = __float2half_rn(v.w - __half2float(hw));
        __half2 h01 = __halves2half2(hx, hy), h23 = __halves2half2(hz, hw);
        __half2 l01 = __halves2half2(lx, ly), l23 = __halves2half2(lz, lw);
        ((uint2*)&g_wdt_h[0][0])[i] = make_uint2(*(uint32_t*)&h01, *(uint32_t*)&h23);
        ((uint2*)&g_wdt_l[0][0])[i] = make_uint2(*(uint32_t*)&l01, *(uint32_t*)&l23);
    }
}

// ---------------------------------------------------------------------------
// Depthwise causal conv (K=4) + bias + SiLU, transpose to (b,t,d).
// MERGED DIRECTIONS: one block loads x[t0-3 .. t0+130] once, emits both dirs.
// ---------------------------------------------------------------------------
__global__ void __launch_bounds__(256) conv_silu_kernel(
    const float* __restrict__ cw_f, const float* __restrict__ cb_f,
    const float* __restrict__ cw_b, const float* __restrict__ cb_b)
{
    const int t0 = blockIdx.x * 128;
    const int d0 = blockIdx.y * 32;
    const int b  = blockIdx.z;

    __shared__ float xs[32][135];

    const float* xbase = g_xz + ((size_t)b * (2*CDI) + d0) * CL;
    const int base = t0 - 3;

    const int lane = threadIdx.x & 31;
    const int wy   = threadIdx.x >> 5;
    for (int d = wy; d < 32; d += 8) {
        const float* row = xbase + (size_t)d * CL;
        for (int i = lane; i < 134; i += 32) {
            int u = base + i;
            xs[d][i] = (u >= 0 && u < CL) ? row[u] : 0.f;
        }
    }
    __syncthreads();

    const int d  = threadIdx.x & 31;
    const int sg = threadIdx.x >> 5;
    const float wf0 = cw_f[(d0+d)*CK + 0];
    const float wf1 = cw_f[(d0+d)*CK + 1];
    const float wf2 = cw_f[(d0+d)*CK + 2];
    const float wf3 = cw_f[(d0+d)*CK + 3];
    const float bf  = cb_f[d0+d];
    const float wb0 = cw_b[(d0+d)*CK + 0];
    const float wb1 = cw_b[(d0+d)*CK + 1];
    const float wb2 = cw_b[(d0+d)*CK + 2];
    const float wb3 = cw_b[(d0+d)*CK + 3];
    const float bb  = cb_b[d0+d];

    __half* ohf = g_xth[0] + (size_t)b * CL * CDI;
    __half* olf = g_xtl[0] + (size_t)b * CL * CDI;
    __half* ohb = g_xth[1] + (size_t)b * CL * CDI;
    __half* olb = g_xtl[1] + (size_t)b * CL * CDI;
    const int tb0 = CL - 128 - t0;
#pragma unroll
    for (int q = 0; q < 16; ++q) {
        int s = sg + 8*q;
        {
            float v = wf0*xs[d][s] + wf1*xs[d][s+1] + wf2*xs[d][s+2] + wf3*xs[d][s+3] + bf;
            float sv = v / (1.f + __expf(-v));
            size_t idx = (size_t)(t0 + s) * CDI + d0 + d;
            __half hb = __float2half_rn(sv);
            ohf[idx] = hb;
            olf[idx] = __float2half_rn(sv - __half2float(hb));
        }
        {
            float v = wb3*xs[d][130-s] + wb2*xs[d][131-s] + wb1*xs[d][132-s]
                    + wb0*xs[d][133-s] + bb;
            float sv = v / (1.f + __expf(-v));
            size_t idx = (size_t)(tb0 + s) * CDI + d0 + d;
            __half hb = __float2half_rn(sv);
            ohb[idx] = hb;
            olb[idx] = __float2half_rn(sv - __half2float(hb));
        }
    }
}

// ---------------------------------------------------------------------------
// Selective scan (round-5 version: 4 scalar arrays, deep load batching)
// ---------------------------------------------------------------------------
__global__ void __launch_bounds__(256) scan_kernel(
    const float* __restrict__ Alog_f, const float* __restrict__ Dv_f,
    const float* __restrict__ Alog_b, const float* __restrict__ Dv_b)
{
    const int dir = blockIdx.z;
    const int b   = blockIdx.y;
    const int d0  = blockIdx.x * 16;

    const float* Alog = dir ? Alog_b : Alog_f;
    const float* Dvec = dir ? Dv_b   : Dv_f;
    const float* delta = g_delta[dir] + (size_t)b * CL * CDI;
    const __half* xth  = g_xth[dir]   + (size_t)b * CL * CDI;
    const __half* xtl  = g_xtl[dir]   + (size_t)b * CL * CDI;
    const float* dbl   = g_dbl[dir]   + (size_t)b * CL * CPROJ;
    float* yout        = g_y[dir]     + (size_t)b * CL * CDI;

    __shared__ __align__(16) float sd[64][16];
    __shared__ __align__(16) float sx[64][16];
    __shared__ __align__(16) float sB[64][16];
    __shared__ __align__(16) float sC[64][16];

    const int tid  = threadIdx.x;
    const int lane = tid & 31;
    const int wid  = tid >> 5;
    const int half = lane >> 4;
    const int n    = lane & 15;
    const int ch   = wid*2 + half;
    const int d    = d0 + ch;

    const float Aval = -__expf(Alog[d*CN + n]);
    const float Dval = Dvec[d];
    float h = 0.f;

    const int li = tid >> 2;
    const int lj = (tid & 3) * 4;

    float4 rd, rB, rC, rx;
    auto LD = [&](int t0) {
        rd = *(const float4*)(delta + (size_t)(t0+li)*CDI + d0 + lj);
        uint2 xh = *(const uint2*)(xth + (size_t)(t0+li)*CDI + d0 + lj);
        uint2 xl = *(const uint2*)(xtl + (size_t)(t0+li)*CDI + d0 + lj);
        __half2 h01 = *(__half2*)&xh.x, h23 = *(__half2*)&xh.y;
        __half2 l01 = *(__half2*)&xl.x, l23 = *(__half2*)&xl.y;
        float2 fh01 = __half22float2(h01), fh23 = __half22float2(h23);
        float2 fl01 = __half22float2(l01), fl23 = __half22float2(l23);
        rx.x = fh01.x + fl01.x; rx.y = fh01.y + fl01.y;
        rx.z = fh23.x + fl23.x; rx.w = fh23.y + fl23.y;
        rB = *(const float4*)(dbl + (size_t)(t0+li)*CPROJ + CR + lj);
        rC = *(const float4*)(dbl + (size_t)(t0+li)*CPROJ + CR + CN + lj);
    };
    LD(0);

    const int NCH = CL / 64;
    for (int c = 0; c < NCH; ++c) {
        __syncthreads();
        *(float4*)&sd[li][lj] = rd;
        *(float4*)&sx[li][lj] = rx;
        *(float4*)&sB[li][lj] = rB;
        *(float4*)&sC[li][lj] = rC;
        __syncthreads();
        if (c + 1 < NCH) LD((c+1) * 64);

        const int tbase = c * 64;
#pragma unroll 8
        for (int s = 0; s < 64; ++s) {
            float dt = sd[s][ch];
            float xv = sx[s][ch];
            float Bv = sB[s][n];
            float Cv = sC[s][n];
            float a = __expf(dt * Aval);
            h = fmaf(a, h, dt * xv * Bv);
            float p = h * Cv;
            p += __shfl_xor_sync(0xffffffffu, p, 8);
            p += __shfl_xor_sync(0xffffffffu, p, 4);
            p += __shfl_xor_sync(0xffffffffu, p, 2);
            p += __shfl_xor_sync(0xffffffffu, p, 1);
            if (n == 0)
                yout[(size_t)(tbase + s)*CDI + d] = p + xv * Dval;
        }
    }
}

// ---------------------------------------------------------------------------
// Gate + direction merge -> fp16 hi/lo comb (out_proj split operand)
// ---------------------------------------------------------------------------
__global__ void __launch_bounds__(256) combine_kernel()
{
    const int l0 = blockIdx.x * 32;
    const int d0 = blockIdx.y * 32;
    const int b  = blockIdx.z;

    __shared__ float zs[32][33];
    const int lane = threadIdx.x & 31;
    const int wy   = threadIdx.x >> 5;

    const float* zbase = g_xz + ((size_t)b * (2*CDI) + CDI + d0) * CL;
    for (int dd = wy; dd < 32; dd += 8)
        zs[dd][lane] = zbase[(size_t)dd * CL + l0 + lane];
    __syncthreads();

#pragma unroll
    for (int q = 0; q < 4; ++q) {
        int lr = wy + 8*q;
        int l = l0 + lr;
        size_t idx  = ((size_t)b*CL + l)*CDI + d0 + lane;
        size_t idxr = ((size_t)b*CL + (CL-1-l))*CDI + d0 + lane;
        float yf = g_y[0][idx];
        float yb = g_y[1][idxr];
        float zv = zs[lane][lr];
        float s = zv / (1.f + __expf(-zv));
        float cv = (yf + yb) * s;
        __half hb = __float2half_rn(cv);
        g_cmb_h[idx] = hb;
        g_cmb_l[idx] = __float2half_rn(cv - __half2float(hb));
    }
}

// ---------------------------------------------------------------------------
// Launcher
// ---------------------------------------------------------------------------
extern "C" void kernel_launch(void* const* d_in, const int* in_sizes, int n_in,
                              void* d_out, int out_size)
{
    (void)in_sizes; (void)n_in; (void)out_size;

    const float* hidden  = (const float*)d_in[0];
    const float* in_w    = (const float*)d_in[1];
    const float* conv_w  = (const float*)d_in[2];
    const float* conv_b  = (const float*)d_in[3];
    const float* xproj_w = (const float*)d_in[4];
    const float* dtw     = (const float*)d_in[5];
    const float* dtb     = (const float*)d_in[6];
    const float* A_log   = (const float*)d_in[7];
    const float* Dv      = (const float*)d_in[8];
    const float* conv_w2 = (const float*)d_in[9];
    const float* conv_b2 = (const float*)d_in[10];
    const float* xproj_w2= (const float*)d_in[11];
    const float* dtw2    = (const float*)d_in[12];
    const float* dtb2    = (const float*)d_in[13];
    const float* A_log2  = (const float*)d_in[14];
    const float* Dv2     = (const float*)d_in[15];
    const float* out_w   = (const float*)d_in[16];

    void *p_xz, *p_dbl;
    void *p_hid_h, *p_hid_l, *p_w1, *p_w2, *p_wx, *p_xth, *p_xtl, *p_cmb_h, *p_cmb_l;
    void *p_dt_h, *p_dt_l;
    cudaGetSymbolAddress(&p_xz, g_xz);
    cudaGetSymbolAddress(&p_dbl, g_dbl);
    cudaGetSymbolAddress(&p_hid_h, g_hid_h);
    cudaGetSymbolAddress(&p_hid_l, g_hid_l);
    cudaGetSymbolAddress(&p_w1, g_w1);
    cudaGetSymbolAddress(&p_w2, g_w2);
    cudaGetSymbolAddress(&p_wx, g_wx);
    cudaGetSymbolAddress(&p_xth, g_xth);
    cudaGetSymbolAddress(&p_xtl, g_xtl);
    cudaGetSymbolAddress(&p_cmb_h, g_cmb_h);
    cudaGetSymbolAddress(&p_cmb_l, g_cmb_l);
    cudaGetSymbolAddress(&p_dt_h, g_dt_h);
    cudaGetSymbolAddress(&p_dt_l, g_dt_l);

    cudaFuncSetAttribute(gemm_f16_kernel<0,0>,
                         cudaFuncAttributeMaxDynamicSharedMemorySize, GF_SMEM);
    cudaFuncSetAttribute(gemm_f16_kernel<1,0>,
                         cudaFuncAttributeMaxDynamicSharedMemorySize, GF_SMEM);
    cudaFuncSetAttribute(gemm_f16_kernel<1,1>,
                         cudaFuncAttributeMaxDynamicSharedMemorySize, GF_SMEM);
    cudaFuncSetAttribute(dtgemm_kernel,
                         cudaFuncAttributeMaxDynamicSharedMemorySize, 65536);

    // 0) operand packing
    split2_kernel<<<1024, 256>>>(hidden, (__half*)p_hid_h, (__half*)p_hid_l, CB*CL*CDM/4);
    tof16_kernel<<<512, 256>>>(in_w, (__half*)p_w1, 2*CDI*CDM/4);
    tof16_kernel<<<512, 256>>>(out_w, (__half*)p_w2, CDM*CDI/4);
    padw_kernel<<<512, 256>>>(xproj_w, xproj_w2);
    padwd_kernel<<<192, 256>>>(dtw, dtw2);

    // 1) in_proj: A = w1 (single), B = hidden (split).  M=3072, N=4096, K=768
    gemm_f16_kernel<0,0><<<dim3(CL/128, (2*CDI)/128, CB), 256, GF_SMEM>>>(
        (const __half*)p_w1, (const __half*)p_hid_l, (const __half*)p_hid_h,
        (float*)p_xz, CL, CDM,
        0, (long long)CL * CDM, (long long)(2*CDI) * CL, CDM / 64,
        nullptr, nullptr);

    // 2) conv + SiLU + transpose (both dirs per block) -> fp16 hi/lo xt
    conv_silu_kernel<<<dim3(CL/128, CDI/32, CB), 256>>>(
        conv_w, conv_b, conv_w2, conv_b2);

    // 3) xproj: A = xt (split), B = wx (single). MODE 1 epilogue emits
    //    dt fp16 hi/lo (padded to 64) + fp32 B|C cols of dbl.
    gemm_f16_kernel<1,1><<<dim3(1, (CB*CL)/128, 2), 256, GF_SMEM>>>(
        (const __half*)p_xth, (const __half*)p_xtl, (const __half*)p_wx,
        (float*)p_dbl, CPROJ, CDI,
        (long long)CB*CL*CDI, (long long)128*CDI, (long long)CB*CL*CPROJ, CDI / 64,
        (__half*)p_dt_h, (__half*)p_dt_l);

    // 4) dtproj as tensor GEMM + softplus -> delta
    dtgemm_kernel<<<dim3(CDI/128, (CB*CL)/128, 2), 256, 65536>>>(dtb, dtb2);

    // 5) selective scan
    scan_kernel<<<dim3(CDI/16, CB, 2), 256>>>(A_log, Dv, A_log2, Dv2);

    // 6) gate + direction merge -> fp16 hi/lo comb
    combine_kernel<<<dim3(CL/32, CDI/32, CB), 256>>>();

    // 7) out_proj: A = comb (split), B = w2 (single).  M=8192, N=768, K=1536
    gemm_f16_kernel<1,0><<<dim3(CDM/128, (CB*CL)/128, 1), 256, GF_SMEM>>>(
        (const __half*)p_cmb_h, (const __half*)p_cmb_l, (const __half*)p_w2,
        (float*)d_out, CDM, CDI,
        0, 0, 0, CDI / 64,
        nullptr, nullptr);
}

// round 10
// speedup vs baseline: 1.1585x; 1.0229x over previous
#include <cuda_runtime.h>
#include <cuda_fp16.h>
#include <cstdint>

// Problem constants
constexpr int CB  = 2;     // batch
constexpr int CL  = 4096;  // seq len
constexpr int CDM = 768;   // d_model
constexpr int CDI = 1536;  // d_inner
constexpr int CN  = 16;    // state dim
constexpr int CR  = 48;    // dt rank
constexpr int CK  = 4;     // conv width
constexpr int CPROJ = CR + 2*CN; // 80
constexpr int CRP = 64;    // dt rank padded for MMA K

// ---------------------------------------------------------------------------
// Scratch (device globals; no runtime allocation allowed)
// ---------------------------------------------------------------------------
__device__ float g_xz[CB * 2 * CDI * CL];        // (b, e, l)
__device__ float g_dbl[2][CB * CL * CPROJ];      // per dir, (b*L, 80): only B|C cols used
__device__ float g_delta[2][CB * CL * CDI];      // per dir, post-softplus
__device__ float g_y[2][CB * CL * CDI];          // per dir, scan out (+D*x)

// fp16 operands for tensor GEMMs
__device__ __half g_hid_h[CB*CL*CDM], g_hid_l[CB*CL*CDM];  // hidden hi/lo (split side)
__device__ __half g_w1[2*CDI*CDM];                          // in_proj W (single)
__device__ __half g_w2[CDM*CDI];                            // out_proj W (single)
__device__ __half g_wx[2][128*CDI];                         // xproj W padded 80->128 (single)
__device__ __half g_xth[2][CB*CL*CDI], g_xtl[2][CB*CL*CDI]; // conv out hi/lo (split side)
__device__ __half g_cmb_h[CB*CL*CDI],  g_cmb_l[CB*CL*CDI];  // gated sum hi/lo (split side)
__device__ __half g_dt_h[2][CB*CL*CRP], g_dt_l[2][CB*CL*CRP]; // dt rows padded 48->64, hi/lo
__device__ __half g_wdt_h[2][CDI*CRP],  g_wdt_l[2][CDI*CRP];  // dtproj W padded, hi/lo

// ---------------------------------------------------------------------------
// PTX helpers
// ---------------------------------------------------------------------------
__device__ __forceinline__ uint32_t smem_u32(const void* p) {
    uint32_t a;
    asm("{ .reg .u64 t; cvta.to.shared.u64 t, %1; cvt.u32.u64 %0, t; }" : "=r"(a) : "l"(p));
    return a;
}
__device__ __forceinline__ uint32_t sw128(uint32_t b) { return b ^ ((b >> 3) & 0x70); }

__device__ __forceinline__ void ldsm4(uint32_t addr, uint32_t r[4]) {
    asm volatile("ldmatrix.sync.aligned.m8n8.x4.shared.b16 {%0,%1,%2,%3}, [%4];"
        : "=r"(r[0]), "=r"(r[1]), "=r"(r[2]), "=r"(r[3]) : "r"(addr));
}
__device__ __forceinline__ void mma_f16(float* d, const uint32_t* a, uint32_t b0, uint32_t b1) {
    asm volatile("mma.sync.aligned.m16n8k16.row.col.f32.f16.f16.f32 "
        "{%0,%1,%2,%3}, {%4,%5,%6,%7}, {%8,%9}, {%0,%1,%2,%3};"
        : "+f"(d[0]), "+f"(d[1]), "+f"(d[2]), "+f"(d[3])
        : "r"(a[0]), "r"(a[1]), "r"(a[2]), "r"(a[3]), "r"(b0), "r"(b1));
}
__device__ __forceinline__ void cp16(uint32_t s, const void* g) {
    asm volatile("cp.async.ca.shared.global [%0], [%1], 16;" :: "r"(s), "l"(g));
}

// ---------------------------------------------------------------------------
// 2-term fp16 tensor GEMM (M=128 tile):  C[m,n] = sum_k A[m,k]*B[n,k]
// Exactly one operand side is split (hi+lo fp16); the other is single fp16.
// CTA tile 128x128, BK=64, 2-stage cp.async ring, 96KB smem -> 2 CTA/SM.
// ---------------------------------------------------------------------------
constexpr int GF_STAGE = 49152;
constexpr int GF_SMEM  = 2 * GF_STAGE;   // 98304 B

template <int SPLIT_A>
__global__ void __launch_bounds__(256, 2) gemm_f16_kernel(
    const __half* __restrict__ Ah, const __half* __restrict__ Xl,  // Xl = Al or Bl
    const __half* __restrict__ Bh,
    float* __restrict__ C, int Nout, int Kd,
    long long strideA, long long strideB, long long strideC, int NC)
{
    extern __shared__ __align__(1024) char smem[];
    const uint32_t su = smem_u32(smem);
    Ah += (size_t)blockIdx.z * strideA;
    Bh += (size_t)blockIdx.z * strideB;
    Xl += (size_t)blockIdx.z * (SPLIT_A ? strideA : strideB);
    C  += (size_t)blockIdx.z * strideC;
    const int bm = blockIdx.y * 128;
    const int bn = blockIdx.x * 128;
    const int tid  = threadIdx.x;
    const int wid  = tid >> 5;
    const int lane = tid & 31;

    const int prow = tid >> 3;
    const int pkc  = tid & 7;
    auto issue = [&](int c) {
        const uint32_t sb = su + (uint32_t)(c & 1) * GF_STAGE;
        const int k0 = c * 64;
#pragma unroll
        for (int i = 0; i < 4; ++i) {
            const int row = prow + i * 32;
            const uint32_t off = sw128((uint32_t)(row * 128 + pkc * 16));
            const size_t ga = (size_t)(bm + row) * Kd + k0 + pkc * 8;
            const size_t gb = (size_t)(bn + row) * Kd + k0 + pkc * 8;
            cp16(sb + off,         Ah + ga);
            cp16(sb + 16384 + off, Xl + (SPLIT_A ? ga : gb));
            cp16(sb + 32768 + off, Bh + gb);
        }
        asm volatile("cp.async.commit_group;" ::: "memory");
    };

    const int m0 = (wid & 3) * 32;
    const int n0 = (wid >> 2) * 64;
    const int g    = lane >> 3;
    const int lr   = lane & 7;
    const int lrow = (g & 1) * 8 + lr;
    const int lkb  = (g >> 1) * 16;

    float acc[2][8][4] = {};

    issue(0); issue(1);

    for (int c = 0; c < NC; ++c) {
        asm volatile("cp.async.wait_group 1;" ::: "memory");
        __syncthreads();
        const uint32_t sb = su + (uint32_t)(c & 1) * GF_STAGE;
#pragma unroll
        for (int kk = 0; kk < 4; ++kk) {
            uint32_t ah[2][4], al[2][4];
#pragma unroll
            for (int mt = 0; mt < 2; ++mt) {
                uint32_t off = sw128((uint32_t)((m0 + mt*16 + lrow) * 128 + kk*32 + lkb));
                ldsm4(sb + off, ah[mt]);
                if (SPLIT_A) ldsm4(sb + 16384 + off, al[mt]);
            }
#pragma unroll
            for (int np = 0; np < 4; ++np) {
                uint32_t boff = sw128((uint32_t)((n0 + np*16 + lrow) * 128 + kk*32 + lkb));
                uint32_t bh[4], bl[4];
                ldsm4(sb + 32768 + boff, bh);
                if (!SPLIT_A) ldsm4(sb + 16384 + boff, bl);
#pragma unroll
                for (int mt = 0; mt < 2; ++mt) {
                    if (SPLIT_A) {
                        mma_f16(acc[mt][2*np],   ah[mt], bh[0], bh[2]);
                        mma_f16(acc[mt][2*np],   al[mt], bh[0], bh[2]);
                        mma_f16(acc[mt][2*np+1], ah[mt], bh[1], bh[3]);
                        mma_f16(acc[mt][2*np+1], al[mt], bh[1], bh[3]);
                    } else {
                        mma_f16(acc[mt][2*np],   ah[mt], bh[0], bh[2]);
                        mma_f16(acc[mt][2*np],   ah[mt], bl[0], bl[2]);
                        mma_f16(acc[mt][2*np+1], ah[mt], bh[1], bh[3]);
                        mma_f16(acc[mt][2*np+1], ah[mt], bl[1], bl[3]);
                    }
                }
            }
        }
        __syncthreads();
        if (c + 2 < NC) issue(c + 2);
        else asm volatile("cp.async.commit_group;" ::: "memory");
    }

    const int er = lane >> 2;
    const int ec = (lane & 3) * 2;
#pragma unroll
    for (int mt = 0; mt < 2; ++mt) {
#pragma unroll
        for (int nt = 0; nt < 8; ++nt) {
            const int row = bm + m0 + mt*16 + er;
            const int col = bn + n0 + nt*8 + ec;
            if (col < Nout) {
                float2 lo = { acc[mt][nt][0], acc[mt][nt][1] };
                float2 hi = { acc[mt][nt][2], acc[mt][nt][3] };
                *(float2*)(C + (size_t)row * Nout + col)       = lo;
                *(float2*)(C + (size_t)(row + 8) * Nout + col) = hi;
            }
        }
    }
}

// ---------------------------------------------------------------------------
// xproj tensor GEMM, M=64 CTA tile for grid fill (256 CTAs vs 128).
// A = xt (split hi/lo), B = wx (single, 128 padded rows). 8 warps = 2m x 4n,
// warp tile 32x32. Stage 32KB (Ah 8K | Al 8K | Bh 16K), 2 stages = 64KB smem.
// Epilogue: cols<64 -> dt fp16 hi/lo (value if col<48 else 0); cols 48..79 ->
// fp32 dbl store.
// ---------------------------------------------------------------------------
constexpr int XP_STAGE = 32768;
constexpr int XP_SMEM  = 2 * XP_STAGE;   // 65536 B

__global__ void __launch_bounds__(256, 2) xproj_kernel()
{
    extern __shared__ __align__(1024) char smem[];
    const uint32_t su = smem_u32(smem);
    const int dir = blockIdx.z;
    const __half* Ah = &g_xth[dir][0];
    const __half* Al = &g_xtl[dir][0];
    const __half* Bh = &g_wx[dir][0];
    float* C   = &g_dbl[dir][0];
    __half* dH = &g_dt_h[dir][0];
    __half* dL = &g_dt_l[dir][0];

    const int bm = blockIdx.y * 64;
    const int tid  = threadIdx.x;
    const int wid  = tid >> 5;
    const int lane = tid & 31;

    const int prow = tid >> 3;          // 0..31
    const int pkc  = tid & 7;
    auto issue = [&](int c) {
        const uint32_t sb = su + (uint32_t)(c & 1) * XP_STAGE;
        const int k0 = c * 64;
#pragma unroll
        for (int i = 0; i < 2; ++i) {   // A: 64 rows, hi+lo
            const int row = prow + i * 32;
            const uint32_t off = sw128((uint32_t)(row * 128 + pkc * 16));
            const size_t ga = (size_t)(bm + row) * CDI + k0 + pkc * 8;
            cp16(sb + off,        Ah + ga);
            cp16(sb + 8192 + off, Al + ga);
        }
#pragma unroll
        for (int i = 0; i < 4; ++i) {   // B: 128 rows
            const int row = prow + i * 32;
            const uint32_t off = sw128((uint32_t)(row * 128 + pkc * 16));
            const size_t gb = (size_t)row * CDI + k0 + pkc * 8;
            cp16(sb + 16384 + off, Bh + gb);
        }
        asm volatile("cp.async.commit_group;" ::: "memory");
    };

    // 2m x 4n warps; warp tile 32 (m) x 32 (n)
    const int m0 = (wid & 1) * 32;
    const int n0 = (wid >> 1) * 32;
    const int g    = lane >> 3;
    const int lr   = lane & 7;
    const int lrow = (g & 1) * 8 + lr;
    const int lkb  = (g >> 1) * 16;

    float acc[2][4][4] = {};

    issue(0); issue(1);

    const int NC = CDI / 64;            // 24
    for (int c = 0; c < NC; ++c) {
        asm volatile("cp.async.wait_group 1;" ::: "memory");
        __syncthreads();
        const uint32_t sb = su + (uint32_t)(c & 1) * XP_STAGE;
#pragma unroll
        for (int kk = 0; kk < 4; ++kk) {
            uint32_t ah[2][4], al[2][4];
#pragma unroll
            for (int mt = 0; mt < 2; ++mt) {
                uint32_t off = sw128((uint32_t)((m0 + mt*16 + lrow) * 128 + kk*32 + lkb));
                ldsm4(sb + off,        ah[mt]);
                ldsm4(sb + 8192 + off, al[mt]);
            }
#pragma unroll
            for (int np = 0; np < 2; ++np) {
                uint32_t boff = sw128((uint32_t)((n0 + np*16 + lrow) * 128 + kk*32 + lkb));
                uint32_t bh[4];
                ldsm4(sb + 16384 + boff, bh);
#pragma unroll
                for (int mt = 0; mt < 2; ++mt) {
                    mma_f16(acc[mt][2*np],   ah[mt], bh[0], bh[2]);
                    mma_f16(acc[mt][2*np],   al[mt], bh[0], bh[2]);
                    mma_f16(acc[mt][2*np+1], ah[mt], bh[1], bh[3]);
                    mma_f16(acc[mt][2*np+1], al[mt], bh[1], bh[3]);
                }
            }
        }
        __syncthreads();
        if (c + 2 < NC) issue(c + 2);
        else asm volatile("cp.async.commit_group;" ::: "memory");
    }

    const int er = lane >> 2;
    const int ec = (lane & 3) * 2;
#pragma unroll
    for (int mt = 0; mt < 2; ++mt) {
#pragma unroll
        for (int nt = 0; nt < 4; ++nt) {
            const int row0 = bm + m0 + mt*16 + er;
            const int col  = n0 + nt*8 + ec;
#pragma unroll
            for (int rr = 0; rr < 2; ++rr) {
                const int row = row0 + rr*8;
#pragma unroll
                for (int e = 0; e < 2; ++e) {
                    const int cc = col + e;
                    const float v = acc[mt][nt][rr*2+e];
                    if (cc < CRP) {
                        float dv = (cc < CR) ? v : 0.f;
                        __half hb = __float2half_rn(dv);
                        dH[(size_t)row * CRP + cc] = hb;
                        dL[(size_t)row * CRP + cc] =
                            __float2half_rn(dv - __half2float(hb));
                    }
                    if (cc >= CR && cc < CPROJ)
                        C[(size_t)row * CPROJ + cc] = v;
                }
            }
        }
    }
}

// ---------------------------------------------------------------------------
// dtproj tensor GEMM: delta[row,d] = softplus(sum_r dt[row,r]*W[d,r] + bias[d])
// ---------------------------------------------------------------------------
__device__ __forceinline__ float softplus_f(float v) {
    return (v > 20.f) ? v : log1pf(__expf(v));
}

__global__ void __launch_bounds__(256) dtgemm_kernel(
    const float* __restrict__ bias_f, const float* __restrict__ bias_b)
{
    extern __shared__ __align__(1024) char smem[];
    const uint32_t su = smem_u32(smem);
    const int dir = blockIdx.z;
    const __half* Ah = &g_dt_h[dir][0];
    const __half* Al = &g_dt_l[dir][0];
    const __half* Bh = &g_wdt_h[dir][0];
    const __half* Bl = &g_wdt_l[dir][0];
    const float* bias = dir ? bias_b : bias_f;
    float* C = &g_delta[dir][0];

    const int bm = blockIdx.y * 128;
    const int bn = blockIdx.x * 128;
    const int tid  = threadIdx.x;
    const int wid  = tid >> 5;
    const int lane = tid & 31;

    const int prow = tid >> 3;
    const int pkc  = tid & 7;
#pragma unroll
    for (int i = 0; i < 4; ++i) {
        const int row = prow + i * 32;
        const uint32_t off = sw128((uint32_t)(row * 128 + pkc * 16));
        const size_t ga = (size_t)(bm + row) * CRP + pkc * 8;
        const size_t gb = (size_t)(bn + row) * CRP + pkc * 8;
        cp16(su + off,         Ah + ga);
        cp16(su + 16384 + off, Al + ga);
        cp16(su + 32768 + off, Bh + gb);
        cp16(su + 49152 + off, Bl + gb);
    }
    asm volatile("cp.async.commit_group;" ::: "memory");
    asm volatile("cp.async.wait_group 0;" ::: "memory");
    __syncthreads();

    const int m0 = (wid & 3) * 32;
    const int n0 = (wid >> 2) * 64;
    const int g    = lane >> 3;
    const int lr   = lane & 7;
    const int lrow = (g & 1) * 8 + lr;
    const int lkb  = (g >> 1) * 16;

    float acc[2][8][4] = {};
#pragma unroll
    for (int kk = 0; kk < 4; ++kk) {
        uint32_t ah[2][4], al[2][4];
#pragma unroll
        for (int mt = 0; mt < 2; ++mt) {
            uint32_t off = sw128((uint32_t)((m0 + mt*16 + lrow) * 128 + kk*32 + lkb));
            ldsm4(su + off,         ah[mt]);
            ldsm4(su + 16384 + off, al[mt]);
        }
#pragma unroll
        for (int np = 0; np < 4; ++np) {
            uint32_t boff = sw128((uint32_t)((n0 + np*16 + lrow) * 128 + kk*32 + lkb));
            uint32_t bh[4], bl[4];
            ldsm4(su + 32768 + boff, bh);
            ldsm4(su + 49152 + boff, bl);
#pragma unroll
            for (int mt = 0; mt < 2; ++mt) {
                mma_f16(acc[mt][2*np],   ah[mt], bh[0], bh[2]);
                mma_f16(acc[mt][2*np],   al[mt], bh[0], bh[2]);
                mma_f16(acc[mt][2*np],   ah[mt], bl[0], bl[2]);
                mma_f16(acc[mt][2*np+1], ah[mt], bh[1], bh[3]);
                mma_f16(acc[mt][2*np+1], al[mt], bh[1], bh[3]);
                mma_f16(acc[mt][2*np+1], ah[mt], bl[1], bl[3]);
            }
        }
    }

    const int er = lane >> 2;
    const int ec = (lane & 3) * 2;
#pragma unroll
    for (int mt = 0; mt < 2; ++mt) {
#pragma unroll
        for (int nt = 0; nt < 8; ++nt) {
            const int row = bm + m0 + mt*16 + er;
            const int col = bn + n0 + nt*8 + ec;
            const float b0 = bias[col], b1 = bias[col+1];
            float2 lo = { softplus_f(acc[mt][nt][0] + b0),
                          softplus_f(acc[mt][nt][1] + b1) };
            float2 hi = { softplus_f(acc[mt][nt][2] + b0),
                          softplus_f(acc[mt][nt][3] + b1) };
            *(float2*)(C + (size_t)row * CDI + col)       = lo;
            *(float2*)(C + (size_t)(row + 8) * CDI + col) = hi;
        }
    }
}

// ---------------------------------------------------------------------------
// fp32 -> fp16 hi/lo splitter and single-fp16 converter (grid-stride, float4)
// ---------------------------------------------------------------------------
__global__ void split2_kernel(const float* __restrict__ s,
                              __half* __restrict__ h, __half* __restrict__ l, int n4)
{
    for (int i = blockIdx.x * blockDim.x + threadIdx.x; i < n4;
         i += gridDim.x * blockDim.x) {
        float4 v = ((const float4*)s)[i];
        __half hx = __float2half_rn(v.x), hy = __float2half_rn(v.y);
        __half hz = __float2half_rn(v.z), hw = __float2half_rn(v.w);
        __half lx = __float2half_rn(v.x - __half2float(hx));
        __half ly = __float2half_rn(v.y - __half2float(hy));
        __half lz = __float2half_rn(v.z - __half2float(hz));
        __half lw = __float2half_rn(v.w - __half2float(hw));
        __half2 h01 = __halves2half2(hx, hy), h23 = __halves2half2(hz, hw);
        __half2 l01 = __halves2half2(lx, ly), l23 = __halves2half2(lz, lw);
        ((uint2*)h)[i] = make_uint2(*(uint32_t*)&h01, *(uint32_t*)&h23);
        ((uint2*)l)[i] = make_uint2(*(uint32_t*)&l01, *(uint32_t*)&l23);
    }
}

__global__ void tof16_kernel(const float* __restrict__ s, __half* __restrict__ h, int n4)
{
    for (int i = blockIdx.x * blockDim.x + threadIdx.x; i < n4;
         i += gridDim.x * blockDim.x) {
        float4 v = ((const float4*)s)[i];
        __half2 h01 = __halves2half2(__float2half_rn(v.x), __float2half_rn(v.y));
        __half2 h23 = __halves2half2(__float2half_rn(v.z), __float2half_rn(v.w));
        ((uint2*)h)[i] = make_uint2(*(uint32_t*)&h01, *(uint32_t*)&h23);
    }
}

// xproj weights: pad 80 -> 128 rows (zeros), single fp16, both dirs.
__global__ void padw_kernel(const float* __restrict__ wf, const float* __restrict__ wb)
{
    const int total4 = 2 * 128 * CDI / 4;
    for (int i = blockIdx.x * blockDim.x + threadIdx.x; i < total4;
         i += gridDim.x * blockDim.x) {
        int e = i * 4;
        int dir = e / (128 * CDI);
        int rem = e - dir * 128 * CDI;
        int row = rem / CDI;
        int k   = rem - row * CDI;
        float4 v = {0.f, 0.f, 0.f, 0.f};
        const float* W = dir ? wb : wf;
        if (row < CPROJ) v = *(const float4*)(W + (size_t)row * CDI + k);
        __half2 h01 = __halves2half2(__float2half_rn(v.x), __float2half_rn(v.y));
        __half2 h23 = __halves2half2(__float2half_rn(v.z), __float2half_rn(v.w));
        ((uint2*)&g_wx[0][0])[i] = make_uint2(*(uint32_t*)&h01, *(uint32_t*)&h23);
    }
}

// dtproj weights: pad K 48 -> 64 (zeros), split to fp16 hi/lo, both dirs.
__global__ void padwd_kernel(const float* __restrict__ wf, const float* __restrict__ wb)
{
    const int total4 = 2 * CDI * CRP / 4;
    for (int i = blockIdx.x * blockDim.x + threadIdx.x; i < total4;
         i += gridDim.x * blockDim.x) {
        int e = i * 4;
        int dir = e / (CDI * CRP);
        int rem = e - dir * CDI * CRP;
        int row = rem / CRP;
        int k   = rem - row * CRP;
        float4 v = {0.f, 0.f, 0.f, 0.f};
        const float* W = dir ? wb : wf;
        if (k < CR) v = *(const float4*)(W + (size_t)row * CR + k);
        __half hx = __float2half_rn(v.x), hy = __float2half_rn(v.y);
        __half hz = __float2half_rn(v.z), hw = __float2half_rn(v.w);
        __half lx = __float2half_rn(v.x - __half2float(hx));
        __half ly = __float2half_rn(v.y - __half2float(hy));
        __half lz = __float2half_rn(v.z - __half2float(hz));
        __half lw = __float2half_rn(v.w - __half2float(hw));
        __half2 h01 = __halves2half2(hx, hy), h23 = __halves2half2(hz, hw);
        __half2 l01 = __halves2half2(lx, ly), l23 = __halves2half2(lz, lw);
        ((uint2*)&g_wdt_h[0][0])[i] = make_uint2(*(uint32_t*)&h01, *(uint32_t*)&h23);
        ((uint2*)&g_wdt_l[0][0])[i] = make_uint2(*(uint32_t*)&l01, *(uint32_t*)&l23);
    }
}

// ---------------------------------------------------------------------------
// Depthwise causal conv (K=4) + bias + SiLU, transpose to (b,t,d).
// MERGED DIRECTIONS: one block loads x[t0-3 .. t0+130] once, emits both dirs.
// ---------------------------------------------------------------------------
__global__ void __launch_bounds__(256) conv_silu_kernel(
    const float* __restrict__ cw_f, const float* __restrict__ cb_f,
    const float* __restrict__ cw_b, const float* __restrict__ cb_b)
{
    const int t0 = blockIdx.x * 128;
    const int d0 = blockIdx.y * 32;
    const int b  = blockIdx.z;

    __shared__ float xs[32][135];

    const float* xbase = g_xz + ((size_t)b * (2*CDI) + d0) * CL;
    const int base = t0 - 3;

    const int lane = threadIdx.x & 31;
    const int wy   = threadIdx.x >> 5;
    for (int d = wy; d < 32; d += 8) {
        const float* row = xbase + (size_t)d * CL;
        for (int i = lane; i < 134; i += 32) {
            int u = base + i;
            xs[d][i] = (u >= 0 && u < CL) ? row[u] : 0.f;
        }
    }
    __syncthreads();

    const int d  = threadIdx.x & 31;
    const int sg = threadIdx.x >> 5;
    const float wf0 = cw_f[(d0+d)*CK + 0];
    const float wf1 = cw_f[(d0+d)*CK + 1];
    const float wf2 = cw_f[(d0+d)*CK + 2];
    const float wf3 = cw_f[(d0+d)*CK + 3];
    const float bf  = cb_f[d0+d];
    const float wb0 = cw_b[(d0+d)*CK + 0];
    const float wb1 = cw_b[(d0+d)*CK + 1];
    const float wb2 = cw_b[(d0+d)*CK + 2];
    const float wb3 = cw_b[(d0+d)*CK + 3];
    const float bb  = cb_b[d0+d];

    __half* ohf = g_xth[0] + (size_t)b * CL * CDI;
    __half* olf = g_xtl[0] + (size_t)b * CL * CDI;
    __half* ohb = g_xth[1] + (size_t)b * CL * CDI;
    __half* olb = g_xtl[1] + (size_t)b * CL * CDI;
    const int tb0 = CL - 128 - t0;
#pragma unroll
    for (int q = 0; q < 16; ++q) {
        int s = sg + 8*q;
        {
            float v = wf0*xs[d][s] + wf1*xs[d][s+1] + wf2*xs[d][s+2] + wf3*xs[d][s+3] + bf;
            float sv = v / (1.f + __expf(-v));
            size_t idx = (size_t)(t0 + s) * CDI + d0 + d;
            __half hb = __float2half_rn(sv);
            ohf[idx] = hb;
            olf[idx] = __float2half_rn(sv - __half2float(hb));
        }
        {
            float v = wb3*xs[d][130-s] + wb2*xs[d][131-s] + wb1*xs[d][132-s]
                    + wb0*xs[d][133-s] + bb;
            float sv = v / (1.f + __expf(-v));
            size_t idx = (size_t)(tb0 + s) * CDI + d0 + d;
            __half hb = __float2half_rn(sv);
            ohb[idx] = hb;
            olb[idx] = __float2half_rn(sv - __half2float(hb));
        }
    }
}

// ---------------------------------------------------------------------------
// Selective scan (round-5 version: 4 scalar arrays, deep load batching)
// ---------------------------------------------------------------------------
__global__ void __launch_bounds__(256) scan_kernel(
    const float* __restrict__ Alog_f, const float* __restrict__ Dv_f,
    const float* __restrict__ Alog_b, const float* __restrict__ Dv_b)
{
    const int dir = blockIdx.z;
    const int b   = blockIdx.y;
    const int d0  = blockIdx.x * 16;

    const float* Alog = dir ? Alog_b : Alog_f;
    const float* Dvec = dir ? Dv_b   : Dv_f;
    const float* delta = g_delta[dir] + (size_t)b * CL * CDI;
    const __half* xth  = g_xth[dir]   + (size_t)b * CL * CDI;
    const __half* xtl  = g_xtl[dir]   + (size_t)b * CL * CDI;
    const float* dbl   = g_dbl[dir]   + (size_t)b * CL * CPROJ;
    float* yout        = g_y[dir]     + (size_t)b * CL * CDI;

    __shared__ __align__(16) float sd[64][16];
    __shared__ __align__(16) float sx[64][16];
    __shared__ __align__(16) float sB[64][16];
    __shared__ __align__(16) float sC[64][16];

    const int tid  = threadIdx.x;
    const int lane = tid & 31;
    const int wid  = tid >> 5;
    const int half = lane >> 4;
    const int n    = lane & 15;
    const int ch   = wid*2 + half;
    const int d    = d0 + ch;

    const float Aval = -__expf(Alog[d*CN + n]);
    const float Dval = Dvec[d];
    float h = 0.f;

    const int li = tid >> 2;
    const int lj = (tid & 3) * 4;

    float4 rd, rB, rC, rx;
    auto LD = [&](int t0) {
        rd = *(const float4*)(delta + (size_t)(t0+li)*CDI + d0 + lj);
        uint2 xh = *(const uint2*)(xth + (size_t)(t0+li)*CDI + d0 + lj);
        uint2 xl = *(const uint2*)(xtl + (size_t)(t0+li)*CDI + d0 + lj);
        __half2 h01 = *(__half2*)&xh.x, h23 = *(__half2*)&xh.y;
        __half2 l01 = *(__half2*)&xl.x, l23 = *(__half2*)&xl.y;
        float2 fh01 = __half22float2(h01), fh23 = __half22float2(h23);
        float2 fl01 = __half22float2(l01), fl23 = __half22float2(l23);
        rx.x = fh01.x + fl01.x; rx.y = fh01.y + fl01.y;
        rx.z = fh23.x + fl23.x; rx.w = fh23.y + fl23.y;
        rB = *(const float4*)(dbl + (size_t)(t0+li)*CPROJ + CR + lj);
        rC = *(const float4*)(dbl + (size_t)(t0+li)*CPROJ + CR + CN + lj);
    };
    LD(0);

    const int NCH = CL / 64;
    for (int c = 0; c < NCH; ++c) {
        __syncthreads();
        *(float4*)&sd[li][lj] = rd;
        *(float4*)&sx[li][lj] = rx;
        *(float4*)&sB[li][lj] = rB;
        *(float4*)&sC[li][lj] = rC;
        __syncthreads();
        if (c + 1 < NCH) LD((c+1) * 64);

        const int tbase = c * 64;
#pragma unroll 8
        for (int s = 0; s < 64; ++s) {
            float dt = sd[s][ch];
            float xv = sx[s][ch];
            float Bv = sB[s][n];
            float Cv = sC[s][n];
            float a = __expf(dt * Aval);
            h = fmaf(a, h, dt * xv * Bv);
            float p = h * Cv;
            p += __shfl_xor_sync(0xffffffffu, p, 8);
            p += __shfl_xor_sync(0xffffffffu, p, 4);
            p += __shfl_xor_sync(0xffffffffu, p, 2);
            p += __shfl_xor_sync(0xffffffffu, p, 1);
            if (n == 0)
                yout[(size_t)(tbase + s)*CDI + d] = p + xv * Dval;
        }
    }
}

// ---------------------------------------------------------------------------
// Gate + direction merge -> fp16 hi/lo comb (out_proj split operand)
// ---------------------------------------------------------------------------
__global__ void __launch_bounds__(256) combine_kernel()
{
    const int l0 = blockIdx.x * 32;
    const int d0 = blockIdx.y * 32;
    const int b  = blockIdx.z;

    __shared__ float zs[32][33];
    const int lane = threadIdx.x & 31;
    const int wy   = threadIdx.x >> 5;

    const float* zbase = g_xz + ((size_t)b * (2*CDI) + CDI + d0) * CL;
    for (int dd = wy; dd < 32; dd += 8)
        zs[dd][lane] = zbase[(size_t)dd * CL + l0 + lane];
    __syncthreads();

#pragma unroll
    for (int q = 0; q < 4; ++q) {
        int lr = wy + 8*q;
        int l = l0 + lr;
        size_t idx  = ((size_t)b*CL + l)*CDI + d0 + lane;
        size_t idxr = ((size_t)b*CL + (CL-1-l))*CDI + d0 + lane;
        float yf = g_y[0][idx];
        float yb = g_y[1][idxr];
        float zv = zs[lane][lr];
        float s = zv / (1.f + __expf(-zv));
        float cv = (yf + yb) * s;
        __half hb = __float2half_rn(cv);
        g_cmb_h[idx] = hb;
        g_cmb_l[idx] = __float2half_rn(cv - __half2float(hb));
    }
}

// ---------------------------------------------------------------------------
// Launcher
// ---------------------------------------------------------------------------
extern "C" void kernel_launch(void* const* d_in, const int* in_sizes, int n_in,
                              void* d_out, int out_size)
{
    (void)in_sizes; (void)n_in; (void)out_size;

    const float* hidden  = (const float*)d_in[0];
    const float* in_w    = (const float*)d_in[1];
    const float* conv_w  = (const float*)d_in[2];
    const float* conv_b  = (const float*)d_in[3];
    const float* xproj_w = (const float*)d_in[4];
    const float* dtw     = (const float*)d_in[5];
    const float* dtb     = (const float*)d_in[6];
    const float* A_log   = (const float*)d_in[7];
    const float* Dv      = (const float*)d_in[8];
    const float* conv_w2 = (const float*)d_in[9];
    const float* conv_b2 = (const float*)d_in[10];
    const float* xproj_w2= (const float*)d_in[11];
    const float* dtw2    = (const float*)d_in[12];
    const float* dtb2    = (const float*)d_in[13];
    const float* A_log2  = (const float*)d_in[14];
    const float* Dv2     = (const float*)d_in[15];
    const float* out_w   = (const float*)d_in[16];

    void *p_xz;
    void *p_hid_h, *p_hid_l, *p_w1, *p_w2, *p_cmb_h, *p_cmb_l;
    cudaGetSymbolAddress(&p_xz, g_xz);
    cudaGetSymbolAddress(&p_hid_h, g_hid_h);
    cudaGetSymbolAddress(&p_hid_l, g_hid_l);
    cudaGetSymbolAddress(&p_w1, g_w1);
    cudaGetSymbolAddress(&p_w2, g_w2);
    cudaGetSymbolAddress(&p_cmb_h, g_cmb_h);
    cudaGetSymbolAddress(&p_cmb_l, g_cmb_l);

    cudaFuncSetAttribute(gemm_f16_kernel<0>,
                         cudaFuncAttributeMaxDynamicSharedMemorySize, GF_SMEM);
    cudaFuncSetAttribute(gemm_f16_kernel<1>,
                         cudaFuncAttributeMaxDynamicSharedMemorySize, GF_SMEM);
    cudaFuncSetAttribute(xproj_kernel,
                         cudaFuncAttributeMaxDynamicSharedMemorySize, XP_SMEM);
    cudaFuncSetAttribute(dtgemm_kernel,
                         cudaFuncAttributeMaxDynamicSharedMemorySize, 65536);

    // 0) operand packing
    split2_kernel<<<1024, 256>>>(hidden, (__half*)p_hid_h, (__half*)p_hid_l, CB*CL*CDM/4);
    tof16_kernel<<<512, 256>>>(in_w, (__half*)p_w1, 2*CDI*CDM/4);
    tof16_kernel<<<512, 256>>>(out_w, (__half*)p_w2, CDM*CDI/4);
    padw_kernel<<<512, 256>>>(xproj_w, xproj_w2);
    padwd_kernel<<<192, 256>>>(dtw, dtw2);

    // 1) in_proj: A = w1 (single), B = hidden (split).  M=3072, N=4096, K=768
    gemm_f16_kernel<0><<<dim3(CL/128, (2*CDI)/128, CB), 256, GF_SMEM>>>(
        (const __half*)p_w1, (const __half*)p_hid_l, (const __half*)p_hid_h,
        (float*)p_xz, CL, CDM,
        0, (long long)CL * CDM, (long long)(2*CDI) * CL, CDM / 64);

    // 2) conv + SiLU + transpose (both dirs per block) -> fp16 hi/lo xt
    conv_silu_kernel<<<dim3(CL/128, CDI/32, CB), 256>>>(
        conv_w, conv_b, conv_w2, conv_b2);

    // 3) xproj, M=64 tiles (256 CTAs): dt fp16 hi/lo + fp32 B|C
    xproj_kernel<<<dim3(1, (CB*CL)/64, 2), 256, XP_SMEM>>>();

    // 4) dtproj as tensor GEMM + softplus -> delta
    dtgemm_kernel<<<dim3(CDI/128, (CB*CL)/128, 2), 256, 65536>>>(dtb, dtb2);

    // 5) selective scan
    scan_kernel<<<dim3(CDI/16, CB, 2), 256>>>(A_log, Dv, A_log2, Dv2);

    // 6) gate + direction merge -> fp16 hi/lo comb
    combine_kernel<<<dim3(CL/32, CDI/32, CB), 256>>>();

    // 7) out_proj: A = comb (split), B = w2 (single).  M=8192, N=768, K=1536
    gemm_f16_kernel<1><<<dim3(CDM/128, (CB*CL)/128, 1), 256, GF_SMEM>>>(
        (const __half*)p_cmb_h, (const __half*)p_cmb_l, (const __half*)p_w2,
        (float*)d_out, CDM, CDI,
        0, 0, 0, CDI / 64);
}

// round 11
// speedup vs baseline: 1.1927x; 1.0295x over previous
#include <cuda_runtime.h>
#include <cuda_fp16.h>
#include <cstdint>

// Problem constants
constexpr int CB  = 2;     // batch
constexpr int CL  = 4096;  // seq len
constexpr int CDM = 768;   // d_model
constexpr int CDI = 1536;  // d_inner
constexpr int CN  = 16;    // state dim
constexpr int CR  = 48;    // dt rank
constexpr int CK  = 4;     // conv width
constexpr int CPROJ = CR + 2*CN; // 80
constexpr int CRP = 64;    // dt rank padded for MMA K

// ---------------------------------------------------------------------------
// Scratch (device globals; no runtime allocation allowed)
// ---------------------------------------------------------------------------
__device__ float g_xz[CB * 2 * CDI * CL];        // (b, e, l)
__device__ float g_dbl[2][CB * CL * CPROJ];      // per dir, (b*L, 80): only B|C cols used
__device__ float g_delta[2][CB * CL * CDI];      // per dir, post-softplus
__device__ float g_y[2][CB * CL * CDI];          // per dir, scan out (+D*x)

// fp16 operands for tensor GEMMs
__device__ __half g_hid_h[CB*CL*CDM], g_hid_l[CB*CL*CDM];  // hidden hi/lo (split side)
__device__ __half g_w1[2*CDI*CDM];                          // in_proj W (single)
__device__ __half g_w2[CDM*CDI];                            // out_proj W (single)
__device__ __half g_wx[2][128*CDI];                         // xproj W padded 80->128 (single)
__device__ __half g_xth[2][CB*CL*CDI], g_xtl[2][CB*CL*CDI]; // conv out hi/lo (split side)
__device__ __half g_cmb_h[CB*CL*CDI],  g_cmb_l[CB*CL*CDI];  // gated sum hi/lo (split side)
__device__ __half g_dt_h[2][CB*CL*CRP], g_dt_l[2][CB*CL*CRP]; // dt rows padded 48->64, hi/lo
__device__ __half g_wdt_h[2][CDI*CRP],  g_wdt_l[2][CDI*CRP];  // dtproj W padded, hi/lo

// ---------------------------------------------------------------------------
// PTX helpers
// ---------------------------------------------------------------------------
__device__ __forceinline__ uint32_t smem_u32(const void* p) {
    uint32_t a;
    asm("{ .reg .u64 t; cvta.to.shared.u64 t, %1; cvt.u32.u64 %0, t; }" : "=r"(a) : "l"(p));
    return a;
}
__device__ __forceinline__ uint32_t sw128(uint32_t b) { return b ^ ((b >> 3) & 0x70); }

__device__ __forceinline__ void ldsm4(uint32_t addr, uint32_t r[4]) {
    asm volatile("ldmatrix.sync.aligned.m8n8.x4.shared.b16 {%0,%1,%2,%3}, [%4];"
        : "=r"(r[0]), "=r"(r[1]), "=r"(r[2]), "=r"(r[3]) : "r"(addr));
}
__device__ __forceinline__ void mma_f16(float* d, const uint32_t* a, uint32_t b0, uint32_t b1) {
    asm volatile("mma.sync.aligned.m16n8k16.row.col.f32.f16.f16.f32 "
        "{%0,%1,%2,%3}, {%4,%5,%6,%7}, {%8,%9}, {%0,%1,%2,%3};"
        : "+f"(d[0]), "+f"(d[1]), "+f"(d[2]), "+f"(d[3])
        : "r"(a[0]), "r"(a[1]), "r"(a[2]), "r"(a[3]), "r"(b0), "r"(b1));
}
__device__ __forceinline__ void cp16(uint32_t s, const void* g) {
    asm volatile("cp.async.ca.shared.global [%0], [%1], 16;" :: "r"(s), "l"(g));
}
__device__ __forceinline__ float ex2f(float x) {
    float r;
    asm("ex2.approx.f32 %0, %1;" : "=f"(r) : "f"(x));
    return r;
}

// ---------------------------------------------------------------------------
// 2-term fp16 tensor GEMM (M=128 tile):  C[m,n] = sum_k A[m,k]*B[n,k]
// Exactly one operand side is split (hi+lo fp16); the other is single fp16.
// CTA tile 128x128, BK=64, 2-stage cp.async ring, 96KB smem -> 2 CTA/SM.
// ---------------------------------------------------------------------------
constexpr int GF_STAGE = 49152;
constexpr int GF_SMEM  = 2 * GF_STAGE;   // 98304 B

template <int SPLIT_A>
__global__ void __launch_bounds__(256, 2) gemm_f16_kernel(
    const __half* __restrict__ Ah, const __half* __restrict__ Xl,  // Xl = Al or Bl
    const __half* __restrict__ Bh,
    float* __restrict__ C, int Nout, int Kd,
    long long strideA, long long strideB, long long strideC, int NC)
{
    extern __shared__ __align__(1024) char smem[];
    const uint32_t su = smem_u32(smem);
    Ah += (size_t)blockIdx.z * strideA;
    Bh += (size_t)blockIdx.z * strideB;
    Xl += (size_t)blockIdx.z * (SPLIT_A ? strideA : strideB);
    C  += (size_t)blockIdx.z * strideC;
    const int bm = blockIdx.y * 128;
    const int bn = blockIdx.x * 128;
    const int tid  = threadIdx.x;
    const int wid  = tid >> 5;
    const int lane = tid & 31;

    const int prow = tid >> 3;
    const int pkc  = tid & 7;
    auto issue = [&](int c) {
        const uint32_t sb = su + (uint32_t)(c & 1) * GF_STAGE;
        const int k0 = c * 64;
#pragma unroll
        for (int i = 0; i < 4; ++i) {
            const int row = prow + i * 32;
            const uint32_t off = sw128((uint32_t)(row * 128 + pkc * 16));
            const size_t ga = (size_t)(bm + row) * Kd + k0 + pkc * 8;
            const size_t gb = (size_t)(bn + row) * Kd + k0 + pkc * 8;
            cp16(sb + off,         Ah + ga);
            cp16(sb + 16384 + off, Xl + (SPLIT_A ? ga : gb));
            cp16(sb + 32768 + off, Bh + gb);
        }
        asm volatile("cp.async.commit_group;" ::: "memory");
    };

    const int m0 = (wid & 3) * 32;
    const int n0 = (wid >> 2) * 64;
    const int g    = lane >> 3;
    const int lr   = lane & 7;
    const int lrow = (g & 1) * 8 + lr;
    const int lkb  = (g >> 1) * 16;

    float acc[2][8][4] = {};

    issue(0); issue(1);

    for (int c = 0; c < NC; ++c) {
        asm volatile("cp.async.wait_group 1;" ::: "memory");
        __syncthreads();
        const uint32_t sb = su + (uint32_t)(c & 1) * GF_STAGE;
#pragma unroll
        for (int kk = 0; kk < 4; ++kk) {
            uint32_t ah[2][4], al[2][4];
#pragma unroll
            for (int mt = 0; mt < 2; ++mt) {
                uint32_t off = sw128((uint32_t)((m0 + mt*16 + lrow) * 128 + kk*32 + lkb));
                ldsm4(sb + off, ah[mt]);
                if (SPLIT_A) ldsm4(sb + 16384 + off, al[mt]);
            }
#pragma unroll
            for (int np = 0; np < 4; ++np) {
                uint32_t boff = sw128((uint32_t)((n0 + np*16 + lrow) * 128 + kk*32 + lkb));
                uint32_t bh[4], bl[4];
                ldsm4(sb + 32768 + boff, bh);
                if (!SPLIT_A) ldsm4(sb + 16384 + boff, bl);
#pragma unroll
                for (int mt = 0; mt < 2; ++mt) {
                    if (SPLIT_A) {
                        mma_f16(acc[mt][2*np],   ah[mt], bh[0], bh[2]);
                        mma_f16(acc[mt][2*np],   al[mt], bh[0], bh[2]);
                        mma_f16(acc[mt][2*np+1], ah[mt], bh[1], bh[3]);
                        mma_f16(acc[mt][2*np+1], al[mt], bh[1], bh[3]);
                    } else {
                        mma_f16(acc[mt][2*np],   ah[mt], bh[0], bh[2]);
                        mma_f16(acc[mt][2*np],   ah[mt], bl[0], bl[2]);
                        mma_f16(acc[mt][2*np+1], ah[mt], bh[1], bh[3]);
                        mma_f16(acc[mt][2*np+1], ah[mt], bl[1], bl[3]);
                    }
                }
            }
        }
        __syncthreads();
        if (c + 2 < NC) issue(c + 2);
        else asm volatile("cp.async.commit_group;" ::: "memory");
    }

    const int er = lane >> 2;
    const int ec = (lane & 3) * 2;
#pragma unroll
    for (int mt = 0; mt < 2; ++mt) {
#pragma unroll
        for (int nt = 0; nt < 8; ++nt) {
            const int row = bm + m0 + mt*16 + er;
            const int col = bn + n0 + nt*8 + ec;
            if (col < Nout) {
                float2 lo = { acc[mt][nt][0], acc[mt][nt][1] };
                float2 hi = { acc[mt][nt][2], acc[mt][nt][3] };
                *(float2*)(C + (size_t)row * Nout + col)       = lo;
                *(float2*)(C + (size_t)(row + 8) * Nout + col) = hi;
            }
        }
    }
}

// ---------------------------------------------------------------------------
// xproj tensor GEMM, M=64 CTA tile for grid fill (256 CTAs vs 128).
// ---------------------------------------------------------------------------
constexpr int XP_STAGE = 32768;
constexpr int XP_SMEM  = 2 * XP_STAGE;   // 65536 B

__global__ void __launch_bounds__(256, 2) xproj_kernel()
{
    extern __shared__ __align__(1024) char smem[];
    const uint32_t su = smem_u32(smem);
    const int dir = blockIdx.z;
    const __half* Ah = &g_xth[dir][0];
    const __half* Al = &g_xtl[dir][0];
    const __half* Bh = &g_wx[dir][0];
    float* C   = &g_dbl[dir][0];
    __half* dH = &g_dt_h[dir][0];
    __half* dL = &g_dt_l[dir][0];

    const int bm = blockIdx.y * 64;
    const int tid  = threadIdx.x;
    const int wid  = tid >> 5;
    const int lane = tid & 31;

    const int prow = tid >> 3;
    const int pkc  = tid & 7;
    auto issue = [&](int c) {
        const uint32_t sb = su + (uint32_t)(c & 1) * XP_STAGE;
        const int k0 = c * 64;
#pragma unroll
        for (int i = 0; i < 2; ++i) {
            const int row = prow + i * 32;
            const uint32_t off = sw128((uint32_t)(row * 128 + pkc * 16));
            const size_t ga = (size_t)(bm + row) * CDI + k0 + pkc * 8;
            cp16(sb + off,        Ah + ga);
            cp16(sb + 8192 + off, Al + ga);
        }
#pragma unroll
        for (int i = 0; i < 4; ++i) {
            const int row = prow + i * 32;
            const uint32_t off = sw128((uint32_t)(row * 128 + pkc * 16));
            const size_t gb = (size_t)row * CDI + k0 + pkc * 8;
            cp16(sb + 16384 + off, Bh + gb);
        }
        asm volatile("cp.async.commit_group;" ::: "memory");
    };

    const int m0 = (wid & 1) * 32;
    const int n0 = (wid >> 1) * 32;
    const int g    = lane >> 3;
    const int lr   = lane & 7;
    const int lrow = (g & 1) * 8 + lr;
    const int lkb  = (g >> 1) * 16;

    float acc[2][4][4] = {};

    issue(0); issue(1);

    const int NC = CDI / 64;
    for (int c = 0; c < NC; ++c) {
        asm volatile("cp.async.wait_group 1;" ::: "memory");
        __syncthreads();
        const uint32_t sb = su + (uint32_t)(c & 1) * XP_STAGE;
#pragma unroll
        for (int kk = 0; kk < 4; ++kk) {
            uint32_t ah[2][4], al[2][4];
#pragma unroll
            for (int mt = 0; mt < 2; ++mt) {
                uint32_t off = sw128((uint32_t)((m0 + mt*16 + lrow) * 128 + kk*32 + lkb));
                ldsm4(sb + off,        ah[mt]);
                ldsm4(sb + 8192 + off, al[mt]);
            }
#pragma unroll
            for (int np = 0; np < 2; ++np) {
                uint32_t boff = sw128((uint32_t)((n0 + np*16 + lrow) * 128 + kk*32 + lkb));
                uint32_t bh[4];
                ldsm4(sb + 16384 + boff, bh);
#pragma unroll
                for (int mt = 0; mt < 2; ++mt) {
                    mma_f16(acc[mt][2*np],   ah[mt], bh[0], bh[2]);
                    mma_f16(acc[mt][2*np],   al[mt], bh[0], bh[2]);
                    mma_f16(acc[mt][2*np+1], ah[mt], bh[1], bh[3]);
                    mma_f16(acc[mt][2*np+1], al[mt], bh[1], bh[3]);
                }
            }
        }
        __syncthreads();
        if (c + 2 < NC) issue(c + 2);
        else asm volatile("cp.async.commit_group;" ::: "memory");
    }

    const int er = lane >> 2;
    const int ec = (lane & 3) * 2;
#pragma unroll
    for (int mt = 0; mt < 2; ++mt) {
#pragma unroll
        for (int nt = 0; nt < 4; ++nt) {
            const int row0 = bm + m0 + mt*16 + er;
            const int col  = n0 + nt*8 + ec;
#pragma unroll
            for (int rr = 0; rr < 2; ++rr) {
                const int row = row0 + rr*8;
#pragma unroll
                for (int e = 0; e < 2; ++e) {
                    const int cc = col + e;
                    const float v = acc[mt][nt][rr*2+e];
                    if (cc < CRP) {
                        float dv = (cc < CR) ? v : 0.f;
                        __half hb = __float2half_rn(dv);
                        dH[(size_t)row * CRP + cc] = hb;
                        dL[(size_t)row * CRP + cc] =
                            __float2half_rn(dv - __half2float(hb));
                    }
                    if (cc >= CR && cc < CPROJ)
                        C[(size_t)row * CPROJ + cc] = v;
                }
            }
        }
    }
}

// ---------------------------------------------------------------------------
// dtproj tensor GEMM: delta[row,d] = softplus(sum_r dt[row,r]*W[d,r] + bias[d])
// ---------------------------------------------------------------------------
__device__ __forceinline__ float softplus_f(float v) {
    return (v > 20.f) ? v : log1pf(__expf(v));
}

__global__ void __launch_bounds__(256) dtgemm_kernel(
    const float* __restrict__ bias_f, const float* __restrict__ bias_b)
{
    extern __shared__ __align__(1024) char smem[];
    const uint32_t su = smem_u32(smem);
    const int dir = blockIdx.z;
    const __half* Ah = &g_dt_h[dir][0];
    const __half* Al = &g_dt_l[dir][0];
    const __half* Bh = &g_wdt_h[dir][0];
    const __half* Bl = &g_wdt_l[dir][0];
    const float* bias = dir ? bias_b : bias_f;
    float* C = &g_delta[dir][0];

    const int bm = blockIdx.y * 128;
    const int bn = blockIdx.x * 128;
    const int tid  = threadIdx.x;
    const int wid  = tid >> 5;
    const int lane = tid & 31;

    const int prow = tid >> 3;
    const int pkc  = tid & 7;
#pragma unroll
    for (int i = 0; i < 4; ++i) {
        const int row = prow + i * 32;
        const uint32_t off = sw128((uint32_t)(row * 128 + pkc * 16));
        const size_t ga = (size_t)(bm + row) * CRP + pkc * 8;
        const size_t gb = (size_t)(bn + row) * CRP + pkc * 8;
        cp16(su + off,         Ah + ga);
        cp16(su + 16384 + off, Al + ga);
        cp16(su + 32768 + off, Bh + gb);
        cp16(su + 49152 + off, Bl + gb);
    }
    asm volatile("cp.async.commit_group;" ::: "memory");
    asm volatile("cp.async.wait_group 0;" ::: "memory");
    __syncthreads();

    const int m0 = (wid & 3) * 32;
    const int n0 = (wid >> 2) * 64;
    const int g    = lane >> 3;
    const int lr   = lane & 7;
    const int lrow = (g & 1) * 8 + lr;
    const int lkb  = (g >> 1) * 16;

    float acc[2][8][4] = {};
#pragma unroll
    for (int kk = 0; kk < 4; ++kk) {
        uint32_t ah[2][4], al[2][4];
#pragma unroll
        for (int mt = 0; mt < 2; ++mt) {
            uint32_t off = sw128((uint32_t)((m0 + mt*16 + lrow) * 128 + kk*32 + lkb));
            ldsm4(su + off,         ah[mt]);
            ldsm4(su + 16384 + off, al[mt]);
        }
#pragma unroll
        for (int np = 0; np < 4; ++np) {
            uint32_t boff = sw128((uint32_t)((n0 + np*16 + lrow) * 128 + kk*32 + lkb));
            uint32_t bh[4], bl[4];
            ldsm4(su + 32768 + boff, bh);
            ldsm4(su + 49152 + boff, bl);
#pragma unroll
            for (int mt = 0; mt < 2; ++mt) {
                mma_f16(acc[mt][2*np],   ah[mt], bh[0], bh[2]);
                mma_f16(acc[mt][2*np],   al[mt], bh[0], bh[2]);
                mma_f16(acc[mt][2*np],   ah[mt], bl[0], bl[2]);
                mma_f16(acc[mt][2*np+1], ah[mt], bh[1], bh[3]);
                mma_f16(acc[mt][2*np+1], al[mt], bh[1], bh[3]);
                mma_f16(acc[mt][2*np+1], ah[mt], bl[1], bl[3]);
            }
        }
    }

    const int er = lane >> 2;
    const int ec = (lane & 3) * 2;
#pragma unroll
    for (int mt = 0; mt < 2; ++mt) {
#pragma unroll
        for (int nt = 0; nt < 8; ++nt) {
            const int row = bm + m0 + mt*16 + er;
            const int col = bn + n0 + nt*8 + ec;
            const float b0 = bias[col], b1 = bias[col+1];
            float2 lo = { softplus_f(acc[mt][nt][0] + b0),
                          softplus_f(acc[mt][nt][1] + b1) };
            float2 hi = { softplus_f(acc[mt][nt][2] + b0),
                          softplus_f(acc[mt][nt][3] + b1) };
            *(float2*)(C + (size_t)row * CDI + col)       = lo;
            *(float2*)(C + (size_t)(row + 8) * CDI + col) = hi;
        }
    }
}

// ---------------------------------------------------------------------------
// fp32 -> fp16 hi/lo splitter and single-fp16 converter (grid-stride, float4)
// ---------------------------------------------------------------------------
__global__ void split2_kernel(const float* __restrict__ s,
                              __half* __restrict__ h, __half* __restrict__ l, int n4)
{
    for (int i = blockIdx.x * blockDim.x + threadIdx.x; i < n4;
         i += gridDim.x * blockDim.x) {
        float4 v = ((const float4*)s)[i];
        __half hx = __float2half_rn(v.x), hy = __float2half_rn(v.y);
        __half hz = __float2half_rn(v.z), hw = __float2half_rn(v.w);
        __half lx = __float2half_rn(v.x - __half2float(hx));
        __half ly = __float2half_rn(v.y - __half2float(hy));
        __half lz = __float2half_rn(v.z - __half2float(hz));
        __half lw = __float2half_rn(v.w - __half2float(hw));
        __half2 h01 = __halves2half2(hx, hy), h23 = __halves2half2(hz, hw);
        __half2 l01 = __halves2half2(lx, ly), l23 = __halves2half2(lz, lw);
        ((uint2*)h)[i] = make_uint2(*(uint32_t*)&h01, *(uint32_t*)&h23);
        ((uint2*)l)[i] = make_uint2(*(uint32_t*)&l01, *(uint32_t*)&l23);
    }
}

__global__ void tof16_kernel(const float* __restrict__ s, __half* __restrict__ h, int n4)
{
    for (int i = blockIdx.x * blockDim.x + threadIdx.x; i < n4;
         i += gridDim.x * blockDim.x) {
        float4 v = ((const float4*)s)[i];
        __half2 h01 = __halves2half2(__float2half_rn(v.x), __float2half_rn(v.y));
        __half2 h23 = __halves2half2(__float2half_rn(v.z), __float2half_rn(v.w));
        ((uint2*)h)[i] = make_uint2(*(uint32_t*)&h01, *(uint32_t*)&h23);
    }
}

// xproj weights: pad 80 -> 128 rows (zeros), single fp16, both dirs.
__global__ void padw_kernel(const float* __restrict__ wf, const float* __restrict__ wb)
{
    const int total4 = 2 * 128 * CDI / 4;
    for (int i = blockIdx.x * blockDim.x + threadIdx.x; i < total4;
         i += gridDim.x * blockDim.x) {
        int e = i * 4;
        int dir = e / (128 * CDI);
        int rem = e - dir * 128 * CDI;
        int row = rem / CDI;
        int k   = rem - row * CDI;
        float4 v = {0.f, 0.f, 0.f, 0.f};
        const float* W = dir ? wb : wf;
        if (row < CPROJ) v = *(const float4*)(W + (size_t)row * CDI + k);
        __half2 h01 = __halves2half2(__float2half_rn(v.x), __float2half_rn(v.y));
        __half2 h23 = __halves2half2(__float2half_rn(v.z), __float2half_rn(v.w));
        ((uint2*)&g_wx[0][0])[i] = make_uint2(*(uint32_t*)&h01, *(uint32_t*)&h23);
    }
}

// dtproj weights: pad K 48 -> 64 (zeros), split to fp16 hi/lo, both dirs.
__global__ void padwd_kernel(const float* __restrict__ wf, const float* __restrict__ wb)
{
    const int total4 = 2 * CDI * CRP / 4;
    for (int i = blockIdx.x * blockDim.x + threadIdx.x; i < total4;
         i += gridDim.x * blockDim.x) {
        int e = i * 4;
        int dir = e / (CDI * CRP);
        int rem = e - dir * CDI * CRP;
        int row = rem / CRP;
        int k   = rem - row * CRP;
        float4 v = {0.f, 0.f, 0.f, 0.f};
        const float* W = dir ? wb : wf;
        if (k < CR) v = *(const float4*)(W + (size_t)row * CR + k);
        __half hx = __float2half_rn(v.x), hy = __float2half_rn(v.y);
        __half hz = __float2half_rn(v.z), hw = __float2half_rn(v.w);
        __half lx = __float2half_rn(v.x - __half2float(hx));
        __half ly = __float2half_rn(v.y - __half2float(hy));
        __half lz = __float2half_rn(v.z - __half2float(hz));
        __half lw = __float2half_rn(v.w - __half2float(hw));
        __half2 h01 = __halves2half2(hx, hy), h23 = __halves2half2(hz, hw);
        __half2 l01 = __halves2half2(lx, ly), l23 = __halves2half2(lz, lw);
        ((uint2*)&g_wdt_h[0][0])[i] = make_uint2(*(uint32_t*)&h01, *(uint32_t*)&h23);
        ((uint2*)&g_wdt_l[0][0])[i] = make_uint2(*(uint32_t*)&l01, *(uint32_t*)&l23);
    }
}

// ---------------------------------------------------------------------------
// Depthwise causal conv (K=4) + bias + SiLU, transpose to (b,t,d).
// MERGED DIRECTIONS: one block loads x[t0-3 .. t0+130] once, emits both dirs.
// ---------------------------------------------------------------------------
__global__ void __launch_bounds__(256) conv_silu_kernel(
    const float* __restrict__ cw_f, const float* __restrict__ cb_f,
    const float* __restrict__ cw_b, const float* __restrict__ cb_b)
{
    const int t0 = blockIdx.x * 128;
    const int d0 = blockIdx.y * 32;
    const int b  = blockIdx.z;

    __shared__ float xs[32][135];

    const float* xbase = g_xz + ((size_t)b * (2*CDI) + d0) * CL;
    const int base = t0 - 3;

    const int lane = threadIdx.x & 31;
    const int wy   = threadIdx.x >> 5;
    for (int d = wy; d < 32; d += 8) {
        const float* row = xbase + (size_t)d * CL;
        for (int i = lane; i < 134; i += 32) {
            int u = base + i;
            xs[d][i] = (u >= 0 && u < CL) ? row[u] : 0.f;
        }
    }
    __syncthreads();

    const int d  = threadIdx.x & 31;
    const int sg = threadIdx.x >> 5;
    const float wf0 = cw_f[(d0+d)*CK + 0];
    const float wf1 = cw_f[(d0+d)*CK + 1];
    const float wf2 = cw_f[(d0+d)*CK + 2];
    const float wf3 = cw_f[(d0+d)*CK + 3];
    const float bf  = cb_f[d0+d];
    const float wb0 = cw_b[(d0+d)*CK + 0];
    const float wb1 = cw_b[(d0+d)*CK + 1];
    const float wb2 = cw_b[(d0+d)*CK + 2];
    const float wb3 = cw_b[(d0+d)*CK + 3];
    const float bb  = cb_b[d0+d];

    __half* ohf = g_xth[0] + (size_t)b * CL * CDI;
    __half* olf = g_xtl[0] + (size_t)b * CL * CDI;
    __half* ohb = g_xth[1] + (size_t)b * CL * CDI;
    __half* olb = g_xtl[1] + (size_t)b * CL * CDI;
    const int tb0 = CL - 128 - t0;
#pragma unroll
    for (int q = 0; q < 16; ++q) {
        int s = sg + 8*q;
        {
            float v = wf0*xs[d][s] + wf1*xs[d][s+1] + wf2*xs[d][s+2] + wf3*xs[d][s+3] + bf;
            float sv = v / (1.f + __expf(-v));
            size_t idx = (size_t)(t0 + s) * CDI + d0 + d;
            __half hb = __float2half_rn(sv);
            ohf[idx] = hb;
            olf[idx] = __float2half_rn(sv - __half2float(hb));
        }
        {
            float v = wb3*xs[d][130-s] + wb2*xs[d][131-s] + wb1*xs[d][132-s]
                    + wb0*xs[d][133-s] + bb;
            float sv = v / (1.f + __expf(-v));
            size_t idx = (size_t)(tb0 + s) * CDI + d0 + d;
            __half hb = __float2half_rn(sv);
            ohb[idx] = hb;
            olb[idx] = __float2half_rn(sv - __half2float(hb));
        }
    }
}

// ---------------------------------------------------------------------------
// Selective scan, 2-states-per-lane layout.
// Warp = 4 channels x 8 lanes; lane handles states n and n+8 of one channel.
// Block = 128 threads = 4 warps = 16 channels. Staging arrays (content only
// differs from round-5 shape): sd = dt, sx = dt*x, sB = B, sC = C, sxD = x*D.
// Inner step: 6 scalar LDS + 2x(mul+EX2) + 2x(mul+fma) + (mul+fma) +
// 3x(shfl+add) + predicated (LDS+add+STG).
// ---------------------------------------------------------------------------
__global__ void __launch_bounds__(128) scan_kernel(
    const float* __restrict__ Alog_f, const float* __restrict__ Dv_f,
    const float* __restrict__ Alog_b, const float* __restrict__ Dv_b)
{
    const int dir = blockIdx.z;
    const int b   = blockIdx.y;
    const int d0  = blockIdx.x * 16;

    const float* Alog = dir ? Alog_b : Alog_f;
    const float* Dvec = dir ? Dv_b   : Dv_f;
    const float* delta = g_delta[dir] + (size_t)b * CL * CDI;
    const __half* xth  = g_xth[dir]   + (size_t)b * CL * CDI;
    const __half* xtl  = g_xtl[dir]   + (size_t)b * CL * CDI;
    const float* dbl   = g_dbl[dir]   + (size_t)b * CL * CPROJ;
    float* yout        = g_y[dir]     + (size_t)b * CL * CDI;

    __shared__ __align__(16) float sd[64][16];   // dt
    __shared__ __align__(16) float sx[64][16];   // dt*x
    __shared__ __align__(16) float sB[64][16];
    __shared__ __align__(16) float sC[64][16];
    __shared__ __align__(16) float sxD[64][16];  // x*D

    const int tid  = threadIdx.x;
    const int lane = tid & 31;
    const int wid  = tid >> 5;
    const int ch   = wid*4 + (lane >> 3);   // 0..15
    const int n    = lane & 7;              // states n and n+8
    const int d    = d0 + ch;

    constexpr float LOG2E = 1.4426950408889634f;
    const float Aval0 = -__expf(Alog[d*CN + n])     * LOG2E;
    const float Aval1 = -__expf(Alog[d*CN + n + 8]) * LOG2E;
    float h0 = 0.f, h1 = 0.f;

    // staging: li = row 0..63, lj = col 0 or 8 (8 cols per thread)
    const int li = tid >> 1;
    const int lj = (tid & 1) * 8;

    float rDv[8];
#pragma unroll
    for (int j = 0; j < 8; ++j) rDv[j] = Dvec[d0 + lj + j];

    float rd[8], rx[8], rB[8], rC[8];
    auto LD = [&](int t0) {
        float4 d0v = *(const float4*)(delta + (size_t)(t0+li)*CDI + d0 + lj);
        float4 d1v = *(const float4*)(delta + (size_t)(t0+li)*CDI + d0 + lj + 4);
        rd[0]=d0v.x; rd[1]=d0v.y; rd[2]=d0v.z; rd[3]=d0v.w;
        rd[4]=d1v.x; rd[5]=d1v.y; rd[6]=d1v.z; rd[7]=d1v.w;
        uint4 xh = *(const uint4*)(xth + (size_t)(t0+li)*CDI + d0 + lj);
        uint4 xl = *(const uint4*)(xtl + (size_t)(t0+li)*CDI + d0 + lj);
        const uint32_t* xhp = &xh.x;
        const uint32_t* xlp = &xl.x;
#pragma unroll
        for (int q = 0; q < 4; ++q) {
            float2 fh = __half22float2(*(const __half2*)&xhp[q]);
            float2 fl = __half22float2(*(const __half2*)&xlp[q]);
            rx[2*q+0] = fh.x + fl.x;
            rx[2*q+1] = fh.y + fl.y;
        }
        float4 b0v = *(const float4*)(dbl + (size_t)(t0+li)*CPROJ + CR + lj);
        float4 b1v = *(const float4*)(dbl + (size_t)(t0+li)*CPROJ + CR + lj + 4);
        rB[0]=b0v.x; rB[1]=b0v.y; rB[2]=b0v.z; rB[3]=b0v.w;
        rB[4]=b1v.x; rB[5]=b1v.y; rB[6]=b1v.z; rB[7]=b1v.w;
        float4 c0v = *(const float4*)(dbl + (size_t)(t0+li)*CPROJ + CR + CN + lj);
        float4 c1v = *(const float4*)(dbl + (size_t)(t0+li)*CPROJ + CR + CN + lj + 4);
        rC[0]=c0v.x; rC[1]=c0v.y; rC[2]=c0v.z; rC[3]=c0v.w;
        rC[4]=c1v.x; rC[5]=c1v.y; rC[6]=c1v.z; rC[7]=c1v.w;
    };
    LD(0);

    const int NCH = CL / 64;
    for (int c = 0; c < NCH; ++c) {
        __syncthreads();
        {
            float4 v;
            v = make_float4(rd[0], rd[1], rd[2], rd[3]);            *(float4*)&sd[li][lj]   = v;
            v = make_float4(rd[4], rd[5], rd[6], rd[7]);            *(float4*)&sd[li][lj+4] = v;
            v = make_float4(rd[0]*rx[0], rd[1]*rx[1], rd[2]*rx[2], rd[3]*rx[3]); *(float4*)&sx[li][lj]   = v;
            v = make_float4(rd[4]*rx[4], rd[5]*rx[5], rd[6]*rx[6], rd[7]*rx[7]); *(float4*)&sx[li][lj+4] = v;
            v = make_float4(rB[0], rB[1], rB[2], rB[3]);            *(float4*)&sB[li][lj]   = v;
            v = make_float4(rB[4], rB[5], rB[6], rB[7]);            *(float4*)&sB[li][lj+4] = v;
            v = make_float4(rC[0], rC[1], rC[2], rC[3]);            *(float4*)&sC[li][lj]   = v;
            v = make_float4(rC[4], rC[5], rC[6], rC[7]);            *(float4*)&sC[li][lj+4] = v;
            v = make_float4(rx[0]*rDv[0], rx[1]*rDv[1], rx[2]*rDv[2], rx[3]*rDv[3]); *(float4*)&sxD[li][lj]   = v;
            v = make_float4(rx[4]*rDv[4], rx[5]*rDv[5], rx[6]*rDv[6], rx[7]*rDv[7]); *(float4*)&sxD[li][lj+4] = v;
        }
        __syncthreads();
        if (c + 1 < NCH) LD((c+1) * 64);

        const int tbase = c * 64;
#pragma unroll 8
        for (int s = 0; s < 64; ++s) {
            float dt  = sd[s][ch];
            float dtx = sx[s][ch];
            float B0 = sB[s][n],     C0 = sC[s][n];
            float B1 = sB[s][n + 8], C1 = sC[s][n + 8];
            float a0 = ex2f(dt * Aval0);
            float a1 = ex2f(dt * Aval1);
            h0 = fmaf(a0, h0, dtx * B0);
            h1 = fmaf(a1, h1, dtx * B1);
            float p = fmaf(h1, C1, h0 * C0);
            p += __shfl_xor_sync(0xffffffffu, p, 4);
            p += __shfl_xor_sync(0xffffffffu, p, 2);
            p += __shfl_xor_sync(0xffffffffu, p, 1);
            if (n == 0)
                yout[(size_t)(tbase + s)*CDI + d] = p + sxD[s][ch];
        }
    }
}

// ---------------------------------------------------------------------------
// Gate + direction merge -> fp16 hi/lo comb (out_proj split operand)
// ---------------------------------------------------------------------------
__global__ void __launch_bounds__(256) combine_kernel()
{
    const int l0 = blockIdx.x * 32;
    const int d0 = blockIdx.y * 32;
    const int b  = blockIdx.z;

    __shared__ float zs[32][33];
    const int lane = threadIdx.x & 31;
    const int wy   = threadIdx.x >> 5;

    const float* zbase = g_xz + ((size_t)b * (2*CDI) + CDI + d0) * CL;
    for (int dd = wy; dd < 32; dd += 8)
        zs[dd][lane] = zbase[(size_t)dd * CL + l0 + lane];
    __syncthreads();

#pragma unroll
    for (int q = 0; q < 4; ++q) {
        int lr = wy + 8*q;
        int l = l0 + lr;
        size_t idx  = ((size_t)b*CL + l)*CDI + d0 + lane;
        size_t idxr = ((size_t)b*CL + (CL-1-l))*CDI + d0 + lane;
        float yf = g_y[0][idx];
        float yb = g_y[1][idxr];
        float zv = zs[lane][lr];
        float s = zv / (1.f + __expf(-zv));
        float cv = (yf + yb) * s;
        __half hb = __float2half_rn(cv);
        g_cmb_h[idx] = hb;
        g_cmb_l[idx] = __float2half_rn(cv - __half2float(hb));
    }
}

// ---------------------------------------------------------------------------
// Launcher
// ---------------------------------------------------------------------------
extern "C" void kernel_launch(void* const* d_in, const int* in_sizes, int n_in,
                              void* d_out, int out_size)
{
    (void)in_sizes; (void)n_in; (void)out_size;

    const float* hidden  = (const float*)d_in[0];
    const float* in_w    = (const float*)d_in[1];
    const float* conv_w  = (const float*)d_in[2];
    const float* conv_b  = (const float*)d_in[3];
    const float* xproj_w = (const float*)d_in[4];
    const float* dtw     = (const float*)d_in[5];
    const float* dtb     = (const float*)d_in[6];
    const float* A_log   = (const float*)d_in[7];
    const float* Dv      = (const float*)d_in[8];
    const float* conv_w2 = (const float*)d_in[9];
    const float* conv_b2 = (const float*)d_in[10];
    const float* xproj_w2= (const float*)d_in[11];
    const float* dtw2    = (const float*)d_in[12];
    const float* dtb2    = (const float*)d_in[13];
    const float* A_log2  = (const float*)d_in[14];
    const float* Dv2     = (const float*)d_in[15];
    const float* out_w   = (const float*)d_in[16];

    void *p_xz;
    void *p_hid_h, *p_hid_l, *p_w1, *p_w2, *p_cmb_h, *p_cmb_l;
    cudaGetSymbolAddress(&p_xz, g_xz);
    cudaGetSymbolAddress(&p_hid_h, g_hid_h);
    cudaGetSymbolAddress(&p_hid_l, g_hid_l);
    cudaGetSymbolAddress(&p_w1, g_w1);
    cudaGetSymbolAddress(&p_w2, g_w2);
    cudaGetSymbolAddress(&p_cmb_h, g_cmb_h);
    cudaGetSymbolAddress(&p_cmb_l, g_cmb_l);

    cudaFuncSetAttribute(gemm_f16_kernel<0>,
                         cudaFuncAttributeMaxDynamicSharedMemorySize, GF_SMEM);
    cudaFuncSetAttribute(gemm_f16_kernel<1>,
                         cudaFuncAttributeMaxDynamicSharedMemorySize, GF_SMEM);
    cudaFuncSetAttribute(xproj_kernel,
                         cudaFuncAttributeMaxDynamicSharedMemorySize, XP_SMEM);
    cudaFuncSetAttribute(dtgemm_kernel,
                         cudaFuncAttributeMaxDynamicSharedMemorySize, 65536);

    // 0) operand packing
    split2_kernel<<<1024, 256>>>(hidden, (__half*)p_hid_h, (__half*)p_hid_l, CB*CL*CDM/4);
    tof16_kernel<<<512, 256>>>(in_w, (__half*)p_w1, 2*CDI*CDM/4);
    tof16_kernel<<<512, 256>>>(out_w, (__half*)p_w2, CDM*CDI/4);
    padw_kernel<<<512, 256>>>(xproj_w, xproj_w2);
    padwd_kernel<<<192, 256>>>(dtw, dtw2);

    // 1) in_proj: A = w1 (single), B = hidden (split).  M=3072, N=4096, K=768
    gemm_f16_kernel<0><<<dim3(CL/128, (2*CDI)/128, CB), 256, GF_SMEM>>>(
        (const __half*)p_w1, (const __half*)p_hid_l, (const __half*)p_hid_h,
        (float*)p_xz, CL, CDM,
        0, (long long)CL * CDM, (long long)(2*CDI) * CL, CDM / 64);

    // 2) conv + SiLU + transpose (both dirs per block) -> fp16 hi/lo xt
    conv_silu_kernel<<<dim3(CL/128, CDI/32, CB), 256>>>(
        conv_w, conv_b, conv_w2, conv_b2);

    // 3) xproj, M=64 tiles (256 CTAs): dt fp16 hi/lo + fp32 B|C
    xproj_kernel<<<dim3(1, (CB*CL)/64, 2), 256, XP_SMEM>>>();

    // 4) dtproj as tensor GEMM + softplus -> delta
    dtgemm_kernel<<<dim3(CDI/128, (CB*CL)/128, 2), 256, 65536>>>(dtb, dtb2);

    // 5) selective scan (2-states-per-lane, 128-thread CTAs)
    scan_kernel<<<dim3(CDI/16, CB, 2), 128>>>(A_log, Dv, A_log2, Dv2);

    // 6) gate + direction merge -> fp16 hi/lo comb
    combine_kernel<<<dim3(CL/32, CDI/32, CB), 256>>>();

    // 7) out_proj: A = comb (split), B = w2 (single).  M=8192, N=768, K=1536
    gemm_f16_kernel<1><<<dim3(CDM/128, (CB*CL)/128, 1), 256, GF_SMEM>>>(
        (const __half*)p_cmb_h, (const __half*)p_cmb_l, (const __half*)p_w2,
        (float*)d_out, CDM, CDI,
        0, 0, 0, CDI / 64);
}

// round 12
// speedup vs baseline: 1.2828x; 1.0755x over previous
#include <cuda_runtime.h>
#include <cuda_fp16.h>
#include <cstdint>

// Problem constants
constexpr int CB  = 2;     // batch
constexpr int CL  = 4096;  // seq len
constexpr int CDM = 768;   // d_model
constexpr int CDI = 1536;  // d_inner
constexpr int CN  = 16;    // state dim
constexpr int CR  = 48;    // dt rank
constexpr int CK  = 4;     // conv width
constexpr int CPROJ = CR + 2*CN; // 80
constexpr int CRP = 64;    // dt rank padded for MMA K

// ---------------------------------------------------------------------------
// Scratch (device globals; no runtime allocation allowed)
// ---------------------------------------------------------------------------
__device__ float g_xz[CB * 2 * CDI * CL];        // (b, e, l)
__device__ float g_dbl[2][CB * CL * CPROJ];      // per dir, (b*L, 80): only B|C cols used
__device__ float g_delta[2][CB * CL * CDI];      // per dir, post-softplus
__device__ float g_y[2][CB * CL * CDI];          // per dir, scan out (+D*x)

// fp16 operands for tensor GEMMs
__device__ __half g_hid_h[CB*CL*CDM], g_hid_l[CB*CL*CDM];  // hidden hi/lo (split side)
__device__ __half g_w1[2*CDI*CDM];                          // in_proj W (single)
__device__ __half g_w2[CDM*CDI];                            // out_proj W (single)
__device__ __half g_wx[2][128*CDI];                         // xproj W padded 80->128 (single)
__device__ __half g_xth[2][CB*CL*CDI], g_xtl[2][CB*CL*CDI]; // conv out hi/lo (split side)
__device__ __half g_cmb_h[CB*CL*CDI];                       // gated sum, single fp16
__device__ __half g_dt_h[2][CB*CL*CRP], g_dt_l[2][CB*CL*CRP]; // dt rows padded 48->64, hi/lo
__device__ __half g_wdt_h[2][CDI*CRP],  g_wdt_l[2][CDI*CRP];  // dtproj W padded, hi/lo

// ---------------------------------------------------------------------------
// PTX helpers
// ---------------------------------------------------------------------------
__device__ __forceinline__ uint32_t smem_u32(const void* p) {
    uint32_t a;
    asm("{ .reg .u64 t; cvta.to.shared.u64 t, %1; cvt.u32.u64 %0, t; }" : "=r"(a) : "l"(p));
    return a;
}
__device__ __forceinline__ uint32_t sw128(uint32_t b) { return b ^ ((b >> 3) & 0x70); }

__device__ __forceinline__ void ldsm4(uint32_t addr, uint32_t r[4]) {
    asm volatile("ldmatrix.sync.aligned.m8n8.x4.shared.b16 {%0,%1,%2,%3}, [%4];"
        : "=r"(r[0]), "=r"(r[1]), "=r"(r[2]), "=r"(r[3]) : "r"(addr));
}
__device__ __forceinline__ void mma_f16(float* d, const uint32_t* a, uint32_t b0, uint32_t b1) {
    asm volatile("mma.sync.aligned.m16n8k16.row.col.f32.f16.f16.f32 "
        "{%0,%1,%2,%3}, {%4,%5,%6,%7}, {%8,%9}, {%0,%1,%2,%3};"
        : "+f"(d[0]), "+f"(d[1]), "+f"(d[2]), "+f"(d[3])
        : "r"(a[0]), "r"(a[1]), "r"(a[2]), "r"(a[3]), "r"(b0), "r"(b1));
}
__device__ __forceinline__ void cp16(uint32_t s, const void* g) {
    asm volatile("cp.async.ca.shared.global [%0], [%1], 16;" :: "r"(s), "l"(g));
}
__device__ __forceinline__ float ex2f(float x) {
    float r;
    asm("ex2.approx.f32 %0, %1;" : "=f"(r) : "f"(x));
    return r;
}

// ---------------------------------------------------------------------------
// fp16 tensor GEMM (M=128 tile):  C[m,n] = sum_k A[m,k]*B[n,k]
// SPLIT_A==1: A split hi/lo (2 terms). SPLIT_A==0: B split (2 terms).
// SPLIT_A==2: no split (1 term; Xl ignored, its cp.async skipped).
// CTA tile 128x128, BK=64, 2-stage cp.async ring, 96KB smem -> 2 CTA/SM.
// ---------------------------------------------------------------------------
constexpr int GF_STAGE = 49152;
constexpr int GF_SMEM  = 2 * GF_STAGE;   // 98304 B

template <int SPLIT_A>
__global__ void __launch_bounds__(256, 2) gemm_f16_kernel(
    const __half* __restrict__ Ah, const __half* __restrict__ Xl,  // Xl = Al or Bl
    const __half* __restrict__ Bh,
    float* __restrict__ C, int Nout, int Kd,
    long long strideA, long long strideB, long long strideC, int NC)
{
    extern __shared__ __align__(1024) char smem[];
    const uint32_t su = smem_u32(smem);
    Ah += (size_t)blockIdx.z * strideA;
    Bh += (size_t)blockIdx.z * strideB;
    Xl += (size_t)blockIdx.z * (SPLIT_A == 1 ? strideA : strideB);
    C  += (size_t)blockIdx.z * strideC;
    const int bm = blockIdx.y * 128;
    const int bn = blockIdx.x * 128;
    const int tid  = threadIdx.x;
    const int wid  = tid >> 5;
    const int lane = tid & 31;

    const int prow = tid >> 3;
    const int pkc  = tid & 7;
    auto issue = [&](int c) {
        const uint32_t sb = su + (uint32_t)(c & 1) * GF_STAGE;
        const int k0 = c * 64;
#pragma unroll
        for (int i = 0; i < 4; ++i) {
            const int row = prow + i * 32;
            const uint32_t off = sw128((uint32_t)(row * 128 + pkc * 16));
            const size_t ga = (size_t)(bm + row) * Kd + k0 + pkc * 8;
            const size_t gb = (size_t)(bn + row) * Kd + k0 + pkc * 8;
            cp16(sb + off,         Ah + ga);
            if (SPLIT_A != 2)
                cp16(sb + 16384 + off, Xl + (SPLIT_A == 1 ? ga : gb));
            cp16(sb + 32768 + off, Bh + gb);
        }
        asm volatile("cp.async.commit_group;" ::: "memory");
    };

    const int m0 = (wid & 3) * 32;
    const int n0 = (wid >> 2) * 64;
    const int g    = lane >> 3;
    const int lr   = lane & 7;
    const int lrow = (g & 1) * 8 + lr;
    const int lkb  = (g >> 1) * 16;

    float acc[2][8][4] = {};

    issue(0); issue(1);

    for (int c = 0; c < NC; ++c) {
        asm volatile("cp.async.wait_group 1;" ::: "memory");
        __syncthreads();
        const uint32_t sb = su + (uint32_t)(c & 1) * GF_STAGE;
#pragma unroll
        for (int kk = 0; kk < 4; ++kk) {
            uint32_t ah[2][4], al[2][4];
#pragma unroll
            for (int mt = 0; mt < 2; ++mt) {
                uint32_t off = sw128((uint32_t)((m0 + mt*16 + lrow) * 128 + kk*32 + lkb));
                ldsm4(sb + off, ah[mt]);
                if (SPLIT_A == 1) ldsm4(sb + 16384 + off, al[mt]);
            }
#pragma unroll
            for (int np = 0; np < 4; ++np) {
                uint32_t boff = sw128((uint32_t)((n0 + np*16 + lrow) * 128 + kk*32 + lkb));
                uint32_t bh[4], bl[4];
                ldsm4(sb + 32768 + boff, bh);
                if (SPLIT_A == 0) ldsm4(sb + 16384 + boff, bl);
#pragma unroll
                for (int mt = 0; mt < 2; ++mt) {
                    if (SPLIT_A == 1) {
                        mma_f16(acc[mt][2*np],   ah[mt], bh[0], bh[2]);
                        mma_f16(acc[mt][2*np],   al[mt], bh[0], bh[2]);
                        mma_f16(acc[mt][2*np+1], ah[mt], bh[1], bh[3]);
                        mma_f16(acc[mt][2*np+1], al[mt], bh[1], bh[3]);
                    } else if (SPLIT_A == 0) {
                        mma_f16(acc[mt][2*np],   ah[mt], bh[0], bh[2]);
                        mma_f16(acc[mt][2*np],   ah[mt], bl[0], bl[2]);
                        mma_f16(acc[mt][2*np+1], ah[mt], bh[1], bh[3]);
                        mma_f16(acc[mt][2*np+1], ah[mt], bl[1], bl[3]);
                    } else {
                        mma_f16(acc[mt][2*np],   ah[mt], bh[0], bh[2]);
                        mma_f16(acc[mt][2*np+1], ah[mt], bh[1], bh[3]);
                    }
                }
            }
        }
        __syncthreads();
        if (c + 2 < NC) issue(c + 2);
        else asm volatile("cp.async.commit_group;" ::: "memory");
    }

    const int er = lane >> 2;
    const int ec = (lane & 3) * 2;
#pragma unroll
    for (int mt = 0; mt < 2; ++mt) {
#pragma unroll
        for (int nt = 0; nt < 8; ++nt) {
            const int row = bm + m0 + mt*16 + er;
            const int col = bn + n0 + nt*8 + ec;
            if (col < Nout) {
                float2 lo = { acc[mt][nt][0], acc[mt][nt][1] };
                float2 hi = { acc[mt][nt][2], acc[mt][nt][3] };
                *(float2*)(C + (size_t)row * Nout + col)       = lo;
                *(float2*)(C + (size_t)(row + 8) * Nout + col) = hi;
            }
        }
    }
}

// ---------------------------------------------------------------------------
// xproj tensor GEMM, M=64 CTA tile for grid fill (256 CTAs vs 128).
// ---------------------------------------------------------------------------
constexpr int XP_STAGE = 32768;
constexpr int XP_SMEM  = 2 * XP_STAGE;   // 65536 B

__global__ void __launch_bounds__(256, 2) xproj_kernel()
{
    extern __shared__ __align__(1024) char smem[];
    const uint32_t su = smem_u32(smem);
    const int dir = blockIdx.z;
    const __half* Ah = &g_xth[dir][0];
    const __half* Al = &g_xtl[dir][0];
    const __half* Bh = &g_wx[dir][0];
    float* C   = &g_dbl[dir][0];
    __half* dH = &g_dt_h[dir][0];
    __half* dL = &g_dt_l[dir][0];

    const int bm = blockIdx.y * 64;
    const int tid  = threadIdx.x;
    const int wid  = tid >> 5;
    const int lane = tid & 31;

    const int prow = tid >> 3;
    const int pkc  = tid & 7;
    auto issue = [&](int c) {
        const uint32_t sb = su + (uint32_t)(c & 1) * XP_STAGE;
        const int k0 = c * 64;
#pragma unroll
        for (int i = 0; i < 2; ++i) {
            const int row = prow + i * 32;
            const uint32_t off = sw128((uint32_t)(row * 128 + pkc * 16));
            const size_t ga = (size_t)(bm + row) * CDI + k0 + pkc * 8;
            cp16(sb + off,        Ah + ga);
            cp16(sb + 8192 + off, Al + ga);
        }
#pragma unroll
        for (int i = 0; i < 4; ++i) {
            const int row = prow + i * 32;
            const uint32_t off = sw128((uint32_t)(row * 128 + pkc * 16));
            const size_t gb = (size_t)row * CDI + k0 + pkc * 8;
            cp16(sb + 16384 + off, Bh + gb);
        }
        asm volatile("cp.async.commit_group;" ::: "memory");
    };

    const int m0 = (wid & 1) * 32;
    const int n0 = (wid >> 1) * 32;
    const int g    = lane >> 3;
    const int lr   = lane & 7;
    const int lrow = (g & 1) * 8 + lr;
    const int lkb  = (g >> 1) * 16;

    float acc[2][4][4] = {};

    issue(0); issue(1);

    const int NC = CDI / 64;
    for (int c = 0; c < NC; ++c) {
        asm volatile("cp.async.wait_group 1;" ::: "memory");
        __syncthreads();
        const uint32_t sb = su + (uint32_t)(c & 1) * XP_STAGE;
#pragma unroll
        for (int kk = 0; kk < 4; ++kk) {
            uint32_t ah[2][4], al[2][4];
#pragma unroll
            for (int mt = 0; mt < 2; ++mt) {
                uint32_t off = sw128((uint32_t)((m0 + mt*16 + lrow) * 128 + kk*32 + lkb));
                ldsm4(sb + off,        ah[mt]);
                ldsm4(sb + 8192 + off, al[mt]);
            }
#pragma unroll
            for (int np = 0; np < 2; ++np) {
                uint32_t boff = sw128((uint32_t)((n0 + np*16 + lrow) * 128 + kk*32 + lkb));
                uint32_t bh[4];
                ldsm4(sb + 16384 + boff, bh);
#pragma unroll
                for (int mt = 0; mt < 2; ++mt) {
                    mma_f16(acc[mt][2*np],   ah[mt], bh[0], bh[2]);
                    mma_f16(acc[mt][2*np],   al[mt], bh[0], bh[2]);
                    mma_f16(acc[mt][2*np+1], ah[mt], bh[1], bh[3]);
                    mma_f16(acc[mt][2*np+1], al[mt], bh[1], bh[3]);
                }
            }
        }
        __syncthreads();
        if (c + 2 < NC) issue(c + 2);
        else asm volatile("cp.async.commit_group;" ::: "memory");
    }

    const int er = lane >> 2;
    const int ec = (lane & 3) * 2;
#pragma unroll
    for (int mt = 0; mt < 2; ++mt) {
#pragma unroll
        for (int nt = 0; nt < 4; ++nt) {
            const int row0 = bm + m0 + mt*16 + er;
            const int col  = n0 + nt*8 + ec;
#pragma unroll
            for (int rr = 0; rr < 2; ++rr) {
                const int row = row0 + rr*8;
#pragma unroll
                for (int e = 0; e < 2; ++e) {
                    const int cc = col + e;
                    const float v = acc[mt][nt][rr*2+e];
                    if (cc < CRP) {
                        float dv = (cc < CR) ? v : 0.f;
                        __half hb = __float2half_rn(dv);
                        dH[(size_t)row * CRP + cc] = hb;
                        dL[(size_t)row * CRP + cc] =
                            __float2half_rn(dv - __half2float(hb));
                    }
                    if (cc >= CR && cc < CPROJ)
                        C[(size_t)row * CPROJ + cc] = v;
                }
            }
        }
    }
}

// ---------------------------------------------------------------------------
// dtproj tensor GEMM: delta[row,d] = softplus(sum_r dt[row,r]*W[d,r] + bias[d])
// ---------------------------------------------------------------------------
__device__ __forceinline__ float softplus_f(float v) {
    return (v > 20.f) ? v : log1pf(__expf(v));
}

__global__ void __launch_bounds__(256) dtgemm_kernel(
    const float* __restrict__ bias_f, const float* __restrict__ bias_b)
{
    extern __shared__ __align__(1024) char smem[];
    const uint32_t su = smem_u32(smem);
    const int dir = blockIdx.z;
    const __half* Ah = &g_dt_h[dir][0];
    const __half* Al = &g_dt_l[dir][0];
    const __half* Bh = &g_wdt_h[dir][0];
    const __half* Bl = &g_wdt_l[dir][0];
    const float* bias = dir ? bias_b : bias_f;
    float* C = &g_delta[dir][0];

    const int bm = blockIdx.y * 128;
    const int bn = blockIdx.x * 128;
    const int tid  = threadIdx.x;
    const int wid  = tid >> 5;
    const int lane = tid & 31;

    const int prow = tid >> 3;
    const int pkc  = tid & 7;
#pragma unroll
    for (int i = 0; i < 4; ++i) {
        const int row = prow + i * 32;
        const uint32_t off = sw128((uint32_t)(row * 128 + pkc * 16));
        const size_t ga = (size_t)(bm + row) * CRP + pkc * 8;
        const size_t gb = (size_t)(bn + row) * CRP + pkc * 8;
        cp16(su + off,         Ah + ga);
        cp16(su + 16384 + off, Al + ga);
        cp16(su + 32768 + off, Bh + gb);
        cp16(su + 49152 + off, Bl + gb);
    }
    asm volatile("cp.async.commit_group;" ::: "memory");
    asm volatile("cp.async.wait_group 0;" ::: "memory");
    __syncthreads();

    const int m0 = (wid & 3) * 32;
    const int n0 = (wid >> 2) * 64;
    const int g    = lane >> 3;
    const int lr   = lane & 7;
    const int lrow = (g & 1) * 8 + lr;
    const int lkb  = (g >> 1) * 16;

    float acc[2][8][4] = {};
#pragma unroll
    for (int kk = 0; kk < 4; ++kk) {
        uint32_t ah[2][4], al[2][4];
#pragma unroll
        for (int mt = 0; mt < 2; ++mt) {
            uint32_t off = sw128((uint32_t)((m0 + mt*16 + lrow) * 128 + kk*32 + lkb));
            ldsm4(su + off,         ah[mt]);
            ldsm4(su + 16384 + off, al[mt]);
        }
#pragma unroll
        for (int np = 0; np < 4; ++np) {
            uint32_t boff = sw128((uint32_t)((n0 + np*16 + lrow) * 128 + kk*32 + lkb));
            uint32_t bh[4], bl[4];
            ldsm4(su + 32768 + boff, bh);
            ldsm4(su + 49152 + boff, bl);
#pragma unroll
            for (int mt = 0; mt < 2; ++mt) {
                mma_f16(acc[mt][2*np],   ah[mt], bh[0], bh[2]);
                mma_f16(acc[mt][2*np],   al[mt], bh[0], bh[2]);
                mma_f16(acc[mt][2*np],   ah[mt], bl[0], bl[2]);
                mma_f16(acc[mt][2*np+1], ah[mt], bh[1], bh[3]);
                mma_f16(acc[mt][2*np+1], al[mt], bh[1], bh[3]);
                mma_f16(acc[mt][2*np+1], ah[mt], bl[1], bl[3]);
            }
        }
    }

    const int er = lane >> 2;
    const int ec = (lane & 3) * 2;
#pragma unroll
    for (int mt = 0; mt < 2; ++mt) {
#pragma unroll
        for (int nt = 0; nt < 8; ++nt) {
            const int row = bm + m0 + mt*16 + er;
            const int col = bn + n0 + nt*8 + ec;
            const float b0 = bias[col], b1 = bias[col+1];
            float2 lo = { softplus_f(acc[mt][nt][0] + b0),
                          softplus_f(acc[mt][nt][1] + b1) };
            float2 hi = { softplus_f(acc[mt][nt][2] + b0),
                          softplus_f(acc[mt][nt][3] + b1) };
            *(float2*)(C + (size_t)row * CDI + col)       = lo;
            *(float2*)(C + (size_t)(row + 8) * CDI + col) = hi;
        }
    }
}

// ---------------------------------------------------------------------------
// fp32 -> fp16 hi/lo splitter and single-fp16 converter (grid-stride, float4)
// ---------------------------------------------------------------------------
__global__ void split2_kernel(const float* __restrict__ s,
                              __half* __restrict__ h, __half* __restrict__ l, int n4)
{
    for (int i = blockIdx.x * blockDim.x + threadIdx.x; i < n4;
         i += gridDim.x * blockDim.x) {
        float4 v = ((const float4*)s)[i];
        __half hx = __float2half_rn(v.x), hy = __float2half_rn(v.y);
        __half hz = __float2half_rn(v.z), hw = __float2half_rn(v.w);
        __half lx = __float2half_rn(v.x - __half2float(hx));
        __half ly = __float2half_rn(v.y - __half2float(hy));
        __half lz = __float2half_rn(v.z - __half2float(hz));
        __half lw = __float2half_rn(v.w - __half2float(hw));
        __half2 h01 = __halves2half2(hx, hy), h23 = __halves2half2(hz, hw);
        __half2 l01 = __halves2half2(lx, ly), l23 = __halves2half2(lz, lw);
        ((uint2*)h)[i] = make_uint2(*(uint32_t*)&h01, *(uint32_t*)&h23);
        ((uint2*)l)[i] = make_uint2(*(uint32_t*)&l01, *(uint32_t*)&l23);
    }
}

__global__ void tof16_kernel(const float* __restrict__ s, __half* __restrict__ h, int n4)
{
    for (int i = blockIdx.x * blockDim.x + threadIdx.x; i < n4;
         i += gridDim.x * blockDim.x) {
        float4 v = ((const float4*)s)[i];
        __half2 h01 = __halves2half2(__float2half_rn(v.x), __float2half_rn(v.y));
        __half2 h23 = __halves2half2(__float2half_rn(v.z), __float2half_rn(v.w));
        ((uint2*)h)[i] = make_uint2(*(uint32_t*)&h01, *(uint32_t*)&h23);
    }
}

// xproj weights: pad 80 -> 128 rows (zeros), single fp16, both dirs.
__global__ void padw_kernel(const float* __restrict__ wf, const float* __restrict__ wb)
{
    const int total4 = 2 * 128 * CDI / 4;
    for (int i = blockIdx.x * blockDim.x + threadIdx.x; i < total4;
         i += gridDim.x * blockDim.x) {
        int e = i * 4;
        int dir = e / (128 * CDI);
        int rem = e - dir * 128 * CDI;
        int row = rem / CDI;
        int k   = rem - row * CDI;
        float4 v = {0.f, 0.f, 0.f, 0.f};
        const float* W = dir ? wb : wf;
        if (row < CPROJ) v = *(const float4*)(W + (size_t)row * CDI + k);
        __half2 h01 = __halves2half2(__float2half_rn(v.x), __float2half_rn(v.y));
        __half2 h23 = __halves2half2(__float2half_rn(v.z), __float2half_rn(v.w));
        ((uint2*)&g_wx[0][0])[i] = make_uint2(*(uint32_t*)&h01, *(uint32_t*)&h23);
    }
}

// dtproj weights: pad K 48 -> 64 (zeros), split to fp16 hi/lo, both dirs.
__global__ void padwd_kernel(const float* __restrict__ wf, const float* __restrict__ wb)
{
    const int total4 = 2 * CDI * CRP / 4;
    for (int i = blockIdx.x * blockDim.x + threadIdx.x; i < total4;
         i += gridDim.x * blockDim.x) {
        int e = i * 4;
        int dir = e / (CDI * CRP);
        int rem = e - dir * CDI * CRP;
        int row = rem / CRP;
        int k   = rem - row * CRP;
        float4 v = {0.f, 0.f, 0.f, 0.f};
        const float* W = dir ? wb : wf;
        if (k < CR) v = *(const float4*)(W + (size_t)row * CR + k);
        __half hx = __float2half_rn(v.x), hy = __float2half_rn(v.y);
        __half hz = __float2half_rn(v.z), hw = __float2half_rn(v.w);
        __half lx = __float2half_rn(v.x - __half2float(hx));
        __half ly = __float2half_rn(v.y - __half2float(hy));
        __half lz = __float2half_rn(v.z - __half2float(hz));
        __half lw = __float2half_rn(v.w - __half2float(hw));
        __half2 h01 = __halves2half2(hx, hy), h23 = __halves2half2(hz, hw);
        __half2 l01 = __halves2half2(lx, ly), l23 = __halves2half2(lz, lw);
        ((uint2*)&g_wdt_h[0][0])[i] = make_uint2(*(uint32_t*)&h01, *(uint32_t*)&h23);
        ((uint2*)&g_wdt_l[0][0])[i] = make_uint2(*(uint32_t*)&l01, *(uint32_t*)&l23);
    }
}

// ---------------------------------------------------------------------------
// Depthwise causal conv (K=4) + bias + SiLU, transpose to (b,t,d).
// MERGED DIRECTIONS: one block loads x[t0-3 .. t0+130] once, emits both dirs.
// ---------------------------------------------------------------------------
__global__ void __launch_bounds__(256) conv_silu_kernel(
    const float* __restrict__ cw_f, const float* __restrict__ cb_f,
    const float* __restrict__ cw_b, const float* __restrict__ cb_b)
{
    const int t0 = blockIdx.x * 128;
    const int d0 = blockIdx.y * 32;
    const int b  = blockIdx.z;

    __shared__ float xs[32][135];

    const float* xbase = g_xz + ((size_t)b * (2*CDI) + d0) * CL;
    const int base = t0 - 3;

    const int lane = threadIdx.x & 31;
    const int wy   = threadIdx.x >> 5;
    for (int d = wy; d < 32; d += 8) {
        const float* row = xbase + (size_t)d * CL;
        for (int i = lane; i < 134; i += 32) {
            int u = base + i;
            xs[d][i] = (u >= 0 && u < CL) ? row[u] : 0.f;
        }
    }
    __syncthreads();

    const int d  = threadIdx.x & 31;
    const int sg = threadIdx.x >> 5;
    const float wf0 = cw_f[(d0+d)*CK + 0];
    const float wf1 = cw_f[(d0+d)*CK + 1];
    const float wf2 = cw_f[(d0+d)*CK + 2];
    const float wf3 = cw_f[(d0+d)*CK + 3];
    const float bf  = cb_f[d0+d];
    const float wb0 = cw_b[(d0+d)*CK + 0];
    const float wb1 = cw_b[(d0+d)*CK + 1];
    const float wb2 = cw_b[(d0+d)*CK + 2];
    const float wb3 = cw_b[(d0+d)*CK + 3];
    const float bb  = cb_b[d0+d];

    __half* ohf = g_xth[0] + (size_t)b * CL * CDI;
    __half* olf = g_xtl[0] + (size_t)b * CL * CDI;
    __half* ohb = g_xth[1] + (size_t)b * CL * CDI;
    __half* olb = g_xtl[1] + (size_t)b * CL * CDI;
    const int tb0 = CL - 128 - t0;
#pragma unroll
    for (int q = 0; q < 16; ++q) {
        int s = sg + 8*q;
        {
            float v = wf0*xs[d][s] + wf1*xs[d][s+1] + wf2*xs[d][s+2] + wf3*xs[d][s+3] + bf;
            float sv = v / (1.f + __expf(-v));
            size_t idx = (size_t)(t0 + s) * CDI + d0 + d;
            __half hb = __float2half_rn(sv);
            ohf[idx] = hb;
            olf[idx] = __float2half_rn(sv - __half2float(hb));
        }
        {
            float v = wb3*xs[d][130-s] + wb2*xs[d][131-s] + wb1*xs[d][132-s]
                    + wb0*xs[d][133-s] + bb;
            float sv = v / (1.f + __expf(-v));
            size_t idx = (size_t)(tb0 + s) * CDI + d0 + d;
            __half hb = __float2half_rn(sv);
            ohb[idx] = hb;
            olb[idx] = __float2half_rn(sv - __half2float(hb));
        }
    }
}

// ---------------------------------------------------------------------------
// Selective scan, 2-states-per-lane layout (round-11 winner).
// ---------------------------------------------------------------------------
__global__ void __launch_bounds__(128) scan_kernel(
    const float* __restrict__ Alog_f, const float* __restrict__ Dv_f,
    const float* __restrict__ Alog_b, const float* __restrict__ Dv_b)
{
    const int dir = blockIdx.z;
    const int b   = blockIdx.y;
    const int d0  = blockIdx.x * 16;

    const float* Alog = dir ? Alog_b : Alog_f;
    const float* Dvec = dir ? Dv_b   : Dv_f;
    const float* delta = g_delta[dir] + (size_t)b * CL * CDI;
    const __half* xth  = g_xth[dir]   + (size_t)b * CL * CDI;
    const __half* xtl  = g_xtl[dir]   + (size_t)b * CL * CDI;
    const float* dbl   = g_dbl[dir]   + (size_t)b * CL * CPROJ;
    float* yout        = g_y[dir]     + (size_t)b * CL * CDI;

    __shared__ __align__(16) float sd[64][16];   // dt
    __shared__ __align__(16) float sx[64][16];   // dt*x
    __shared__ __align__(16) float sB[64][16];
    __shared__ __align__(16) float sC[64][16];
    __shared__ __align__(16) float sxD[64][16];  // x*D

    const int tid  = threadIdx.x;
    const int lane = tid & 31;
    const int wid  = tid >> 5;
    const int ch   = wid*4 + (lane >> 3);
    const int n    = lane & 7;
    const int d    = d0 + ch;

    constexpr float LOG2E = 1.4426950408889634f;
    const float Aval0 = -__expf(Alog[d*CN + n])     * LOG2E;
    const float Aval1 = -__expf(Alog[d*CN + n + 8]) * LOG2E;
    float h0 = 0.f, h1 = 0.f;

    const int li = tid >> 1;
    const int lj = (tid & 1) * 8;

    float rDv[8];
#pragma unroll
    for (int j = 0; j < 8; ++j) rDv[j] = Dvec[d0 + lj + j];

    float rd[8], rx[8], rB[8], rC[8];
    auto LD = [&](int t0) {
        float4 d0v = *(const float4*)(delta + (size_t)(t0+li)*CDI + d0 + lj);
        float4 d1v = *(const float4*)(delta + (size_t)(t0+li)*CDI + d0 + lj + 4);
        rd[0]=d0v.x; rd[1]=d0v.y; rd[2]=d0v.z; rd[3]=d0v.w;
        rd[4]=d1v.x; rd[5]=d1v.y; rd[6]=d1v.z; rd[7]=d1v.w;
        uint4 xh = *(const uint4*)(xth + (size_t)(t0+li)*CDI + d0 + lj);
        uint4 xl = *(const uint4*)(xtl + (size_t)(t0+li)*CDI + d0 + lj);
        const uint32_t* xhp = &xh.x;
        const uint32_t* xlp = &xl.x;
#pragma unroll
        for (int q = 0; q < 4; ++q) {
            float2 fh = __half22float2(*(const __half2*)&xhp[q]);
            float2 fl = __half22float2(*(const __half2*)&xlp[q]);
            rx[2*q+0] = fh.x + fl.x;
            rx[2*q+1] = fh.y + fl.y;
        }
        float4 b0v = *(const float4*)(dbl + (size_t)(t0+li)*CPROJ + CR + lj);
        float4 b1v = *(const float4*)(dbl + (size_t)(t0+li)*CPROJ + CR + lj + 4);
        rB[0]=b0v.x; rB[1]=b0v.y; rB[2]=b0v.z; rB[3]=b0v.w;
        rB[4]=b1v.x; rB[5]=b1v.y; rB[6]=b1v.z; rB[7]=b1v.w;
        float4 c0v = *(const float4*)(dbl + (size_t)(t0+li)*CPROJ + CR + CN + lj);
        float4 c1v = *(const float4*)(dbl + (size_t)(t0+li)*CPROJ + CR + CN + lj + 4);
        rC[0]=c0v.x; rC[1]=c0v.y; rC[2]=c0v.z; rC[3]=c0v.w;
        rC[4]=c1v.x; rC[5]=c1v.y; rC[6]=c1v.z; rC[7]=c1v.w;
    };
    LD(0);

    const int NCH = CL / 64;
    for (int c = 0; c < NCH; ++c) {
        __syncthreads();
        {
            float4 v;
            v = make_float4(rd[0], rd[1], rd[2], rd[3]);            *(float4*)&sd[li][lj]   = v;
            v = make_float4(rd[4], rd[5], rd[6], rd[7]);            *(float4*)&sd[li][lj+4] = v;
            v = make_float4(rd[0]*rx[0], rd[1]*rx[1], rd[2]*rx[2], rd[3]*rx[3]); *(float4*)&sx[li][lj]   = v;
            v = make_float4(rd[4]*rx[4], rd[5]*rx[5], rd[6]*rx[6], rd[7]*rx[7]); *(float4*)&sx[li][lj+4] = v;
            v = make_float4(rB[0], rB[1], rB[2], rB[3]);            *(float4*)&sB[li][lj]   = v;
            v = make_float4(rB[4], rB[5], rB[6], rB[7]);            *(float4*)&sB[li][lj+4] = v;
            v = make_float4(rC[0], rC[1], rC[2], rC[3]);            *(float4*)&sC[li][lj]   = v;
            v = make_float4(rC[4], rC[5], rC[6], rC[7]);            *(float4*)&sC[li][lj+4] = v;
            v = make_float4(rx[0]*rDv[0], rx[1]*rDv[1], rx[2]*rDv[2], rx[3]*rDv[3]); *(float4*)&sxD[li][lj]   = v;
            v = make_float4(rx[4]*rDv[4], rx[5]*rDv[5], rx[6]*rDv[6], rx[7]*rDv[7]); *(float4*)&sxD[li][lj+4] = v;
        }
        __syncthreads();
        if (c + 1 < NCH) LD((c+1) * 64);

        const int tbase = c * 64;
#pragma unroll 8
        for (int s = 0; s < 64; ++s) {
            float dt  = sd[s][ch];
            float dtx = sx[s][ch];
            float B0 = sB[s][n],     C0 = sC[s][n];
            float B1 = sB[s][n + 8], C1 = sC[s][n + 8];
            float a0 = ex2f(dt * Aval0);
            float a1 = ex2f(dt * Aval1);
            h0 = fmaf(a0, h0, dtx * B0);
            h1 = fmaf(a1, h1, dtx * B1);
            float p = fmaf(h1, C1, h0 * C0);
            p += __shfl_xor_sync(0xffffffffu, p, 4);
            p += __shfl_xor_sync(0xffffffffu, p, 2);
            p += __shfl_xor_sync(0xffffffffu, p, 1);
            if (n == 0)
                yout[(size_t)(tbase + s)*CDI + d] = p + sxD[s][ch];
        }
    }
}

// ---------------------------------------------------------------------------
// Gate + direction merge -> single fp16 comb (out_proj 1-term operand)
// ---------------------------------------------------------------------------
__global__ void __launch_bounds__(256) combine_kernel()
{
    const int l0 = blockIdx.x * 32;
    const int d0 = blockIdx.y * 32;
    const int b  = blockIdx.z;

    __shared__ float zs[32][33];
    const int lane = threadIdx.x & 31;
    const int wy   = threadIdx.x >> 5;

    const float* zbase = g_xz + ((size_t)b * (2*CDI) + CDI + d0) * CL;
    for (int dd = wy; dd < 32; dd += 8)
        zs[dd][lane] = zbase[(size_t)dd * CL + l0 + lane];
    __syncthreads();

#pragma unroll
    for (int q = 0; q < 4; ++q) {
        int lr = wy + 8*q;
        int l = l0 + lr;
        size_t idx  = ((size_t)b*CL + l)*CDI + d0 + lane;
        size_t idxr = ((size_t)b*CL + (CL-1-l))*CDI + d0 + lane;
        float yf = g_y[0][idx];
        float yb = g_y[1][idxr];
        float zv = zs[lane][lr];
        float s = zv / (1.f + __expf(-zv));
        float cv = (yf + yb) * s;
        g_cmb_h[idx] = __float2half_rn(cv);
    }
}

// ---------------------------------------------------------------------------
// Launcher
// ---------------------------------------------------------------------------
extern "C" void kernel_launch(void* const* d_in, const int* in_sizes, int n_in,
                              void* d_out, int out_size)
{
    (void)in_sizes; (void)n_in; (void)out_size;

    const float* hidden  = (const float*)d_in[0];
    const float* in_w    = (const float*)d_in[1];
    const float* conv_w  = (const float*)d_in[2];
    const float* conv_b  = (const float*)d_in[3];
    const float* xproj_w = (const float*)d_in[4];
    const float* dtw     = (const float*)d_in[5];
    const float* dtb     = (const float*)d_in[6];
    const float* A_log   = (const float*)d_in[7];
    const float* Dv      = (const float*)d_in[8];
    const float* conv_w2 = (const float*)d_in[9];
    const float* conv_b2 = (const float*)d_in[10];
    const float* xproj_w2= (const float*)d_in[11];
    const float* dtw2    = (const float*)d_in[12];
    const float* dtb2    = (const float*)d_in[13];
    const float* A_log2  = (const float*)d_in[14];
    const float* Dv2     = (const float*)d_in[15];
    const float* out_w   = (const float*)d_in[16];

    void *p_xz;
    void *p_hid_h, *p_hid_l, *p_w1, *p_w2, *p_cmb_h;
    cudaGetSymbolAddress(&p_xz, g_xz);
    cudaGetSymbolAddress(&p_hid_h, g_hid_h);
    cudaGetSymbolAddress(&p_hid_l, g_hid_l);
    cudaGetSymbolAddress(&p_w1, g_w1);
    cudaGetSymbolAddress(&p_w2, g_w2);
    cudaGetSymbolAddress(&p_cmb_h, g_cmb_h);

    cudaFuncSetAttribute(gemm_f16_kernel<0>,
                         cudaFuncAttributeMaxDynamicSharedMemorySize, GF_SMEM);
    cudaFuncSetAttribute(gemm_f16_kernel<2>,
                         cudaFuncAttributeMaxDynamicSharedMemorySize, GF_SMEM);
    cudaFuncSetAttribute(xproj_kernel,
                         cudaFuncAttributeMaxDynamicSharedMemorySize, XP_SMEM);
    cudaFuncSetAttribute(dtgemm_kernel,
                         cudaFuncAttributeMaxDynamicSharedMemorySize, 65536);

    // 0) operand packing
    split2_kernel<<<1024, 256>>>(hidden, (__half*)p_hid_h, (__half*)p_hid_l, CB*CL*CDM/4);
    tof16_kernel<<<512, 256>>>(in_w, (__half*)p_w1, 2*CDI*CDM/4);
    tof16_kernel<<<512, 256>>>(out_w, (__half*)p_w2, CDM*CDI/4);
    padw_kernel<<<512, 256>>>(xproj_w, xproj_w2);
    padwd_kernel<<<192, 256>>>(dtw, dtw2);

    // 1) in_proj: A = w1 (single), B = hidden (split).  M=3072, N=4096, K=768
    gemm_f16_kernel<0><<<dim3(CL/128, (2*CDI)/128, CB), 256, GF_SMEM>>>(
        (const __half*)p_w1, (const __half*)p_hid_l, (const __half*)p_hid_h,
        (float*)p_xz, CL, CDM,
        0, (long long)CL * CDM, (long long)(2*CDI) * CL, CDM / 64);

    // 2) conv + SiLU + transpose (both dirs per block) -> fp16 hi/lo xt
    conv_silu_kernel<<<dim3(CL/128, CDI/32, CB), 256>>>(
        conv_w, conv_b, conv_w2, conv_b2);

    // 3) xproj, M=64 tiles (256 CTAs): dt fp16 hi/lo + fp32 B|C
    xproj_kernel<<<dim3(1, (CB*CL)/64, 2), 256, XP_SMEM>>>();

    // 4) dtproj as tensor GEMM + softplus -> delta
    dtgemm_kernel<<<dim3(CDI/128, (CB*CL)/128, 2), 256, 65536>>>(dtb, dtb2);

    // 5) selective scan (2-states-per-lane, 128-thread CTAs)
    scan_kernel<<<dim3(CDI/16, CB, 2), 128>>>(A_log, Dv, A_log2, Dv2);

    // 6) gate + direction merge -> single fp16 comb
    combine_kernel<<<dim3(CL/32, CDI/32, CB), 256>>>();

    // 7) out_proj, 1-term: A = comb (single fp16), B = w2 (single fp16).
    gemm_f16_kernel<2><<<dim3(CDM/128, (CB*CL)/128, 1), 256, GF_SMEM>>>(
        (const __half*)p_cmb_h, (const __half*)p_cmb_h, (const __half*)p_w2,
        (float*)d_out, CDM, CDI,
        0, 0, 0, CDI / 64);
}

// round 13
// speedup vs baseline: 1.3305x; 1.0372x over previous
#include <cuda_runtime.h>
#include <cuda_fp16.h>
#include <cstdint>

// Problem constants
constexpr int CB  = 2;     // batch
constexpr int CL  = 4096;  // seq len
constexpr int CDM = 768;   // d_model
constexpr int CDI = 1536;  // d_inner
constexpr int CN  = 16;    // state dim
constexpr int CR  = 48;    // dt rank
constexpr int CK  = 4;     // conv width
constexpr int CPROJ = CR + 2*CN; // 80
constexpr int CRP = 64;    // dt rank padded for MMA K

// ---------------------------------------------------------------------------
// Scratch (device globals; no runtime allocation allowed)
// ---------------------------------------------------------------------------
__device__ float g_xz[CB * 2 * CDI * CL];        // (b, e, l)
__device__ float g_dbl[2][CB * CL * CPROJ];      // per dir, (b*L, 80): only B|C cols used
__device__ float g_delta[2][CB * CL * CDI];      // per dir, post-softplus
__device__ float g_y[2][CB * CL * CDI];          // per dir, scan out (+D*x)

// fp16 operands for tensor GEMMs
__device__ __half g_hid_h[CB*CL*CDM], g_hid_l[CB*CL*CDM];  // hidden hi/lo (split side)
__device__ __half g_w1[2*CDI*CDM];                          // in_proj W (single)
__device__ __half g_w2[CDM*CDI];                            // out_proj W (single)
__device__ __half g_wx[2][128*CDI];                         // xproj W padded 80->128 (single)
__device__ __half g_xth[2][CB*CL*CDI], g_xtl[2][CB*CL*CDI]; // conv out hi/lo (scan uses both)
__device__ __half g_cmb_h[CB*CL*CDI];                       // gated sum, single fp16
__device__ __half g_dt_h[2][CB*CL*CRP], g_dt_l[2][CB*CL*CRP]; // dt rows padded 48->64, hi/lo
__device__ __half g_wdt_h[2][CDI*CRP],  g_wdt_l[2][CDI*CRP];  // dtproj W padded, hi/lo

// ---------------------------------------------------------------------------
// PTX helpers
// ---------------------------------------------------------------------------
__device__ __forceinline__ uint32_t smem_u32(const void* p) {
    uint32_t a;
    asm("{ .reg .u64 t; cvta.to.shared.u64 t, %1; cvt.u32.u64 %0, t; }" : "=r"(a) : "l"(p));
    return a;
}
__device__ __forceinline__ uint32_t sw128(uint32_t b) { return b ^ ((b >> 3) & 0x70); }

__device__ __forceinline__ void ldsm4(uint32_t addr, uint32_t r[4]) {
    asm volatile("ldmatrix.sync.aligned.m8n8.x4.shared.b16 {%0,%1,%2,%3}, [%4];"
        : "=r"(r[0]), "=r"(r[1]), "=r"(r[2]), "=r"(r[3]) : "r"(addr));
}
__device__ __forceinline__ void mma_f16(float* d, const uint32_t* a, uint32_t b0, uint32_t b1) {
    asm volatile("mma.sync.aligned.m16n8k16.row.col.f32.f16.f16.f32 "
        "{%0,%1,%2,%3}, {%4,%5,%6,%7}, {%8,%9}, {%0,%1,%2,%3};"
        : "+f"(d[0]), "+f"(d[1]), "+f"(d[2]), "+f"(d[3])
        : "r"(a[0]), "r"(a[1]), "r"(a[2]), "r"(a[3]), "r"(b0), "r"(b1));
}
__device__ __forceinline__ void cp16(uint32_t s, const void* g) {
    asm volatile("cp.async.ca.shared.global [%0], [%1], 16;" :: "r"(s), "l"(g));
}
__device__ __forceinline__ float ex2f(float x) {
    float r;
    asm("ex2.approx.f32 %0, %1;" : "=f"(r) : "f"(x));
    return r;
}

// ---------------------------------------------------------------------------
// fp16 tensor GEMM (M=128 tile):  C[m,n] = sum_k A[m,k]*B[n,k]
// SPLIT_A==0: B split (2 terms), but lo-term only for row blocks bm < mlimit
//             (rows >= mlimit get 1-term; used by in_proj to keep x exactish
//              while letting gate-only z rows absorb fp16 quantization).
// SPLIT_A==2: no split (1 term; Xl ignored).
// CTA tile 128x128, BK=64, 2-stage cp.async ring, 96KB smem -> 2 CTA/SM.
// ---------------------------------------------------------------------------
constexpr int GF_STAGE = 49152;
constexpr int GF_SMEM  = 2 * GF_STAGE;   // 98304 B

template <int SPLIT_A>
__global__ void __launch_bounds__(256, 2) gemm_f16_kernel(
    const __half* __restrict__ Ah, const __half* __restrict__ Xl,  // Xl = Bl
    const __half* __restrict__ Bh,
    float* __restrict__ C, int Nout, int Kd,
    long long strideA, long long strideB, long long strideC, int NC, int mlimit)
{
    extern __shared__ __align__(1024) char smem[];
    const uint32_t su = smem_u32(smem);
    Ah += (size_t)blockIdx.z * strideA;
    Bh += (size_t)blockIdx.z * strideB;
    Xl += (size_t)blockIdx.z * strideB;
    C  += (size_t)blockIdx.z * strideC;
    const int bm = blockIdx.y * 128;
    const int bn = blockIdx.x * 128;
    const bool use_lo = (SPLIT_A == 0) && (bm < mlimit);
    const int tid  = threadIdx.x;
    const int wid  = tid >> 5;
    const int lane = tid & 31;

    const int prow = tid >> 3;
    const int pkc  = tid & 7;
    auto issue = [&](int c) {
        const uint32_t sb = su + (uint32_t)(c & 1) * GF_STAGE;
        const int k0 = c * 64;
#pragma unroll
        for (int i = 0; i < 4; ++i) {
            const int row = prow + i * 32;
            const uint32_t off = sw128((uint32_t)(row * 128 + pkc * 16));
            const size_t ga = (size_t)(bm + row) * Kd + k0 + pkc * 8;
            const size_t gb = (size_t)(bn + row) * Kd + k0 + pkc * 8;
            cp16(sb + off,         Ah + ga);
            if (use_lo)
                cp16(sb + 16384 + off, Xl + gb);
            cp16(sb + 32768 + off, Bh + gb);
        }
        asm volatile("cp.async.commit_group;" ::: "memory");
    };

    const int m0 = (wid & 3) * 32;
    const int n0 = (wid >> 2) * 64;
    const int g    = lane >> 3;
    const int lr   = lane & 7;
    const int lrow = (g & 1) * 8 + lr;
    const int lkb  = (g >> 1) * 16;

    float acc[2][8][4] = {};

    issue(0); issue(1);

    for (int c = 0; c < NC; ++c) {
        asm volatile("cp.async.wait_group 1;" ::: "memory");
        __syncthreads();
        const uint32_t sb = su + (uint32_t)(c & 1) * GF_STAGE;
#pragma unroll
        for (int kk = 0; kk < 4; ++kk) {
            uint32_t ah[2][4];
#pragma unroll
            for (int mt = 0; mt < 2; ++mt) {
                uint32_t off = sw128((uint32_t)((m0 + mt*16 + lrow) * 128 + kk*32 + lkb));
                ldsm4(sb + off, ah[mt]);
            }
#pragma unroll
            for (int np = 0; np < 4; ++np) {
                uint32_t boff = sw128((uint32_t)((n0 + np*16 + lrow) * 128 + kk*32 + lkb));
                uint32_t bh[4], bl[4];
                ldsm4(sb + 32768 + boff, bh);
                if (use_lo) ldsm4(sb + 16384 + boff, bl);
#pragma unroll
                for (int mt = 0; mt < 2; ++mt) {
                    mma_f16(acc[mt][2*np],   ah[mt], bh[0], bh[2]);
                    mma_f16(acc[mt][2*np+1], ah[mt], bh[1], bh[3]);
                    if (use_lo) {
                        mma_f16(acc[mt][2*np],   ah[mt], bl[0], bl[2]);
                        mma_f16(acc[mt][2*np+1], ah[mt], bl[1], bl[3]);
                    }
                }
            }
        }
        __syncthreads();
        if (c + 2 < NC) issue(c + 2);
        else asm volatile("cp.async.commit_group;" ::: "memory");
    }

    const int er = lane >> 2;
    const int ec = (lane & 3) * 2;
#pragma unroll
    for (int mt = 0; mt < 2; ++mt) {
#pragma unroll
        for (int nt = 0; nt < 8; ++nt) {
            const int row = bm + m0 + mt*16 + er;
            const int col = bn + n0 + nt*8 + ec;
            if (col < Nout) {
                float2 lo = { acc[mt][nt][0], acc[mt][nt][1] };
                float2 hi = { acc[mt][nt][2], acc[mt][nt][3] };
                *(float2*)(C + (size_t)row * Nout + col)       = lo;
                *(float2*)(C + (size_t)(row + 8) * Nout + col) = hi;
            }
        }
    }
}

// ---------------------------------------------------------------------------
// xproj tensor GEMM, M=64 CTA tile, 1-term (xt-hi only).
// A = xt-hi (single fp16), B = wx (single fp16, 128 padded rows).
// Stage: Ah 8K @0 | Bh 16K @16384 (slot @8192 unused). 2 stages = 64KB.
// ---------------------------------------------------------------------------
constexpr int XP_STAGE = 32768;
constexpr int XP_SMEM  = 2 * XP_STAGE;   // 65536 B

__global__ void __launch_bounds__(256, 2) xproj_kernel()
{
    extern __shared__ __align__(1024) char smem[];
    const uint32_t su = smem_u32(smem);
    const int dir = blockIdx.z;
    const __half* Ah = &g_xth[dir][0];
    const __half* Bh = &g_wx[dir][0];
    float* C   = &g_dbl[dir][0];
    __half* dH = &g_dt_h[dir][0];
    __half* dL = &g_dt_l[dir][0];

    const int bm = blockIdx.y * 64;
    const int tid  = threadIdx.x;
    const int wid  = tid >> 5;
    const int lane = tid & 31;

    const int prow = tid >> 3;
    const int pkc  = tid & 7;
    auto issue = [&](int c) {
        const uint32_t sb = su + (uint32_t)(c & 1) * XP_STAGE;
        const int k0 = c * 64;
#pragma unroll
        for (int i = 0; i < 2; ++i) {
            const int row = prow + i * 32;
            const uint32_t off = sw128((uint32_t)(row * 128 + pkc * 16));
            const size_t ga = (size_t)(bm + row) * CDI + k0 + pkc * 8;
            cp16(sb + off, Ah + ga);
        }
#pragma unroll
        for (int i = 0; i < 4; ++i) {
            const int row = prow + i * 32;
            const uint32_t off = sw128((uint32_t)(row * 128 + pkc * 16));
            const size_t gb = (size_t)row * CDI + k0 + pkc * 8;
            cp16(sb + 16384 + off, Bh + gb);
        }
        asm volatile("cp.async.commit_group;" ::: "memory");
    };

    const int m0 = (wid & 1) * 32;
    const int n0 = (wid >> 1) * 32;
    const int g    = lane >> 3;
    const int lr   = lane & 7;
    const int lrow = (g & 1) * 8 + lr;
    const int lkb  = (g >> 1) * 16;

    float acc[2][4][4] = {};

    issue(0); issue(1);

    const int NC = CDI / 64;
    for (int c = 0; c < NC; ++c) {
        asm volatile("cp.async.wait_group 1;" ::: "memory");
        __syncthreads();
        const uint32_t sb = su + (uint32_t)(c & 1) * XP_STAGE;
#pragma unroll
        for (int kk = 0; kk < 4; ++kk) {
            uint32_t ah[2][4];
#pragma unroll
            for (int mt = 0; mt < 2; ++mt) {
                uint32_t off = sw128((uint32_t)((m0 + mt*16 + lrow) * 128 + kk*32 + lkb));
                ldsm4(sb + off, ah[mt]);
            }
#pragma unroll
            for (int np = 0; np < 2; ++np) {
                uint32_t boff = sw128((uint32_t)((n0 + np*16 + lrow) * 128 + kk*32 + lkb));
                uint32_t bh[4];
                ldsm4(sb + 16384 + boff, bh);
#pragma unroll
                for (int mt = 0; mt < 2; ++mt) {
                    mma_f16(acc[mt][2*np],   ah[mt], bh[0], bh[2]);
                    mma_f16(acc[mt][2*np+1], ah[mt], bh[1], bh[3]);
                }
            }
        }
        __syncthreads();
        if (c + 2 < NC) issue(c + 2);
        else asm volatile("cp.async.commit_group;" ::: "memory");
    }

    const int er = lane >> 2;
    const int ec = (lane & 3) * 2;
#pragma unroll
    for (int mt = 0; mt < 2; ++mt) {
#pragma unroll
        for (int nt = 0; nt < 4; ++nt) {
            const int row0 = bm + m0 + mt*16 + er;
            const int col  = n0 + nt*8 + ec;
#pragma unroll
            for (int rr = 0; rr < 2; ++rr) {
                const int row = row0 + rr*8;
#pragma unroll
                for (int e = 0; e < 2; ++e) {
                    const int cc = col + e;
                    const float v = acc[mt][nt][rr*2+e];
                    if (cc < CRP) {
                        float dv = (cc < CR) ? v : 0.f;
                        __half hb = __float2half_rn(dv);
                        dH[(size_t)row * CRP + cc] = hb;
                        dL[(size_t)row * CRP + cc] =
                            __float2half_rn(dv - __half2float(hb));
                    }
                    if (cc >= CR && cc < CPROJ)
                        C[(size_t)row * CPROJ + cc] = v;
                }
            }
        }
    }
}

// ---------------------------------------------------------------------------
// dtproj tensor GEMM: delta[row,d] = softplus(sum_r dt[row,r]*W[d,r] + bias[d])
// ---------------------------------------------------------------------------
__device__ __forceinline__ float softplus_f(float v) {
    return (v > 20.f) ? v : log1pf(__expf(v));
}

__global__ void __launch_bounds__(256) dtgemm_kernel(
    const float* __restrict__ bias_f, const float* __restrict__ bias_b)
{
    extern __shared__ __align__(1024) char smem[];
    const uint32_t su = smem_u32(smem);
    const int dir = blockIdx.z;
    const __half* Ah = &g_dt_h[dir][0];
    const __half* Al = &g_dt_l[dir][0];
    const __half* Bh = &g_wdt_h[dir][0];
    const __half* Bl = &g_wdt_l[dir][0];
    const float* bias = dir ? bias_b : bias_f;
    float* C = &g_delta[dir][0];

    const int bm = blockIdx.y * 128;
    const int bn = blockIdx.x * 128;
    const int tid  = threadIdx.x;
    const int wid  = tid >> 5;
    const int lane = tid & 31;

    const int prow = tid >> 3;
    const int pkc  = tid & 7;
#pragma unroll
    for (int i = 0; i < 4; ++i) {
        const int row = prow + i * 32;
        const uint32_t off = sw128((uint32_t)(row * 128 + pkc * 16));
        const size_t ga = (size_t)(bm + row) * CRP + pkc * 8;
        const size_t gb = (size_t)(bn + row) * CRP + pkc * 8;
        cp16(su + off,         Ah + ga);
        cp16(su + 16384 + off, Al + ga);
        cp16(su + 32768 + off, Bh + gb);
        cp16(su + 49152 + off, Bl + gb);
    }
    asm volatile("cp.async.commit_group;" ::: "memory");
    asm volatile("cp.async.wait_group 0;" ::: "memory");
    __syncthreads();

    const int m0 = (wid & 3) * 32;
    const int n0 = (wid >> 2) * 64;
    const int g    = lane >> 3;
    const int lr   = lane & 7;
    const int lrow = (g & 1) * 8 + lr;
    const int lkb  = (g >> 1) * 16;

    float acc[2][8][4] = {};
#pragma unroll
    for (int kk = 0; kk < 4; ++kk) {
        uint32_t ah[2][4], al[2][4];
#pragma unroll
        for (int mt = 0; mt < 2; ++mt) {
            uint32_t off = sw128((uint32_t)((m0 + mt*16 + lrow) * 128 + kk*32 + lkb));
            ldsm4(su + off,         ah[mt]);
            ldsm4(su + 16384 + off, al[mt]);
        }
#pragma unroll
        for (int np = 0; np < 4; ++np) {
            uint32_t boff = sw128((uint32_t)((n0 + np*16 + lrow) * 128 + kk*32 + lkb));
            uint32_t bh[4], bl[4];
            ldsm4(su + 32768 + boff, bh);
            ldsm4(su + 49152 + boff, bl);
#pragma unroll
            for (int mt = 0; mt < 2; ++mt) {
                mma_f16(acc[mt][2*np],   ah[mt], bh[0], bh[2]);
                mma_f16(acc[mt][2*np],   al[mt], bh[0], bh[2]);
                mma_f16(acc[mt][2*np],   ah[mt], bl[0], bl[2]);
                mma_f16(acc[mt][2*np+1], ah[mt], bh[1], bh[3]);
                mma_f16(acc[mt][2*np+1], al[mt], bh[1], bh[3]);
                mma_f16(acc[mt][2*np+1], ah[mt], bl[1], bl[3]);
            }
        }
    }

    const int er = lane >> 2;
    const int ec = (lane & 3) * 2;
#pragma unroll
    for (int mt = 0; mt < 2; ++mt) {
#pragma unroll
        for (int nt = 0; nt < 8; ++nt) {
            const int row = bm + m0 + mt*16 + er;
            const int col = bn + n0 + nt*8 + ec;
            const float b0 = bias[col], b1 = bias[col+1];
            float2 lo = { softplus_f(acc[mt][nt][0] + b0),
                          softplus_f(acc[mt][nt][1] + b1) };
            float2 hi = { softplus_f(acc[mt][nt][2] + b0),
                          softplus_f(acc[mt][nt][3] + b1) };
            *(float2*)(C + (size_t)row * CDI + col)       = lo;
            *(float2*)(C + (size_t)(row + 8) * CDI + col) = hi;
        }
    }
}

// ---------------------------------------------------------------------------
// fp32 -> fp16 hi/lo splitter and single-fp16 converter (grid-stride, float4)
// ---------------------------------------------------------------------------
__global__ void split2_kernel(const float* __restrict__ s,
                              __half* __restrict__ h, __half* __restrict__ l, int n4)
{
    for (int i = blockIdx.x * blockDim.x + threadIdx.x; i < n4;
         i += gridDim.x * blockDim.x) {
        float4 v = ((const float4*)s)[i];
        __half hx = __float2half_rn(v.x), hy = __float2half_rn(v.y);
        __half hz = __float2half_rn(v.z), hw = __float2half_rn(v.w);
        __half lx = __float2half_rn(v.x - __half2float(hx));
        __half ly = __float2half_rn(v.y - __half2float(hy));
        __half lz = __float2half_rn(v.z - __half2float(hz));
        __half lw = __float2half_rn(v.w - __half2float(hw));
        __half2 h01 = __halves2half2(hx, hy), h23 = __halves2half2(hz, hw);
        __half2 l01 = __halves2half2(lx, ly), l23 = __halves2half2(lz, lw);
        ((uint2*)h)[i] = make_uint2(*(uint32_t*)&h01, *(uint32_t*)&h23);
        ((uint2*)l)[i] = make_uint2(*(uint32_t*)&l01, *(uint32_t*)&l23);
    }
}

__global__ void tof16_kernel(const float* __restrict__ s, __half* __restrict__ h, int n4)
{
    for (int i = blockIdx.x * blockDim.x + threadIdx.x; i < n4;
         i += gridDim.x * blockDim.x) {
        float4 v = ((const float4*)s)[i];
        __half2 h01 = __halves2half2(__float2half_rn(v.x), __float2half_rn(v.y));
        __half2 h23 = __halves2half2(__float2half_rn(v.z), __float2half_rn(v.w));
        ((uint2*)h)[i] = make_uint2(*(uint32_t*)&h01, *(uint32_t*)&h23);
    }
}

// xproj weights: pad 80 -> 128 rows (zeros), single fp16, both dirs.
__global__ void padw_kernel(const float* __restrict__ wf, const float* __restrict__ wb)
{
    const int total4 = 2 * 128 * CDI / 4;
    for (int i = blockIdx.x * blockDim.x + threadIdx.x; i < total4;
         i += gridDim.x * blockDim.x) {
        int e = i * 4;
        int dir = e / (128 * CDI);
        int rem = e - dir * 128 * CDI;
        int row = rem / CDI;
        int k   = rem - row * CDI;
        float4 v = {0.f, 0.f, 0.f, 0.f};
        const float* W = dir ? wb : wf;
        if (row < CPROJ) v = *(const float4*)(W + (size_t)row * CDI + k);
        __half2 h01 = __halves2half2(__float2half_rn(v.x), __float2half_rn(v.y));
        __half2 h23 = __halves2half2(__float2half_rn(v.z), __float2half_rn(v.w));
        ((uint2*)&g_wx[0][0])[i] = make_uint2(*(uint32_t*)&h01, *(uint32_t*)&h23);
    }
}

// dtproj weights: pad K 48 -> 64 (zeros), split to fp16 hi/lo, both dirs.
__global__ void padwd_kernel(const float* __restrict__ wf, const float* __restrict__ wb)
{
    const int total4 = 2 * CDI * CRP / 4;
    for (int i = blockIdx.x * blockDim.x + threadIdx.x; i < total4;
         i += gridDim.x * blockDim.x) {
        int e = i * 4;
        int dir = e / (CDI * CRP);
        int rem = e - dir * CDI * CRP;
        int row = rem / CRP;
        int k   = rem - row * CRP;
        float4 v = {0.f, 0.f, 0.f, 0.f};
        const float* W = dir ? wb : wf;
        if (k < CR) v = *(const float4*)(W + (size_t)row * CR + k);
        __half hx = __float2half_rn(v.x), hy = __float2half_rn(v.y);
        __half hz = __float2half_rn(v.z), hw = __float2half_rn(v.w);
        __half lx = __float2half_rn(v.x - __half2float(hx));
        __half ly = __float2half_rn(v.y - __half2float(hy));
        __half lz = __float2half_rn(v.z - __half2float(hz));
        __half lw = __float2half_rn(v.w - __half2float(hw));
        __half2 h01 = __halves2half2(hx, hy), h23 = __halves2half2(hz, hw);
        __half2 l01 = __halves2half2(lx, ly), l23 = __halves2half2(lz, lw);
        ((uint2*)&g_wdt_h[0][0])[i] = make_uint2(*(uint32_t*)&h01, *(uint32_t*)&h23);
        ((uint2*)&g_wdt_l[0][0])[i] = make_uint2(*(uint32_t*)&l01, *(uint32_t*)&l23);
    }
}

// ---------------------------------------------------------------------------
// Depthwise causal conv (K=4) + bias + SiLU, transpose to (b,t,d).
// MERGED DIRECTIONS: one block loads x[t0-3 .. t0+130] once, emits both dirs.
// ---------------------------------------------------------------------------
__global__ void __launch_bounds__(256) conv_silu_kernel(
    const float* __restrict__ cw_f, const float* __restrict__ cb_f,
    const float* __restrict__ cw_b, const float* __restrict__ cb_b)
{
    const int t0 = blockIdx.x * 128;
    const int d0 = blockIdx.y * 32;
    const int b  = blockIdx.z;

    __shared__ float xs[32][135];

    const float* xbase = g_xz + ((size_t)b * (2*CDI) + d0) * CL;
    const int base = t0 - 3;

    const int lane = threadIdx.x & 31;
    const int wy   = threadIdx.x >> 5;
    for (int d = wy; d < 32; d += 8) {
        const float* row = xbase + (size_t)d * CL;
        for (int i = lane; i < 134; i += 32) {
            int u = base + i;
            xs[d][i] = (u >= 0 && u < CL) ? row[u] : 0.f;
        }
    }
    __syncthreads();

    const int d  = threadIdx.x & 31;
    const int sg = threadIdx.x >> 5;
    const float wf0 = cw_f[(d0+d)*CK + 0];
    const float wf1 = cw_f[(d0+d)*CK + 1];
    const float wf2 = cw_f[(d0+d)*CK + 2];
    const float wf3 = cw_f[(d0+d)*CK + 3];
    const float bf  = cb_f[d0+d];
    const float wb0 = cw_b[(d0+d)*CK + 0];
    const float wb1 = cw_b[(d0+d)*CK + 1];
    const float wb2 = cw_b[(d0+d)*CK + 2];
    const float wb3 = cw_b[(d0+d)*CK + 3];
    const float bb  = cb_b[d0+d];

    __half* ohf = g_xth[0] + (size_t)b * CL * CDI;
    __half* olf = g_xtl[0] + (size_t)b * CL * CDI;
    __half* ohb = g_xth[1] + (size_t)b * CL * CDI;
    __half* olb = g_xtl[1] + (size_t)b * CL * CDI;
    const int tb0 = CL - 128 - t0;
#pragma unroll
    for (int q = 0; q < 16; ++q) {
        int s = sg + 8*q;
        {
            float v = wf0*xs[d][s] + wf1*xs[d][s+1] + wf2*xs[d][s+2] + wf3*xs[d][s+3] + bf;
            float sv = v / (1.f + __expf(-v));
            size_t idx = (size_t)(t0 + s) * CDI + d0 + d;
            __half hb = __float2half_rn(sv);
            ohf[idx] = hb;
            olf[idx] = __float2half_rn(sv - __half2float(hb));
        }
        {
            float v = wb3*xs[d][130-s] + wb2*xs[d][131-s] + wb1*xs[d][132-s]
                    + wb0*xs[d][133-s] + bb;
            float sv = v / (1.f + __expf(-v));
            size_t idx = (size_t)(tb0 + s) * CDI + d0 + d;
            __half hb = __float2half_rn(sv);
            ohb[idx] = hb;
            olb[idx] = __float2half_rn(sv - __half2float(hb));
        }
    }
}

// ---------------------------------------------------------------------------
// Selective scan, 2-states-per-lane layout (round-11 winner).
// ---------------------------------------------------------------------------
__global__ void __launch_bounds__(128) scan_kernel(
    const float* __restrict__ Alog_f, const float* __restrict__ Dv_f,
    const float* __restrict__ Alog_b, const float* __restrict__ Dv_b)
{
    const int dir = blockIdx.z;
    const int b   = blockIdx.y;
    const int d0  = blockIdx.x * 16;

    const float* Alog = dir ? Alog_b : Alog_f;
    const float* Dvec = dir ? Dv_b   : Dv_f;
    const float* delta = g_delta[dir] + (size_t)b * CL * CDI;
    const __half* xth  = g_xth[dir]   + (size_t)b * CL * CDI;
    const __half* xtl  = g_xtl[dir]   + (size_t)b * CL * CDI;
    const float* dbl   = g_dbl[dir]   + (size_t)b * CL * CPROJ;
    float* yout        = g_y[dir]     + (size_t)b * CL * CDI;

    __shared__ __align__(16) float sd[64][16];   // dt
    __shared__ __align__(16) float sx[64][16];   // dt*x
    __shared__ __align__(16) float sB[64][16];
    __shared__ __align__(16) float sC[64][16];
    __shared__ __align__(16) float sxD[64][16];  // x*D

    const int tid  = threadIdx.x;
    const int lane = tid & 31;
    const int wid  = tid >> 5;
    const int ch   = wid*4 + (lane >> 3);
    const int n    = lane & 7;
    const int d    = d0 + ch;

    constexpr float LOG2E = 1.4426950408889634f;
    const float Aval0 = -__expf(Alog[d*CN + n])     * LOG2E;
    const float Aval1 = -__expf(Alog[d*CN + n + 8]) * LOG2E;
    float h0 = 0.f, h1 = 0.f;

    const int li = tid >> 1;
    const int lj = (tid & 1) * 8;

    float rDv[8];
#pragma unroll
    for (int j = 0; j < 8; ++j) rDv[j] = Dvec[d0 + lj + j];

    float rd[8], rx[8], rB[8], rC[8];
    auto LD = [&](int t0) {
        float4 d0v = *(const float4*)(delta + (size_t)(t0+li)*CDI + d0 + lj);
        float4 d1v = *(const float4*)(delta + (size_t)(t0+li)*CDI + d0 + lj + 4);
        rd[0]=d0v.x; rd[1]=d0v.y; rd[2]=d0v.z; rd[3]=d0v.w;
        rd[4]=d1v.x; rd[5]=d1v.y; rd[6]=d1v.z; rd[7]=d1v.w;
        uint4 xh = *(const uint4*)(xth + (size_t)(t0+li)*CDI + d0 + lj);
        uint4 xl = *(const uint4*)(xtl + (size_t)(t0+li)*CDI + d0 + lj);
        const uint32_t* xhp = &xh.x;
        const uint32_t* xlp = &xl.x;
#pragma unroll
        for (int q = 0; q < 4; ++q) {
            float2 fh = __half22float2(*(const __half2*)&xhp[q]);
            float2 fl = __half22float2(*(const __half2*)&xlp[q]);
            rx[2*q+0] = fh.x + fl.x;
            rx[2*q+1] = fh.y + fl.y;
        }
        float4 b0v = *(const float4*)(dbl + (size_t)(t0+li)*CPROJ + CR + lj);
        float4 b1v = *(const float4*)(dbl + (size_t)(t0+li)*CPROJ + CR + lj + 4);
        rB[0]=b0v.x; rB[1]=b0v.y; rB[2]=b0v.z; rB[3]=b0v.w;
        rB[4]=b1v.x; rB[5]=b1v.y; rB[6]=b1v.z; rB[7]=b1v.w;
        float4 c0v = *(const float4*)(dbl + (size_t)(t0+li)*CPROJ + CR + CN + lj);
        float4 c1v = *(const float4*)(dbl + (size_t)(t0+li)*CPROJ + CR + CN + lj + 4);
        rC[0]=c0v.x; rC[1]=c0v.y; rC[2]=c0v.z; rC[3]=c0v.w;
        rC[4]=c1v.x; rC[5]=c1v.y; rC[6]=c1v.z; rC[7]=c1v.w;
    };
    LD(0);

    const int NCH = CL / 64;
    for (int c = 0; c < NCH; ++c) {
        __syncthreads();
        {
            float4 v;
            v = make_float4(rd[0], rd[1], rd[2], rd[3]);            *(float4*)&sd[li][lj]   = v;
            v = make_float4(rd[4], rd[5], rd[6], rd[7]);            *(float4*)&sd[li][lj+4] = v;
            v = make_float4(rd[0]*rx[0], rd[1]*rx[1], rd[2]*rx[2], rd[3]*rx[3]); *(float4*)&sx[li][lj]   = v;
            v = make_float4(rd[4]*rx[4], rd[5]*rx[5], rd[6]*rx[6], rd[7]*rx[7]); *(float4*)&sx[li][lj+4] = v;
            v = make_float4(rB[0], rB[1], rB[2], rB[3]);            *(float4*)&sB[li][lj]   = v;
            v = make_float4(rB[4], rB[5], rB[6], rB[7]);            *(float4*)&sB[li][lj+4] = v;
            v = make_float4(rC[0], rC[1], rC[2], rC[3]);            *(float4*)&sC[li][lj]   = v;
            v = make_float4(rC[4], rC[5], rC[6], rC[7]);            *(float4*)&sC[li][lj+4] = v;
            v = make_float4(rx[0]*rDv[0], rx[1]*rDv[1], rx[2]*rDv[2], rx[3]*rDv[3]); *(float4*)&sxD[li][lj]   = v;
            v = make_float4(rx[4]*rDv[4], rx[5]*rDv[5], rx[6]*rDv[6], rx[7]*rDv[7]); *(float4*)&sxD[li][lj+4] = v;
        }
        __syncthreads();
        if (c + 1 < NCH) LD((c+1) * 64);

        const int tbase = c * 64;
#pragma unroll 8
        for (int s = 0; s < 64; ++s) {
            float dt  = sd[s][ch];
            float dtx = sx[s][ch];
            float B0 = sB[s][n],     C0 = sC[s][n];
            float B1 = sB[s][n + 8], C1 = sC[s][n + 8];
            float a0 = ex2f(dt * Aval0);
            float a1 = ex2f(dt * Aval1);
            h0 = fmaf(a0, h0, dtx * B0);
            h1 = fmaf(a1, h1, dtx * B1);
            float p = fmaf(h1, C1, h0 * C0);
            p += __shfl_xor_sync(0xffffffffu, p, 4);
            p += __shfl_xor_sync(0xffffffffu, p, 2);
            p += __shfl_xor_sync(0xffffffffu, p, 1);
            if (n == 0)
                yout[(size_t)(tbase + s)*CDI + d] = p + sxD[s][ch];
        }
    }
}

// ---------------------------------------------------------------------------
// Gate + direction merge -> single fp16 comb (out_proj 1-term operand)
// ---------------------------------------------------------------------------
__global__ void __launch_bounds__(256) combine_kernel()
{
    const int l0 = blockIdx.x * 32;
    const int d0 = blockIdx.y * 32;
    const int b  = blockIdx.z;

    __shared__ float zs[32][33];
    const int lane = threadIdx.x & 31;
    const int wy   = threadIdx.x >> 5;

    const float* zbase = g_xz + ((size_t)b * (2*CDI) + CDI + d0) * CL;
    for (int dd = wy; dd < 32; dd += 8)
        zs[dd][lane] = zbase[(size_t)dd * CL + l0 + lane];
    __syncthreads();

#pragma unroll
    for (int q = 0; q < 4; ++q) {
        int lr = wy + 8*q;
        int l = l0 + lr;
        size_t idx  = ((size_t)b*CL + l)*CDI + d0 + lane;
        size_t idxr = ((size_t)b*CL + (CL-1-l))*CDI + d0 + lane;
        float yf = g_y[0][idx];
        float yb = g_y[1][idxr];
        float zv = zs[lane][lr];
        float s = zv / (1.f + __expf(-zv));
        float cv = (yf + yb) * s;
        g_cmb_h[idx] = __float2half_rn(cv);
    }
}

// ---------------------------------------------------------------------------
// Launcher
// ---------------------------------------------------------------------------
extern "C" void kernel_launch(void* const* d_in, const int* in_sizes, int n_in,
                              void* d_out, int out_size)
{
    (void)in_sizes; (void)n_in; (void)out_size;

    const float* hidden  = (const float*)d_in[0];
    const float* in_w    = (const float*)d_in[1];
    const float* conv_w  = (const float*)d_in[2];
    const float* conv_b  = (const float*)d_in[3];
    const float* xproj_w = (const float*)d_in[4];
    const float* dtw     = (const float*)d_in[5];
    const float* dtb     = (const float*)d_in[6];
    const float* A_log   = (const float*)d_in[7];
    const float* Dv      = (const float*)d_in[8];
    const float* conv_w2 = (const float*)d_in[9];
    const float* conv_b2 = (const float*)d_in[10];
    const float* xproj_w2= (const float*)d_in[11];
    const float* dtw2    = (const float*)d_in[12];
    const float* dtb2    = (const float*)d_in[13];
    const float* A_log2  = (const float*)d_in[14];
    const float* Dv2     = (const float*)d_in[15];
    const float* out_w   = (const float*)d_in[16];

    void *p_xz;
    void *p_hid_h, *p_hid_l, *p_w1, *p_w2, *p_cmb_h;
    cudaGetSymbolAddress(&p_xz, g_xz);
    cudaGetSymbolAddress(&p_hid_h, g_hid_h);
    cudaGetSymbolAddress(&p_hid_l, g_hid_l);
    cudaGetSymbolAddress(&p_w1, g_w1);
    cudaGetSymbolAddress(&p_w2, g_w2);
    cudaGetSymbolAddress(&p_cmb_h, g_cmb_h);

    cudaFuncSetAttribute(gemm_f16_kernel<0>,
                         cudaFuncAttributeMaxDynamicSharedMemorySize, GF_SMEM);
    cudaFuncSetAttribute(gemm_f16_kernel<2>,
                         cudaFuncAttributeMaxDynamicSharedMemorySize, GF_SMEM);
    cudaFuncSetAttribute(xproj_kernel,
                         cudaFuncAttributeMaxDynamicSharedMemorySize, XP_SMEM);
    cudaFuncSetAttribute(dtgemm_kernel,
                         cudaFuncAttributeMaxDynamicSharedMemorySize, 65536);

    // 0) operand packing
    split2_kernel<<<1024, 256>>>(hidden, (__half*)p_hid_h, (__half*)p_hid_l, CB*CL*CDM/4);
    tof16_kernel<<<512, 256>>>(in_w, (__half*)p_w1, 2*CDI*CDM/4);
    tof16_kernel<<<512, 256>>>(out_w, (__half*)p_w2, CDM*CDI/4);
    padw_kernel<<<512, 256>>>(xproj_w, xproj_w2);
    padwd_kernel<<<192, 256>>>(dtw, dtw2);

    // 1) in_proj: A = w1 (single), B = hidden (split); lo-term only for the
    //    x rows (e < CDI). z rows (gate-only) take fp16 quantization.
    gemm_f16_kernel<0><<<dim3(CL/128, (2*CDI)/128, CB), 256, GF_SMEM>>>(
        (const __half*)p_w1, (const __half*)p_hid_l, (const __half*)p_hid_h,
        (float*)p_xz, CL, CDM,
        0, (long long)CL * CDM, (long long)(2*CDI) * CL, CDM / 64, CDI);

    // 2) conv + SiLU + transpose (both dirs per block) -> fp16 hi/lo xt
    conv_silu_kernel<<<dim3(CL/128, CDI/32, CB), 256>>>(
        conv_w, conv_b, conv_w2, conv_b2);

    // 3) xproj, M=64 tiles, 1-term: dt fp16 hi/lo + fp32 B|C
    xproj_kernel<<<dim3(1, (CB*CL)/64, 2), 256, XP_SMEM>>>();

    // 4) dtproj as tensor GEMM + softplus -> delta
    dtgemm_kernel<<<dim3(CDI/128, (CB*CL)/128, 2), 256, 65536>>>(dtb, dtb2);

    // 5) selective scan (2-states-per-lane, 128-thread CTAs)
    scan_kernel<<<dim3(CDI/16, CB, 2), 128>>>(A_log, Dv, A_log2, Dv2);

    // 6) gate + direction merge -> single fp16 comb
    combine_kernel<<<dim3(CL/32, CDI/32, CB), 256>>>();

    // 7) out_proj, 1-term: A = comb (single fp16), B = w2 (single fp16).
    gemm_f16_kernel<2><<<dim3(CDM/128, (CB*CL)/128, 1), 256, GF_SMEM>>>(
        (const __half*)p_cmb_h, (const __half*)p_cmb_h, (const __half*)p_w2,
        (float*)d_out, CDM, CDI,
        0, 0, 0, CDI / 64, 0);
}

// round 14
// speedup vs baseline: 1.4681x; 1.1034x over previous
#include <cuda_runtime.h>
#include <cuda_fp16.h>
#include <cstdint>

// Problem constants
constexpr int CB  = 2;     // batch
constexpr int CL  = 4096;  // seq len
constexpr int CDM = 768;   // d_model
constexpr int CDI = 1536;  // d_inner
constexpr int CN  = 16;    // state dim
constexpr int CR  = 48;    // dt rank
constexpr int CK  = 4;     // conv width
constexpr int CPROJ = CR + 2*CN; // 80
constexpr int CRP = 64;    // dt rank padded for MMA K

// ---------------------------------------------------------------------------
// Scratch (device globals; no runtime allocation allowed)
// ---------------------------------------------------------------------------
__device__ float g_xz[CB * 2 * CDI * CL];        // (b, e, l)
__device__ float g_dbl[2][CB * CL * CPROJ];      // per dir, (b*L, 80): only B|C cols used
__device__ float g_delta[2][CB * CL * CDI];      // per dir, post-softplus
__device__ float g_y[2][CB * CL * CDI];          // per dir, scan out (+D*x)

// fp16 operands for tensor GEMMs
__device__ __half g_hid_h[CB*CL*CDM];                       // hidden, single fp16
__device__ __half g_w1[2*CDI*CDM];                          // in_proj W (single)
__device__ __half g_w2[CDM*CDI];                            // out_proj W (single)
__device__ __half g_wx[2][128*CDI];                         // xproj W padded 80->128 (single)
__device__ __half g_xth[2][CB*CL*CDI], g_xtl[2][CB*CL*CDI]; // conv out hi/lo (scan uses both)
__device__ __half g_cmb_h[CB*CL*CDI];                       // gated sum, single fp16
__device__ __half g_dt_h[2][CB*CL*CRP], g_dt_l[2][CB*CL*CRP]; // dt rows padded 48->64, hi/lo
__device__ __half g_wdt_h[2][CDI*CRP],  g_wdt_l[2][CDI*CRP];  // dtproj W padded, hi/lo

// ---------------------------------------------------------------------------
// PTX helpers
// ---------------------------------------------------------------------------
__device__ __forceinline__ uint32_t smem_u32(const void* p) {
    uint32_t a;
    asm("{ .reg .u64 t; cvta.to.shared.u64 t, %1; cvt.u32.u64 %0, t; }" : "=r"(a) : "l"(p));
    return a;
}
__device__ __forceinline__ uint32_t sw128(uint32_t b) { return b ^ ((b >> 3) & 0x70); }

__device__ __forceinline__ void ldsm4(uint32_t addr, uint32_t r[4]) {
    asm volatile("ldmatrix.sync.aligned.m8n8.x4.shared.b16 {%0,%1,%2,%3}, [%4];"
        : "=r"(r[0]), "=r"(r[1]), "=r"(r[2]), "=r"(r[3]) : "r"(addr));
}
__device__ __forceinline__ void mma_f16(float* d, const uint32_t* a, uint32_t b0, uint32_t b1) {
    asm volatile("mma.sync.aligned.m16n8k16.row.col.f32.f16.f16.f32 "
        "{%0,%1,%2,%3}, {%4,%5,%6,%7}, {%8,%9}, {%0,%1,%2,%3};"
        : "+f"(d[0]), "+f"(d[1]), "+f"(d[2]), "+f"(d[3])
        : "r"(a[0]), "r"(a[1]), "r"(a[2]), "r"(a[3]), "r"(b0), "r"(b1));
}
__device__ __forceinline__ void cp16(uint32_t s, const void* g) {
    asm volatile("cp.async.ca.shared.global [%0], [%1], 16;" :: "r"(s), "l"(g));
}
__device__ __forceinline__ float ex2f(float x) {
    float r;
    asm("ex2.approx.f32 %0, %1;" : "=f"(r) : "f"(x));
    return r;
}

// ---------------------------------------------------------------------------
// fp16 tensor GEMM (M=128 tile), 1-term:  C[m,n] = sum_k A[m,k]*B[n,k]
// Both operands single fp16. CTA tile 128x128, BK=64, 2-stage cp.async ring.
// Stage: Ah 16K @0 | Bh 16K @32768 (middle slot unused; layout kept stable).
// ---------------------------------------------------------------------------
constexpr int GF_STAGE = 49152;
constexpr int GF_SMEM  = 2 * GF_STAGE;   // 98304 B

__global__ void __launch_bounds__(256, 2) gemm_f16_kernel(
    const __half* __restrict__ Ah, const __half* __restrict__ Bh,
    float* __restrict__ C, int Nout, int Kd,
    long long strideA, long long strideB, long long strideC, int NC)
{
    extern __shared__ __align__(1024) char smem[];
    const uint32_t su = smem_u32(smem);
    Ah += (size_t)blockIdx.z * strideA;
    Bh += (size_t)blockIdx.z * strideB;
    C  += (size_t)blockIdx.z * strideC;
    const int bm = blockIdx.y * 128;
    const int bn = blockIdx.x * 128;
    const int tid  = threadIdx.x;
    const int wid  = tid >> 5;
    const int lane = tid & 31;

    const int prow = tid >> 3;
    const int pkc  = tid & 7;
    auto issue = [&](int c) {
        const uint32_t sb = su + (uint32_t)(c & 1) * GF_STAGE;
        const int k0 = c * 64;
#pragma unroll
        for (int i = 0; i < 4; ++i) {
            const int row = prow + i * 32;
            const uint32_t off = sw128((uint32_t)(row * 128 + pkc * 16));
            const size_t ga = (size_t)(bm + row) * Kd + k0 + pkc * 8;
            const size_t gb = (size_t)(bn + row) * Kd + k0 + pkc * 8;
            cp16(sb + off,         Ah + ga);
            cp16(sb + 32768 + off, Bh + gb);
        }
        asm volatile("cp.async.commit_group;" ::: "memory");
    };

    const int m0 = (wid & 3) * 32;
    const int n0 = (wid >> 2) * 64;
    const int g    = lane >> 3;
    const int lr   = lane & 7;
    const int lrow = (g & 1) * 8 + lr;
    const int lkb  = (g >> 1) * 16;

    float acc[2][8][4] = {};

    issue(0); issue(1);

    for (int c = 0; c < NC; ++c) {
        asm volatile("cp.async.wait_group 1;" ::: "memory");
        __syncthreads();
        const uint32_t sb = su + (uint32_t)(c & 1) * GF_STAGE;
#pragma unroll
        for (int kk = 0; kk < 4; ++kk) {
            uint32_t ah[2][4];
#pragma unroll
            for (int mt = 0; mt < 2; ++mt) {
                uint32_t off = sw128((uint32_t)((m0 + mt*16 + lrow) * 128 + kk*32 + lkb));
                ldsm4(sb + off, ah[mt]);
            }
#pragma unroll
            for (int np = 0; np < 4; ++np) {
                uint32_t boff = sw128((uint32_t)((n0 + np*16 + lrow) * 128 + kk*32 + lkb));
                uint32_t bh[4];
                ldsm4(sb + 32768 + boff, bh);
#pragma unroll
                for (int mt = 0; mt < 2; ++mt) {
                    mma_f16(acc[mt][2*np],   ah[mt], bh[0], bh[2]);
                    mma_f16(acc[mt][2*np+1], ah[mt], bh[1], bh[3]);
                }
            }
        }
        __syncthreads();
        if (c + 2 < NC) issue(c + 2);
        else asm volatile("cp.async.commit_group;" ::: "memory");
    }

    const int er = lane >> 2;
    const int ec = (lane & 3) * 2;
#pragma unroll
    for (int mt = 0; mt < 2; ++mt) {
#pragma unroll
        for (int nt = 0; nt < 8; ++nt) {
            const int row = bm + m0 + mt*16 + er;
            const int col = bn + n0 + nt*8 + ec;
            if (col < Nout) {
                float2 lo = { acc[mt][nt][0], acc[mt][nt][1] };
                float2 hi = { acc[mt][nt][2], acc[mt][nt][3] };
                *(float2*)(C + (size_t)row * Nout + col)       = lo;
                *(float2*)(C + (size_t)(row + 8) * Nout + col) = hi;
            }
        }
    }
}

// ---------------------------------------------------------------------------
// xproj tensor GEMM, M=64 CTA tile, 1-term (xt-hi only).
// ---------------------------------------------------------------------------
constexpr int XP_STAGE = 32768;
constexpr int XP_SMEM  = 2 * XP_STAGE;   // 65536 B

__global__ void __launch_bounds__(256, 2) xproj_kernel()
{
    extern __shared__ __align__(1024) char smem[];
    const uint32_t su = smem_u32(smem);
    const int dir = blockIdx.z;
    const __half* Ah = &g_xth[dir][0];
    const __half* Bh = &g_wx[dir][0];
    float* C   = &g_dbl[dir][0];
    __half* dH = &g_dt_h[dir][0];
    __half* dL = &g_dt_l[dir][0];

    const int bm = blockIdx.y * 64;
    const int tid  = threadIdx.x;
    const int wid  = tid >> 5;
    const int lane = tid & 31;

    const int prow = tid >> 3;
    const int pkc  = tid & 7;
    auto issue = [&](int c) {
        const uint32_t sb = su + (uint32_t)(c & 1) * XP_STAGE;
        const int k0 = c * 64;
#pragma unroll
        for (int i = 0; i < 2; ++i) {
            const int row = prow + i * 32;
            const uint32_t off = sw128((uint32_t)(row * 128 + pkc * 16));
            const size_t ga = (size_t)(bm + row) * CDI + k0 + pkc * 8;
            cp16(sb + off, Ah + ga);
        }
#pragma unroll
        for (int i = 0; i < 4; ++i) {
            const int row = prow + i * 32;
            const uint32_t off = sw128((uint32_t)(row * 128 + pkc * 16));
            const size_t gb = (size_t)row * CDI + k0 + pkc * 8;
            cp16(sb + 16384 + off, Bh + gb);
        }
        asm volatile("cp.async.commit_group;" ::: "memory");
    };

    const int m0 = (wid & 1) * 32;
    const int n0 = (wid >> 1) * 32;
    const int g    = lane >> 3;
    const int lr   = lane & 7;
    const int lrow = (g & 1) * 8 + lr;
    const int lkb  = (g >> 1) * 16;

    float acc[2][4][4] = {};

    issue(0); issue(1);

    const int NC = CDI / 64;
    for (int c = 0; c < NC; ++c) {
        asm volatile("cp.async.wait_group 1;" ::: "memory");
        __syncthreads();
        const uint32_t sb = su + (uint32_t)(c & 1) * XP_STAGE;
#pragma unroll
        for (int kk = 0; kk < 4; ++kk) {
            uint32_t ah[2][4];
#pragma unroll
            for (int mt = 0; mt < 2; ++mt) {
                uint32_t off = sw128((uint32_t)((m0 + mt*16 + lrow) * 128 + kk*32 + lkb));
                ldsm4(sb + off, ah[mt]);
            }
#pragma unroll
            for (int np = 0; np < 2; ++np) {
                uint32_t boff = sw128((uint32_t)((n0 + np*16 + lrow) * 128 + kk*32 + lkb));
                uint32_t bh[4];
                ldsm4(sb + 16384 + boff, bh);
#pragma unroll
                for (int mt = 0; mt < 2; ++mt) {
                    mma_f16(acc[mt][2*np],   ah[mt], bh[0], bh[2]);
                    mma_f16(acc[mt][2*np+1], ah[mt], bh[1], bh[3]);
                }
            }
        }
        __syncthreads();
        if (c + 2 < NC) issue(c + 2);
        else asm volatile("cp.async.commit_group;" ::: "memory");
    }

    const int er = lane >> 2;
    const int ec = (lane & 3) * 2;
#pragma unroll
    for (int mt = 0; mt < 2; ++mt) {
#pragma unroll
        for (int nt = 0; nt < 4; ++nt) {
            const int row0 = bm + m0 + mt*16 + er;
            const int col  = n0 + nt*8 + ec;
#pragma unroll
            for (int rr = 0; rr < 2; ++rr) {
                const int row = row0 + rr*8;
#pragma unroll
                for (int e = 0; e < 2; ++e) {
                    const int cc = col + e;
                    const float v = acc[mt][nt][rr*2+e];
                    if (cc < CRP) {
                        float dv = (cc < CR) ? v : 0.f;
                        __half hb = __float2half_rn(dv);
                        dH[(size_t)row * CRP + cc] = hb;
                        dL[(size_t)row * CRP + cc] =
                            __float2half_rn(dv - __half2float(hb));
                    }
                    if (cc >= CR && cc < CPROJ)
                        C[(size_t)row * CPROJ + cc] = v;
                }
            }
        }
    }
}

// ---------------------------------------------------------------------------
// dtproj tensor GEMM: delta[row,d] = softplus(sum_r dt[row,r]*W[d,r] + bias[d])
// ---------------------------------------------------------------------------
__device__ __forceinline__ float softplus_f(float v) {
    return (v > 20.f) ? v : log1pf(__expf(v));
}

__global__ void __launch_bounds__(256) dtgemm_kernel(
    const float* __restrict__ bias_f, const float* __restrict__ bias_b)
{
    extern __shared__ __align__(1024) char smem[];
    const uint32_t su = smem_u32(smem);
    const int dir = blockIdx.z;
    const __half* Ah = &g_dt_h[dir][0];
    const __half* Al = &g_dt_l[dir][0];
    const __half* Bh = &g_wdt_h[dir][0];
    const __half* Bl = &g_wdt_l[dir][0];
    const float* bias = dir ? bias_b : bias_f;
    float* C = &g_delta[dir][0];

    const int bm = blockIdx.y * 128;
    const int bn = blockIdx.x * 128;
    const int tid  = threadIdx.x;
    const int wid  = tid >> 5;
    const int lane = tid & 31;

    const int prow = tid >> 3;
    const int pkc  = tid & 7;
#pragma unroll
    for (int i = 0; i < 4; ++i) {
        const int row = prow + i * 32;
        const uint32_t off = sw128((uint32_t)(row * 128 + pkc * 16));
        const size_t ga = (size_t)(bm + row) * CRP + pkc * 8;
        const size_t gb = (size_t)(bn + row) * CRP + pkc * 8;
        cp16(su + off,         Ah + ga);
        cp16(su + 16384 + off, Al + ga);
        cp16(su + 32768 + off, Bh + gb);
        cp16(su + 49152 + off, Bl + gb);
    }
    asm volatile("cp.async.commit_group;" ::: "memory");
    asm volatile("cp.async.wait_group 0;" ::: "memory");
    __syncthreads();

    const int m0 = (wid & 3) * 32;
    const int n0 = (wid >> 2) * 64;
    const int g    = lane >> 3;
    const int lr   = lane & 7;
    const int lrow = (g & 1) * 8 + lr;
    const int lkb  = (g >> 1) * 16;

    float acc[2][8][4] = {};
#pragma unroll
    for (int kk = 0; kk < 4; ++kk) {
        uint32_t ah[2][4], al[2][4];
#pragma unroll
        for (int mt = 0; mt < 2; ++mt) {
            uint32_t off = sw128((uint32_t)((m0 + mt*16 + lrow) * 128 + kk*32 + lkb));
            ldsm4(su + off,         ah[mt]);
            ldsm4(su + 16384 + off, al[mt]);
        }
#pragma unroll
        for (int np = 0; np < 4; ++np) {
            uint32_t boff = sw128((uint32_t)((n0 + np*16 + lrow) * 128 + kk*32 + lkb));
            uint32_t bh[4], bl[4];
            ldsm4(su + 32768 + boff, bh);
            ldsm4(su + 49152 + boff, bl);
#pragma unroll
            for (int mt = 0; mt < 2; ++mt) {
                mma_f16(acc[mt][2*np],   ah[mt], bh[0], bh[2]);
                mma_f16(acc[mt][2*np],   al[mt], bh[0], bh[2]);
                mma_f16(acc[mt][2*np],   ah[mt], bl[0], bl[2]);
                mma_f16(acc[mt][2*np+1], ah[mt], bh[1], bh[3]);
                mma_f16(acc[mt][2*np+1], al[mt], bh[1], bh[3]);
                mma_f16(acc[mt][2*np+1], ah[mt], bl[1], bl[3]);
            }
        }
    }

    const int er = lane >> 2;
    const int ec = (lane & 3) * 2;
#pragma unroll
    for (int mt = 0; mt < 2; ++mt) {
#pragma unroll
        for (int nt = 0; nt < 8; ++nt) {
            const int row = bm + m0 + mt*16 + er;
            const int col = bn + n0 + nt*8 + ec;
            const float b0 = bias[col], b1 = bias[col+1];
            float2 lo = { softplus_f(acc[mt][nt][0] + b0),
                          softplus_f(acc[mt][nt][1] + b1) };
            float2 hi = { softplus_f(acc[mt][nt][2] + b0),
                          softplus_f(acc[mt][nt][3] + b1) };
            *(float2*)(C + (size_t)row * CDI + col)       = lo;
            *(float2*)(C + (size_t)(row + 8) * CDI + col) = hi;
        }
    }
}

// ---------------------------------------------------------------------------
// Fused operand packer (single launch):
//   R0: hidden -> g_hid_h (single fp16)
//   R1: in_w   -> g_w1
//   R2: out_w  -> g_w2
//   R3: xproj W pad 80->128 rows -> g_wx (both dirs)
//   R4: dtproj W pad K 48->64, split hi/lo -> g_wdt_h/l (both dirs)
// All ranges in float4 units.
// ---------------------------------------------------------------------------
constexpr int PK_R0 = CB*CL*CDM/4;            // 1,572,864
constexpr int PK_R1 = PK_R0 + 2*CDI*CDM/4;    // + 589,824
constexpr int PK_R2 = PK_R1 + CDM*CDI/4;      // + 294,912
constexpr int PK_R3 = PK_R2 + 2*128*CDI/4;    // +  98,304
constexpr int PK_R4 = PK_R3 + 2*CDI*CRP/4;    // +  49,152

__device__ __forceinline__ uint2 pack4_f16(float4 v) {
    __half2 h01 = __halves2half2(__float2half_rn(v.x), __float2half_rn(v.y));
    __half2 h23 = __halves2half2(__float2half_rn(v.z), __float2half_rn(v.w));
    return make_uint2(*(uint32_t*)&h01, *(uint32_t*)&h23);
}

__global__ void pack_kernel(
    const float* __restrict__ hidden, const float* __restrict__ in_w,
    const float* __restrict__ out_w,
    const float* __restrict__ xw_f, const float* __restrict__ xw_b,
    const float* __restrict__ dw_f, const float* __restrict__ dw_b)
{
    for (int i = blockIdx.x * blockDim.x + threadIdx.x; i < PK_R4;
         i += gridDim.x * blockDim.x) {
        if (i < PK_R0) {
            ((uint2*)g_hid_h)[i] = pack4_f16(((const float4*)hidden)[i]);
        } else if (i < PK_R1) {
            int j = i - PK_R0;
            ((uint2*)g_w1)[j] = pack4_f16(((const float4*)in_w)[j]);
        } else if (i < PK_R2) {
            int j = i - PK_R1;
            ((uint2*)g_w2)[j] = pack4_f16(((const float4*)out_w)[j]);
        } else if (i < PK_R3) {
            int j = i - PK_R2;
            int e = j * 4;
            int dir = e / (128 * CDI);
            int rem = e - dir * 128 * CDI;
            int row = rem / CDI;
            int k   = rem - row * CDI;
            float4 v = {0.f, 0.f, 0.f, 0.f};
            const float* W = dir ? xw_b : xw_f;
            if (row < CPROJ) v = *(const float4*)(W + (size_t)row * CDI + k);
            ((uint2*)&g_wx[0][0])[j] = pack4_f16(v);
        } else {
            int j = i - PK_R3;
            int e = j * 4;
            int dir = e / (CDI * CRP);
            int rem = e - dir * CDI * CRP;
            int row = rem / CRP;
            int k   = rem - row * CRP;
            float4 v = {0.f, 0.f, 0.f, 0.f};
            const float* W = dir ? dw_b : dw_f;
            if (k < CR) v = *(const float4*)(W + (size_t)row * CR + k);
            __half hx = __float2half_rn(v.x), hy = __float2half_rn(v.y);
            __half hz = __float2half_rn(v.z), hw = __float2half_rn(v.w);
            __half lx = __float2half_rn(v.x - __half2float(hx));
            __half ly = __float2half_rn(v.y - __half2float(hy));
            __half lz = __float2half_rn(v.z - __half2float(hz));
            __half lw = __float2half_rn(v.w - __half2float(hw));
            __half2 h01 = __halves2half2(hx, hy), h23 = __halves2half2(hz, hw);
            __half2 l01 = __halves2half2(lx, ly), l23 = __halves2half2(lz, lw);
            ((uint2*)&g_wdt_h[0][0])[j] = make_uint2(*(uint32_t*)&h01, *(uint32_t*)&h23);
            ((uint2*)&g_wdt_l[0][0])[j] = make_uint2(*(uint32_t*)&l01, *(uint32_t*)&l23);
        }
    }
}

// ---------------------------------------------------------------------------
// Depthwise causal conv (K=4) + bias + SiLU, transpose to (b,t,d).
// MERGED DIRECTIONS: one block loads x[t0-3 .. t0+130] once, emits both dirs.
// ---------------------------------------------------------------------------
__global__ void __launch_bounds__(256) conv_silu_kernel(
    const float* __restrict__ cw_f, const float* __restrict__ cb_f,
    const float* __restrict__ cw_b, const float* __restrict__ cb_b)
{
    const int t0 = blockIdx.x * 128;
    const int d0 = blockIdx.y * 32;
    const int b  = blockIdx.z;

    __shared__ float xs[32][135];

    const float* xbase = g_xz + ((size_t)b * (2*CDI) + d0) * CL;
    const int base = t0 - 3;

    const int lane = threadIdx.x & 31;
    const int wy   = threadIdx.x >> 5;
    for (int d = wy; d < 32; d += 8) {
        const float* row = xbase + (size_t)d * CL;
        for (int i = lane; i < 134; i += 32) {
            int u = base + i;
            xs[d][i] = (u >= 0 && u < CL) ? row[u] : 0.f;
        }
    }
    __syncthreads();

    const int d  = threadIdx.x & 31;
    const int sg = threadIdx.x >> 5;
    const float wf0 = cw_f[(d0+d)*CK + 0];
    const float wf1 = cw_f[(d0+d)*CK + 1];
    const float wf2 = cw_f[(d0+d)*CK + 2];
    const float wf3 = cw_f[(d0+d)*CK + 3];
    const float bf  = cb_f[d0+d];
    const float wb0 = cw_b[(d0+d)*CK + 0];
    const float wb1 = cw_b[(d0+d)*CK + 1];
    const float wb2 = cw_b[(d0+d)*CK + 2];
    const float wb3 = cw_b[(d0+d)*CK + 3];
    const float bb  = cb_b[d0+d];

    __half* ohf = g_xth[0] + (size_t)b * CL * CDI;
    __half* olf = g_xtl[0] + (size_t)b * CL * CDI;
    __half* ohb = g_xth[1] + (size_t)b * CL * CDI;
    __half* olb = g_xtl[1] + (size_t)b * CL * CDI;
    const int tb0 = CL - 128 - t0;
#pragma unroll
    for (int q = 0; q < 16; ++q) {
        int s = sg + 8*q;
        {
            float v = wf0*xs[d][s] + wf1*xs[d][s+1] + wf2*xs[d][s+2] + wf3*xs[d][s+3] + bf;
            float sv = v / (1.f + __expf(-v));
            size_t idx = (size_t)(t0 + s) * CDI + d0 + d;
            __half hb = __float2half_rn(sv);
            ohf[idx] = hb;
            olf[idx] = __float2half_rn(sv - __half2float(hb));
        }
        {
            float v = wb3*xs[d][130-s] + wb2*xs[d][131-s] + wb1*xs[d][132-s]
                    + wb0*xs[d][133-s] + bb;
            float sv = v / (1.f + __expf(-v));
            size_t idx = (size_t)(tb0 + s) * CDI + d0 + d;
            __half hb = __float2half_rn(sv);
            ohb[idx] = hb;
            olb[idx] = __float2half_rn(sv - __half2float(hb));
        }
    }
}

// ---------------------------------------------------------------------------
// Selective scan, 2-states-per-lane layout (round-11 winner).
// ---------------------------------------------------------------------------
__global__ void __launch_bounds__(128) scan_kernel(
    const float* __restrict__ Alog_f, const float* __restrict__ Dv_f,
    const float* __restrict__ Alog_b, const float* __restrict__ Dv_b)
{
    const int dir = blockIdx.z;
    const int b   = blockIdx.y;
    const int d0  = blockIdx.x * 16;

    const float* Alog = dir ? Alog_b : Alog_f;
    const float* Dvec = dir ? Dv_b   : Dv_f;
    const float* delta = g_delta[dir] + (size_t)b * CL * CDI;
    const __half* xth  = g_xth[dir]   + (size_t)b * CL * CDI;
    const __half* xtl  = g_xtl[dir]   + (size_t)b * CL * CDI;
    const float* dbl   = g_dbl[dir]   + (size_t)b * CL * CPROJ;
    float* yout        = g_y[dir]     + (size_t)b * CL * CDI;

    __shared__ __align__(16) float sd[64][16];   // dt
    __shared__ __align__(16) float sx[64][16];   // dt*x
    __shared__ __align__(16) float sB[64][16];
    __shared__ __align__(16) float sC[64][16];
    __shared__ __align__(16) float sxD[64][16];  // x*D

    const int tid  = threadIdx.x;
    const int lane = tid & 31;
    const int wid  = tid >> 5;
    const int ch   = wid*4 + (lane >> 3);
    const int n    = lane & 7;
    const int d    = d0 + ch;

    constexpr float LOG2E = 1.4426950408889634f;
    const float Aval0 = -__expf(Alog[d*CN + n])     * LOG2E;
    const float Aval1 = -__expf(Alog[d*CN + n + 8]) * LOG2E;
    float h0 = 0.f, h1 = 0.f;

    const int li = tid >> 1;
    const int lj = (tid & 1) * 8;

    float rDv[8];
#pragma unroll
    for (int j = 0; j < 8; ++j) rDv[j] = Dvec[d0 + lj + j];

    float rd[8], rx[8], rB[8], rC[8];
    auto LD = [&](int t0) {
        float4 d0v = *(const float4*)(delta + (size_t)(t0+li)*CDI + d0 + lj);
        float4 d1v = *(const float4*)(delta + (size_t)(t0+li)*CDI + d0 + lj + 4);
        rd[0]=d0v.x; rd[1]=d0v.y; rd[2]=d0v.z; rd[3]=d0v.w;
        rd[4]=d1v.x; rd[5]=d1v.y; rd[6]=d1v.z; rd[7]=d1v.w;
        uint4 xh = *(const uint4*)(xth + (size_t)(t0+li)*CDI + d0 + lj);
        uint4 xl = *(const uint4*)(xtl + (size_t)(t0+li)*CDI + d0 + lj);
        const uint32_t* xhp = &xh.x;
        const uint32_t* xlp = &xl.x;
#pragma unroll
        for (int q = 0; q < 4; ++q) {
            float2 fh = __half22float2(*(const __half2*)&xhp[q]);
            float2 fl = __half22float2(*(const __half2*)&xlp[q]);
            rx[2*q+0] = fh.x + fl.x;
            rx[2*q+1] = fh.y + fl.y;
        }
        float4 b0v = *(const float4*)(dbl + (size_t)(t0+li)*CPROJ + CR + lj);
        float4 b1v = *(const float4*)(dbl + (size_t)(t0+li)*CPROJ + CR + lj + 4);
        rB[0]=b0v.x; rB[1]=b0v.y; rB[2]=b0v.z; rB[3]=b0v.w;
        rB[4]=b1v.x; rB[5]=b1v.y; rB[6]=b1v.z; rB[7]=b1v.w;
        float4 c0v = *(const float4*)(dbl + (size_t)(t0+li)*CPROJ + CR + CN + lj);
        float4 c1v = *(const float4*)(dbl + (size_t)(t0+li)*CPROJ + CR + CN + lj + 4);
        rC[0]=c0v.x; rC[1]=c0v.y; rC[2]=c0v.z; rC[3]=c0v.w;
        rC[4]=c1v.x; rC[5]=c1v.y; rC[6]=c1v.z; rC[7]=c1v.w;
    };
    LD(0);

    const int NCH = CL / 64;
    for (int c = 0; c < NCH; ++c) {
        __syncthreads();
        {
            float4 v;
            v = make_float4(rd[0], rd[1], rd[2], rd[3]);            *(float4*)&sd[li][lj]   = v;
            v = make_float4(rd[4], rd[5], rd[6], rd[7]);            *(float4*)&sd[li][lj+4] = v;
            v = make_float4(rd[0]*rx[0], rd[1]*rx[1], rd[2]*rx[2], rd[3]*rx[3]); *(float4*)&sx[li][lj]   = v;
            v = make_float4(rd[4]*rx[4], rd[5]*rx[5], rd[6]*rx[6], rd[7]*rx[7]); *(float4*)&sx[li][lj+4] = v;
            v = make_float4(rB[0], rB[1], rB[2], rB[3]);            *(float4*)&sB[li][lj]   = v;
            v = make_float4(rB[4], rB[5], rB[6], rB[7]);            *(float4*)&sB[li][lj+4] = v;
            v = make_float4(rC[0], rC[1], rC[2], rC[3]);            *(float4*)&sC[li][lj]   = v;
            v = make_float4(rC[4], rC[5], rC[6], rC[7]);            *(float4*)&sC[li][lj+4] = v;
            v = make_float4(rx[0]*rDv[0], rx[1]*rDv[1], rx[2]*rDv[2], rx[3]*rDv[3]); *(float4*)&sxD[li][lj]   = v;
            v = make_float4(rx[4]*rDv[4], rx[5]*rDv[5], rx[6]*rDv[6], rx[7]*rDv[7]); *(float4*)&sxD[li][lj+4] = v;
        }
        __syncthreads();
        if (c + 1 < NCH) LD((c+1) * 64);

        const int tbase = c * 64;
#pragma unroll 8
        for (int s = 0; s < 64; ++s) {
            float dt  = sd[s][ch];
            float dtx = sx[s][ch];
            float B0 = sB[s][n],     C0 = sC[s][n];
            float B1 = sB[s][n + 8], C1 = sC[s][n + 8];
            float a0 = ex2f(dt * Aval0);
            float a1 = ex2f(dt * Aval1);
            h0 = fmaf(a0, h0, dtx * B0);
            h1 = fmaf(a1, h1, dtx * B1);
            float p = fmaf(h1, C1, h0 * C0);
            p += __shfl_xor_sync(0xffffffffu, p, 4);
            p += __shfl_xor_sync(0xffffffffu, p, 2);
            p += __shfl_xor_sync(0xffffffffu, p, 1);
            if (n == 0)
                yout[(size_t)(tbase + s)*CDI + d] = p + sxD[s][ch];
        }
    }
}

// ---------------------------------------------------------------------------
// Gate + direction merge -> single fp16 comb (out_proj 1-term operand)
// ---------------------------------------------------------------------------
__global__ void __launch_bounds__(256) combine_kernel()
{
    const int l0 = blockIdx.x * 32;
    const int d0 = blockIdx.y * 32;
    const int b  = blockIdx.z;

    __shared__ float zs[32][33];
    const int lane = threadIdx.x & 31;
    const int wy   = threadIdx.x >> 5;

    const float* zbase = g_xz + ((size_t)b * (2*CDI) + CDI + d0) * CL;
    for (int dd = wy; dd < 32; dd += 8)
        zs[dd][lane] = zbase[(size_t)dd * CL + l0 + lane];
    __syncthreads();

#pragma unroll
    for (int q = 0; q < 4; ++q) {
        int lr = wy + 8*q;
        int l = l0 + lr;
        size_t idx  = ((size_t)b*CL + l)*CDI + d0 + lane;
        size_t idxr = ((size_t)b*CL + (CL-1-l))*CDI + d0 + lane;
        float yf = g_y[0][idx];
        float yb = g_y[1][idxr];
        float zv = zs[lane][lr];
        float s = zv / (1.f + __expf(-zv));
        float cv = (yf + yb) * s;
        g_cmb_h[idx] = __float2half_rn(cv);
    }
}

// ---------------------------------------------------------------------------
// Launcher
// ---------------------------------------------------------------------------
extern "C" void kernel_launch(void* const* d_in, const int* in_sizes, int n_in,
                              void* d_out, int out_size)
{
    (void)in_sizes; (void)n_in; (void)out_size;

    const float* hidden  = (const float*)d_in[0];
    const float* in_w    = (const float*)d_in[1];
    const float* conv_w  = (const float*)d_in[2];
    const float* conv_b  = (const float*)d_in[3];
    const float* xproj_w = (const float*)d_in[4];
    const float* dtw     = (const float*)d_in[5];
    const float* dtb     = (const float*)d_in[6];
    const float* A_log   = (const float*)d_in[7];
    const float* Dv      = (const float*)d_in[8];
    const float* conv_w2 = (const float*)d_in[9];
    const float* conv_b2 = (const float*)d_in[10];
    const float* xproj_w2= (const float*)d_in[11];
    const float* dtw2    = (const float*)d_in[12];
    const float* dtb2    = (const float*)d_in[13];
    const float* A_log2  = (const float*)d_in[14];
    const float* Dv2     = (const float*)d_in[15];
    const float* out_w   = (const float*)d_in[16];

    void *p_xz, *p_hid_h, *p_w1, *p_w2, *p_cmb_h;
    cudaGetSymbolAddress(&p_xz, g_xz);
    cudaGetSymbolAddress(&p_hid_h, g_hid_h);
    cudaGetSymbolAddress(&p_w1, g_w1);
    cudaGetSymbolAddress(&p_w2, g_w2);
    cudaGetSymbolAddress(&p_cmb_h, g_cmb_h);

    cudaFuncSetAttribute(gemm_f16_kernel,
                         cudaFuncAttributeMaxDynamicSharedMemorySize, GF_SMEM);
    cudaFuncSetAttribute(xproj_kernel,
                         cudaFuncAttributeMaxDynamicSharedMemorySize, XP_SMEM);
    cudaFuncSetAttribute(dtgemm_kernel,
                         cudaFuncAttributeMaxDynamicSharedMemorySize, 65536);

    // 0) fused operand packing (one launch)
    pack_kernel<<<2048, 256>>>(hidden, in_w, out_w, xproj_w, xproj_w2, dtw, dtw2);

    // 1) in_proj, 1-term: A = w1, B = hidden.  M=3072, N=4096, K=768
    gemm_f16_kernel<<<dim3(CL/128, (2*CDI)/128, CB), 256, GF_SMEM>>>(
        (const __half*)p_w1, (const __half*)p_hid_h,
        (float*)p_xz, CL, CDM,
        0, (long long)CL * CDM, (long long)(2*CDI) * CL, CDM / 64);

    // 2) conv + SiLU + transpose (both dirs per block) -> fp16 hi/lo xt
    conv_silu_kernel<<<dim3(CL/128, CDI/32, CB), 256>>>(
        conv_w, conv_b, conv_w2, conv_b2);

    // 3) xproj, M=64 tiles, 1-term: dt fp16 hi/lo + fp32 B|C
    xproj_kernel<<<dim3(1, (CB*CL)/64, 2), 256, XP_SMEM>>>();

    // 4) dtproj as tensor GEMM + softplus -> delta
    dtgemm_kernel<<<dim3(CDI/128, (CB*CL)/128, 2), 256, 65536>>>(dtb, dtb2);

    // 5) selective scan (2-states-per-lane, 128-thread CTAs)
    scan_kernel<<<dim3(CDI/16, CB, 2), 128>>>(A_log, Dv, A_log2, Dv2);

    // 6) gate + direction merge -> single fp16 comb
    combine_kernel<<<dim3(CL/32, CDI/32, CB), 256>>>();

    // 7) out_proj, 1-term: A = comb, B = w2.  M=8192, N=768, K=1536
    gemm_f16_kernel<<<dim3(CDM/128, (CB*CL)/128, 1), 256, GF_SMEM>>>(
        (const __half*)p_cmb_h, (const __half*)p_w2,
        (float*)d_out, CDM, CDI,
        0, 0, 0, CDI / 64);
}

// round 15
// speedup vs baseline: 1.5139x; 1.0312x over previous
#include <cuda_runtime.h>
#include <cuda_fp16.h>
#include <cstdint>

// Problem constants
constexpr int CB  = 2;     // batch
constexpr int CL  = 4096;  // seq len
constexpr int CDM = 768;   // d_model
constexpr int CDI = 1536;  // d_inner
constexpr int CN  = 16;    // state dim
constexpr int CR  = 48;    // dt rank
constexpr int CK  = 4;     // conv width
constexpr int CPROJ = CR + 2*CN; // 80
constexpr int CRP = 64;    // dt rank padded for MMA K

// ---------------------------------------------------------------------------
// Scratch (device globals; no runtime allocation allowed)
// ---------------------------------------------------------------------------
__device__ __half g_xz[CB * 2 * CDI * CL];       // (b, e, l), fp16
__device__ float g_dbl[2][CB * CL * CPROJ];      // per dir, (b*L, 80): only B|C cols used
__device__ __half g_delta[2][CB * CL * CDI];     // per dir, post-softplus, fp16
__device__ float g_y[2][CB * CL * CDI];          // per dir, scan out (+D*x)

// fp16 operands for tensor GEMMs
__device__ __half g_hid_h[CB*CL*CDM];                       // hidden, single fp16
__device__ __half g_w1[2*CDI*CDM];                          // in_proj W (single)
__device__ __half g_w2[CDM*CDI];                            // out_proj W (single)
__device__ __half g_wx[2][128*CDI];                         // xproj W padded 80->128 (single)
__device__ __half g_xth[2][CB*CL*CDI], g_xtl[2][CB*CL*CDI]; // conv out hi/lo (scan uses both)
__device__ __half g_cmb_h[CB*CL*CDI];                       // gated sum, single fp16
__device__ __half g_dt_h[2][CB*CL*CRP], g_dt_l[2][CB*CL*CRP]; // dt rows padded 48->64, hi/lo
__device__ __half g_wdt_h[2][CDI*CRP],  g_wdt_l[2][CDI*CRP];  // dtproj W padded, hi/lo

// ---------------------------------------------------------------------------
// PTX helpers
// ---------------------------------------------------------------------------
__device__ __forceinline__ uint32_t smem_u32(const void* p) {
    uint32_t a;
    asm("{ .reg .u64 t; cvta.to.shared.u64 t, %1; cvt.u32.u64 %0, t; }" : "=r"(a) : "l"(p));
    return a;
}
__device__ __forceinline__ uint32_t sw128(uint32_t b) { return b ^ ((b >> 3) & 0x70); }

__device__ __forceinline__ void ldsm4(uint32_t addr, uint32_t r[4]) {
    asm volatile("ldmatrix.sync.aligned.m8n8.x4.shared.b16 {%0,%1,%2,%3}, [%4];"
        : "=r"(r[0]), "=r"(r[1]), "=r"(r[2]), "=r"(r[3]) : "r"(addr));
}
__device__ __forceinline__ void mma_f16(float* d, const uint32_t* a, uint32_t b0, uint32_t b1) {
    asm volatile("mma.sync.aligned.m16n8k16.row.col.f32.f16.f16.f32 "
        "{%0,%1,%2,%3}, {%4,%5,%6,%7}, {%8,%9}, {%0,%1,%2,%3};"
        : "+f"(d[0]), "+f"(d[1]), "+f"(d[2]), "+f"(d[3])
        : "r"(a[0]), "r"(a[1]), "r"(a[2]), "r"(a[3]), "r"(b0), "r"(b1));
}
__device__ __forceinline__ void cp16(uint32_t s, const void* g) {
    asm volatile("cp.async.ca.shared.global [%0], [%1], 16;" :: "r"(s), "l"(g));
}
__device__ __forceinline__ float ex2f(float x) {
    float r;
    asm("ex2.approx.f32 %0, %1;" : "=f"(r) : "f"(x));
    return r;
}

// ---------------------------------------------------------------------------
// fp16 tensor GEMM (M=128 tile), 1-term:  C[m,n] = sum_k A[m,k]*B[n,k]
// OUT16=1: store fp16 (__half) output; OUT16=0: fp32 output.
// CTA tile 128x128, BK=64, 2-stage cp.async ring, 96KB smem -> 2 CTA/SM.
// ---------------------------------------------------------------------------
constexpr int GF_STAGE = 49152;
constexpr int GF_SMEM  = 2 * GF_STAGE;   // 98304 B

template <int OUT16>
__global__ void __launch_bounds__(256, 2) gemm_f16_kernel(
    const __half* __restrict__ Ah, const __half* __restrict__ Bh,
    void* __restrict__ Cv, int Nout, int Kd,
    long long strideA, long long strideB, long long strideC, int NC)
{
    extern __shared__ __align__(1024) char smem[];
    const uint32_t su = smem_u32(smem);
    Ah += (size_t)blockIdx.z * strideA;
    Bh += (size_t)blockIdx.z * strideB;
    const int bm = blockIdx.y * 128;
    const int bn = blockIdx.x * 128;
    const int tid  = threadIdx.x;
    const int wid  = tid >> 5;
    const int lane = tid & 31;

    const int prow = tid >> 3;
    const int pkc  = tid & 7;
    auto issue = [&](int c) {
        const uint32_t sb = su + (uint32_t)(c & 1) * GF_STAGE;
        const int k0 = c * 64;
#pragma unroll
        for (int i = 0; i < 4; ++i) {
            const int row = prow + i * 32;
            const uint32_t off = sw128((uint32_t)(row * 128 + pkc * 16));
            const size_t ga = (size_t)(bm + row) * Kd + k0 + pkc * 8;
            const size_t gb = (size_t)(bn + row) * Kd + k0 + pkc * 8;
            cp16(sb + off,         Ah + ga);
            cp16(sb + 32768 + off, Bh + gb);
        }
        asm volatile("cp.async.commit_group;" ::: "memory");
    };

    const int m0 = (wid & 3) * 32;
    const int n0 = (wid >> 2) * 64;
    const int g    = lane >> 3;
    const int lr   = lane & 7;
    const int lrow = (g & 1) * 8 + lr;
    const int lkb  = (g >> 1) * 16;

    float acc[2][8][4] = {};

    issue(0); issue(1);

    for (int c = 0; c < NC; ++c) {
        asm volatile("cp.async.wait_group 1;" ::: "memory");
        __syncthreads();
        const uint32_t sb = su + (uint32_t)(c & 1) * GF_STAGE;
#pragma unroll
        for (int kk = 0; kk < 4; ++kk) {
            uint32_t ah[2][4];
#pragma unroll
            for (int mt = 0; mt < 2; ++mt) {
                uint32_t off = sw128((uint32_t)((m0 + mt*16 + lrow) * 128 + kk*32 + lkb));
                ldsm4(sb + off, ah[mt]);
            }
#pragma unroll
            for (int np = 0; np < 4; ++np) {
                uint32_t boff = sw128((uint32_t)((n0 + np*16 + lrow) * 128 + kk*32 + lkb));
                uint32_t bh[4];
                ldsm4(sb + 32768 + boff, bh);
#pragma unroll
                for (int mt = 0; mt < 2; ++mt) {
                    mma_f16(acc[mt][2*np],   ah[mt], bh[0], bh[2]);
                    mma_f16(acc[mt][2*np+1], ah[mt], bh[1], bh[3]);
                }
            }
        }
        __syncthreads();
        if (c + 2 < NC) issue(c + 2);
        else asm volatile("cp.async.commit_group;" ::: "memory");
    }

    const int er = lane >> 2;
    const int ec = (lane & 3) * 2;
#pragma unroll
    for (int mt = 0; mt < 2; ++mt) {
#pragma unroll
        for (int nt = 0; nt < 8; ++nt) {
            const int row = bm + m0 + mt*16 + er;
            const int col = bn + n0 + nt*8 + ec;
            if (col < Nout) {
                if (OUT16) {
                    __half* C = (__half*)Cv + (size_t)blockIdx.z * strideC;
                    __half2 lo = __halves2half2(__float2half_rn(acc[mt][nt][0]),
                                                __float2half_rn(acc[mt][nt][1]));
                    __half2 hi = __halves2half2(__float2half_rn(acc[mt][nt][2]),
                                                __float2half_rn(acc[mt][nt][3]));
                    *(__half2*)(C + (size_t)row * Nout + col)       = lo;
                    *(__half2*)(C + (size_t)(row + 8) * Nout + col) = hi;
                } else {
                    float* C = (float*)Cv + (size_t)blockIdx.z * strideC;
                    float2 lo = { acc[mt][nt][0], acc[mt][nt][1] };
                    float2 hi = { acc[mt][nt][2], acc[mt][nt][3] };
                    *(float2*)(C + (size_t)row * Nout + col)       = lo;
                    *(float2*)(C + (size_t)(row + 8) * Nout + col) = hi;
                }
            }
        }
    }
}

// ---------------------------------------------------------------------------
// xproj tensor GEMM, M=64 CTA tile, 1-term (xt-hi only).
// ---------------------------------------------------------------------------
constexpr int XP_STAGE = 32768;
constexpr int XP_SMEM  = 2 * XP_STAGE;   // 65536 B

__global__ void __launch_bounds__(256, 2) xproj_kernel()
{
    extern __shared__ __align__(1024) char smem[];
    const uint32_t su = smem_u32(smem);
    const int dir = blockIdx.z;
    const __half* Ah = &g_xth[dir][0];
    const __half* Bh = &g_wx[dir][0];
    float* C   = &g_dbl[dir][0];
    __half* dH = &g_dt_h[dir][0];
    __half* dL = &g_dt_l[dir][0];

    const int bm = blockIdx.y * 64;
    const int tid  = threadIdx.x;
    const int wid  = tid >> 5;
    const int lane = tid & 31;

    const int prow = tid >> 3;
    const int pkc  = tid & 7;
    auto issue = [&](int c) {
        const uint32_t sb = su + (uint32_t)(c & 1) * XP_STAGE;
        const int k0 = c * 64;
#pragma unroll
        for (int i = 0; i < 2; ++i) {
            const int row = prow + i * 32;
            const uint32_t off = sw128((uint32_t)(row * 128 + pkc * 16));
            const size_t ga = (size_t)(bm + row) * CDI + k0 + pkc * 8;
            cp16(sb + off, Ah + ga);
        }
#pragma unroll
        for (int i = 0; i < 4; ++i) {
            const int row = prow + i * 32;
            const uint32_t off = sw128((uint32_t)(row * 128 + pkc * 16));
            const size_t gb = (size_t)row * CDI + k0 + pkc * 8;
            cp16(sb + 16384 + off, Bh + gb);
        }
        asm volatile("cp.async.commit_group;" ::: "memory");
    };

    const int m0 = (wid & 1) * 32;
    const int n0 = (wid >> 1) * 32;
    const int g    = lane >> 3;
    const int lr   = lane & 7;
    const int lrow = (g & 1) * 8 + lr;
    const int lkb  = (g >> 1) * 16;

    float acc[2][4][4] = {};

    issue(0); issue(1);

    const int NC = CDI / 64;
    for (int c = 0; c < NC; ++c) {
        asm volatile("cp.async.wait_group 1;" ::: "memory");
        __syncthreads();
        const uint32_t sb = su + (uint32_t)(c & 1) * XP_STAGE;
#pragma unroll
        for (int kk = 0; kk < 4; ++kk) {
            uint32_t ah[2][4];
#pragma unroll
            for (int mt = 0; mt < 2; ++mt) {
                uint32_t off = sw128((uint32_t)((m0 + mt*16 + lrow) * 128 + kk*32 + lkb));
                ldsm4(sb + off, ah[mt]);
            }
#pragma unroll
            for (int np = 0; np < 2; ++np) {
                uint32_t boff = sw128((uint32_t)((n0 + np*16 + lrow) * 128 + kk*32 + lkb));
                uint32_t bh[4];
                ldsm4(sb + 16384 + boff, bh);
#pragma unroll
                for (int mt = 0; mt < 2; ++mt) {
                    mma_f16(acc[mt][2*np],   ah[mt], bh[0], bh[2]);
                    mma_f16(acc[mt][2*np+1], ah[mt], bh[1], bh[3]);
                }
            }
        }
        __syncthreads();
        if (c + 2 < NC) issue(c + 2);
        else asm volatile("cp.async.commit_group;" ::: "memory");
    }

    const int er = lane >> 2;
    const int ec = (lane & 3) * 2;
#pragma unroll
    for (int mt = 0; mt < 2; ++mt) {
#pragma unroll
        for (int nt = 0; nt < 4; ++nt) {
            const int row0 = bm + m0 + mt*16 + er;
            const int col  = n0 + nt*8 + ec;
#pragma unroll
            for (int rr = 0; rr < 2; ++rr) {
                const int row = row0 + rr*8;
#pragma unroll
                for (int e = 0; e < 2; ++e) {
                    const int cc = col + e;
                    const float v = acc[mt][nt][rr*2+e];
                    if (cc < CRP) {
                        float dv = (cc < CR) ? v : 0.f;
                        __half hb = __float2half_rn(dv);
                        dH[(size_t)row * CRP + cc] = hb;
                        dL[(size_t)row * CRP + cc] =
                            __float2half_rn(dv - __half2float(hb));
                    }
                    if (cc >= CR && cc < CPROJ)
                        C[(size_t)row * CPROJ + cc] = v;
                }
            }
        }
    }
}

// ---------------------------------------------------------------------------
// dtproj tensor GEMM: delta[row,d] = softplus(sum_r dt[row,r]*W[d,r] + bias[d])
// Output stored fp16.
// ---------------------------------------------------------------------------
__device__ __forceinline__ float softplus_f(float v) {
    return (v > 20.f) ? v : log1pf(__expf(v));
}

__global__ void __launch_bounds__(256) dtgemm_kernel(
    const float* __restrict__ bias_f, const float* __restrict__ bias_b)
{
    extern __shared__ __align__(1024) char smem[];
    const uint32_t su = smem_u32(smem);
    const int dir = blockIdx.z;
    const __half* Ah = &g_dt_h[dir][0];
    const __half* Al = &g_dt_l[dir][0];
    const __half* Bh = &g_wdt_h[dir][0];
    const __half* Bl = &g_wdt_l[dir][0];
    const float* bias = dir ? bias_b : bias_f;
    __half* C = &g_delta[dir][0];

    const int bm = blockIdx.y * 128;
    const int bn = blockIdx.x * 128;
    const int tid  = threadIdx.x;
    const int wid  = tid >> 5;
    const int lane = tid & 31;

    const int prow = tid >> 3;
    const int pkc  = tid & 7;
#pragma unroll
    for (int i = 0; i < 4; ++i) {
        const int row = prow + i * 32;
        const uint32_t off = sw128((uint32_t)(row * 128 + pkc * 16));
        const size_t ga = (size_t)(bm + row) * CRP + pkc * 8;
        const size_t gb = (size_t)(bn + row) * CRP + pkc * 8;
        cp16(su + off,         Ah + ga);
        cp16(su + 16384 + off, Al + ga);
        cp16(su + 32768 + off, Bh + gb);
        cp16(su + 49152 + off, Bl + gb);
    }
    asm volatile("cp.async.commit_group;" ::: "memory");
    asm volatile("cp.async.wait_group 0;" ::: "memory");
    __syncthreads();

    const int m0 = (wid & 3) * 32;
    const int n0 = (wid >> 2) * 64;
    const int g    = lane >> 3;
    const int lr   = lane & 7;
    const int lrow = (g & 1) * 8 + lr;
    const int lkb  = (g >> 1) * 16;

    float acc[2][8][4] = {};
#pragma unroll
    for (int kk = 0; kk < 4; ++kk) {
        uint32_t ah[2][4], al[2][4];
#pragma unroll
        for (int mt = 0; mt < 2; ++mt) {
            uint32_t off = sw128((uint32_t)((m0 + mt*16 + lrow) * 128 + kk*32 + lkb));
            ldsm4(su + off,         ah[mt]);
            ldsm4(su + 16384 + off, al[mt]);
        }
#pragma unroll
        for (int np = 0; np < 4; ++np) {
            uint32_t boff = sw128((uint32_t)((n0 + np*16 + lrow) * 128 + kk*32 + lkb));
            uint32_t bh[4], bl[4];
            ldsm4(su + 32768 + boff, bh);
            ldsm4(su + 49152 + boff, bl);
#pragma unroll
            for (int mt = 0; mt < 2; ++mt) {
                mma_f16(acc[mt][2*np],   ah[mt], bh[0], bh[2]);
                mma_f16(acc[mt][2*np],   al[mt], bh[0], bh[2]);
                mma_f16(acc[mt][2*np],   ah[mt], bl[0], bl[2]);
                mma_f16(acc[mt][2*np+1], ah[mt], bh[1], bh[3]);
                mma_f16(acc[mt][2*np+1], al[mt], bh[1], bh[3]);
                mma_f16(acc[mt][2*np+1], ah[mt], bl[1], bl[3]);
            }
        }
    }

    const int er = lane >> 2;
    const int ec = (lane & 3) * 2;
#pragma unroll
    for (int mt = 0; mt < 2; ++mt) {
#pragma unroll
        for (int nt = 0; nt < 8; ++nt) {
            const int row = bm + m0 + mt*16 + er;
            const int col = bn + n0 + nt*8 + ec;
            const float b0 = bias[col], b1 = bias[col+1];
            __half2 lo = __halves2half2(
                __float2half_rn(softplus_f(acc[mt][nt][0] + b0)),
                __float2half_rn(softplus_f(acc[mt][nt][1] + b1)));
            __half2 hi = __halves2half2(
                __float2half_rn(softplus_f(acc[mt][nt][2] + b0)),
                __float2half_rn(softplus_f(acc[mt][nt][3] + b1)));
            *(__half2*)(C + (size_t)row * CDI + col)       = lo;
            *(__half2*)(C + (size_t)(row + 8) * CDI + col) = hi;
        }
    }
}

// ---------------------------------------------------------------------------
// Fused operand packer (single launch)
// ---------------------------------------------------------------------------
constexpr int PK_R0 = CB*CL*CDM/4;
constexpr int PK_R1 = PK_R0 + 2*CDI*CDM/4;
constexpr int PK_R2 = PK_R1 + CDM*CDI/4;
constexpr int PK_R3 = PK_R2 + 2*128*CDI/4;
constexpr int PK_R4 = PK_R3 + 2*CDI*CRP/4;

__device__ __forceinline__ uint2 pack4_f16(float4 v) {
    __half2 h01 = __halves2half2(__float2half_rn(v.x), __float2half_rn(v.y));
    __half2 h23 = __halves2half2(__float2half_rn(v.z), __float2half_rn(v.w));
    return make_uint2(*(uint32_t*)&h01, *(uint32_t*)&h23);
}

__global__ void pack_kernel(
    const float* __restrict__ hidden, const float* __restrict__ in_w,
    const float* __restrict__ out_w,
    const float* __restrict__ xw_f, const float* __restrict__ xw_b,
    const float* __restrict__ dw_f, const float* __restrict__ dw_b)
{
    for (int i = blockIdx.x * blockDim.x + threadIdx.x; i < PK_R4;
         i += gridDim.x * blockDim.x) {
        if (i < PK_R0) {
            ((uint2*)g_hid_h)[i] = pack4_f16(((const float4*)hidden)[i]);
        } else if (i < PK_R1) {
            int j = i - PK_R0;
            ((uint2*)g_w1)[j] = pack4_f16(((const float4*)in_w)[j]);
        } else if (i < PK_R2) {
            int j = i - PK_R1;
            ((uint2*)g_w2)[j] = pack4_f16(((const float4*)out_w)[j]);
        } else if (i < PK_R3) {
            int j = i - PK_R2;
            int e = j * 4;
            int dir = e / (128 * CDI);
            int rem = e - dir * 128 * CDI;
            int row = rem / CDI;
            int k   = rem - row * CDI;
            float4 v = {0.f, 0.f, 0.f, 0.f};
            const float* W = dir ? xw_b : xw_f;
            if (row < CPROJ) v = *(const float4*)(W + (size_t)row * CDI + k);
            ((uint2*)&g_wx[0][0])[j] = pack4_f16(v);
        } else {
            int j = i - PK_R3;
            int e = j * 4;
            int dir = e / (CDI * CRP);
            int rem = e - dir * CDI * CRP;
            int row = rem / CRP;
            int k   = rem - row * CRP;
            float4 v = {0.f, 0.f, 0.f, 0.f};
            const float* W = dir ? dw_b : dw_f;
            if (k < CR) v = *(const float4*)(W + (size_t)row * CR + k);
            __half hx = __float2half_rn(v.x), hy = __float2half_rn(v.y);
            __half hz = __float2half_rn(v.z), hw = __float2half_rn(v.w);
            __half lx = __float2half_rn(v.x - __half2float(hx));
            __half ly = __float2half_rn(v.y - __half2float(hy));
            __half lz = __float2half_rn(v.z - __half2float(hz));
            __half lw = __float2half_rn(v.w - __half2float(hw));
            __half2 h01 = __halves2half2(hx, hy), h23 = __halves2half2(hz, hw);
            __half2 l01 = __halves2half2(lx, ly), l23 = __halves2half2(lz, lw);
            ((uint2*)&g_wdt_h[0][0])[j] = make_uint2(*(uint32_t*)&h01, *(uint32_t*)&h23);
            ((uint2*)&g_wdt_l[0][0])[j] = make_uint2(*(uint32_t*)&l01, *(uint32_t*)&l23);
        }
    }
}

// ---------------------------------------------------------------------------
// Depthwise causal conv (K=4) + bias + SiLU, transpose to (b,t,d).
// MERGED DIRECTIONS: one block loads x (fp16) once, emits both dirs.
// ---------------------------------------------------------------------------
__global__ void __launch_bounds__(256) conv_silu_kernel(
    const float* __restrict__ cw_f, const float* __restrict__ cb_f,
    const float* __restrict__ cw_b, const float* __restrict__ cb_b)
{
    const int t0 = blockIdx.x * 128;
    const int d0 = blockIdx.y * 32;
    const int b  = blockIdx.z;

    __shared__ float xs[32][135];

    const __half* xbase = g_xz + ((size_t)b * (2*CDI) + d0) * CL;
    const int base = t0 - 3;

    const int lane = threadIdx.x & 31;
    const int wy   = threadIdx.x >> 5;
    for (int d = wy; d < 32; d += 8) {
        const __half* row = xbase + (size_t)d * CL;
        for (int i = lane; i < 134; i += 32) {
            int u = base + i;
            xs[d][i] = (u >= 0 && u < CL) ? __half2float(row[u]) : 0.f;
        }
    }
    __syncthreads();

    const int d  = threadIdx.x & 31;
    const int sg = threadIdx.x >> 5;
    const float wf0 = cw_f[(d0+d)*CK + 0];
    const float wf1 = cw_f[(d0+d)*CK + 1];
    const float wf2 = cw_f[(d0+d)*CK + 2];
    const float wf3 = cw_f[(d0+d)*CK + 3];
    const float bf  = cb_f[d0+d];
    const float wb0 = cw_b[(d0+d)*CK + 0];
    const float wb1 = cw_b[(d0+d)*CK + 1];
    const float wb2 = cw_b[(d0+d)*CK + 2];
    const float wb3 = cw_b[(d0+d)*CK + 3];
    const float bb  = cb_b[d0+d];

    __half* ohf = g_xth[0] + (size_t)b * CL * CDI;
    __half* olf = g_xtl[0] + (size_t)b * CL * CDI;
    __half* ohb = g_xth[1] + (size_t)b * CL * CDI;
    __half* olb = g_xtl[1] + (size_t)b * CL * CDI;
    const int tb0 = CL - 128 - t0;
#pragma unroll
    for (int q = 0; q < 16; ++q) {
        int s = sg + 8*q;
        {
            float v = wf0*xs[d][s] + wf1*xs[d][s+1] + wf2*xs[d][s+2] + wf3*xs[d][s+3] + bf;
            float sv = v / (1.f + __expf(-v));
            size_t idx = (size_t)(t0 + s) * CDI + d0 + d;
            __half hb = __float2half_rn(sv);
            ohf[idx] = hb;
            olf[idx] = __float2half_rn(sv - __half2float(hb));
        }
        {
            float v = wb3*xs[d][130-s] + wb2*xs[d][131-s] + wb1*xs[d][132-s]
                    + wb0*xs[d][133-s] + bb;
            float sv = v / (1.f + __expf(-v));
            size_t idx = (size_t)(tb0 + s) * CDI + d0 + d;
            __half hb = __float2half_rn(sv);
            ohb[idx] = hb;
            olb[idx] = __float2half_rn(sv - __half2float(hb));
        }
    }
}

// ---------------------------------------------------------------------------
// Selective scan, 2-states-per-lane layout; delta read as fp16.
// ---------------------------------------------------------------------------
__global__ void __launch_bounds__(128) scan_kernel(
    const float* __restrict__ Alog_f, const float* __restrict__ Dv_f,
    const float* __restrict__ Alog_b, const float* __restrict__ Dv_b)
{
    const int dir = blockIdx.z;
    const int b   = blockIdx.y;
    const int d0  = blockIdx.x * 16;

    const float* Alog = dir ? Alog_b : Alog_f;
    const float* Dvec = dir ? Dv_b   : Dv_f;
    const __half* delta = g_delta[dir] + (size_t)b * CL * CDI;
    const __half* xth  = g_xth[dir]   + (size_t)b * CL * CDI;
    const __half* xtl  = g_xtl[dir]   + (size_t)b * CL * CDI;
    const float* dbl   = g_dbl[dir]   + (size_t)b * CL * CPROJ;
    float* yout        = g_y[dir]     + (size_t)b * CL * CDI;

    __shared__ __align__(16) float sd[64][16];   // dt
    __shared__ __align__(16) float sx[64][16];   // dt*x
    __shared__ __align__(16) float sB[64][16];
    __shared__ __align__(16) float sC[64][16];
    __shared__ __align__(16) float sxD[64][16];  // x*D

    const int tid  = threadIdx.x;
    const int lane = tid & 31;
    const int wid  = tid >> 5;
    const int ch   = wid*4 + (lane >> 3);
    const int n    = lane & 7;
    const int d    = d0 + ch;

    constexpr float LOG2E = 1.4426950408889634f;
    const float Aval0 = -__expf(Alog[d*CN + n])     * LOG2E;
    const float Aval1 = -__expf(Alog[d*CN + n + 8]) * LOG2E;
    float h0 = 0.f, h1 = 0.f;

    const int li = tid >> 1;
    const int lj = (tid & 1) * 8;

    float rDv[8];
#pragma unroll
    for (int j = 0; j < 8; ++j) rDv[j] = Dvec[d0 + lj + j];

    float rd[8], rx[8], rB[8], rC[8];
    auto LD = [&](int t0) {
        uint4 dv = *(const uint4*)(delta + (size_t)(t0+li)*CDI + d0 + lj);
        const uint32_t* dvp = &dv.x;
#pragma unroll
        for (int q = 0; q < 4; ++q) {
            float2 f = __half22float2(*(const __half2*)&dvp[q]);
            rd[2*q+0] = f.x; rd[2*q+1] = f.y;
        }
        uint4 xh = *(const uint4*)(xth + (size_t)(t0+li)*CDI + d0 + lj);
        uint4 xl = *(const uint4*)(xtl + (size_t)(t0+li)*CDI + d0 + lj);
        const uint32_t* xhp = &xh.x;
        const uint32_t* xlp = &xl.x;
#pragma unroll
        for (int q = 0; q < 4; ++q) {
            float2 fh = __half22float2(*(const __half2*)&xhp[q]);
            float2 fl = __half22float2(*(const __half2*)&xlp[q]);
            rx[2*q+0] = fh.x + fl.x;
            rx[2*q+1] = fh.y + fl.y;
        }
        float4 b0v = *(const float4*)(dbl + (size_t)(t0+li)*CPROJ + CR + lj);
        float4 b1v = *(const float4*)(dbl + (size_t)(t0+li)*CPROJ + CR + lj + 4);
        rB[0]=b0v.x; rB[1]=b0v.y; rB[2]=b0v.z; rB[3]=b0v.w;
        rB[4]=b1v.x; rB[5]=b1v.y; rB[6]=b1v.z; rB[7]=b1v.w;
        float4 c0v = *(const float4*)(dbl + (size_t)(t0+li)*CPROJ + CR + CN + lj);
        float4 c1v = *(const float4*)(dbl + (size_t)(t0+li)*CPROJ + CR + CN + lj + 4);
        rC[0]=c0v.x; rC[1]=c0v.y; rC[2]=c0v.z; rC[3]=c0v.w;
        rC[4]=c1v.x; rC[5]=c1v.y; rC[6]=c1v.z; rC[7]=c1v.w;
    };
    LD(0);

    const int NCH = CL / 64;
    for (int c = 0; c < NCH; ++c) {
        __syncthreads();
        {
            float4 v;
            v = make_float4(rd[0], rd[1], rd[2], rd[3]);            *(float4*)&sd[li][lj]   = v;
            v = make_float4(rd[4], rd[5], rd[6], rd[7]);            *(float4*)&sd[li][lj+4] = v;
            v = make_float4(rd[0]*rx[0], rd[1]*rx[1], rd[2]*rx[2], rd[3]*rx[3]); *(float4*)&sx[li][lj]   = v;
            v = make_float4(rd[4]*rx[4], rd[5]*rx[5], rd[6]*rx[6], rd[7]*rx[7]); *(float4*)&sx[li][lj+4] = v;
            v = make_float4(rB[0], rB[1], rB[2], rB[3]);            *(float4*)&sB[li][lj]   = v;
            v = make_float4(rB[4], rB[5], rB[6], rB[7]);            *(float4*)&sB[li][lj+4] = v;
            v = make_float4(rC[0], rC[1], rC[2], rC[3]);            *(float4*)&sC[li][lj]   = v;
            v = make_float4(rC[4], rC[5], rC[6], rC[7]);            *(float4*)&sC[li][lj+4] = v;
            v = make_float4(rx[0]*rDv[0], rx[1]*rDv[1], rx[2]*rDv[2], rx[3]*rDv[3]); *(float4*)&sxD[li][lj]   = v;
            v = make_float4(rx[4]*rDv[4], rx[5]*rDv[5], rx[6]*rDv[6], rx[7]*rDv[7]); *(float4*)&sxD[li][lj+4] = v;
        }
        __syncthreads();
        if (c + 1 < NCH) LD((c+1) * 64);

        const int tbase = c * 64;
#pragma unroll 8
        for (int s = 0; s < 64; ++s) {
            float dt  = sd[s][ch];
            float dtx = sx[s][ch];
            float B0 = sB[s][n],     C0 = sC[s][n];
            float B1 = sB[s][n + 8], C1 = sC[s][n + 8];
            float a0 = ex2f(dt * Aval0);
            float a1 = ex2f(dt * Aval1);
            h0 = fmaf(a0, h0, dtx * B0);
            h1 = fmaf(a1, h1, dtx * B1);
            float p = fmaf(h1, C1, h0 * C0);
            p += __shfl_xor_sync(0xffffffffu, p, 4);
            p += __shfl_xor_sync(0xffffffffu, p, 2);
            p += __shfl_xor_sync(0xffffffffu, p, 1);
            if (n == 0)
                yout[(size_t)(tbase + s)*CDI + d] = p + sxD[s][ch];
        }
    }
}

// ---------------------------------------------------------------------------
// Gate + direction merge -> single fp16 comb (z read from fp16 xz)
// ---------------------------------------------------------------------------
__global__ void __launch_bounds__(256) combine_kernel()
{
    const int l0 = blockIdx.x * 32;
    const int d0 = blockIdx.y * 32;
    const int b  = blockIdx.z;

    __shared__ float zs[32][33];
    const int lane = threadIdx.x & 31;
    const int wy   = threadIdx.x >> 5;

    const __half* zbase = g_xz + ((size_t)b * (2*CDI) + CDI + d0) * CL;
    for (int dd = wy; dd < 32; dd += 8)
        zs[dd][lane] = __half2float(zbase[(size_t)dd * CL + l0 + lane]);
    __syncthreads();

#pragma unroll
    for (int q = 0; q < 4; ++q) {
        int lr = wy + 8*q;
        int l = l0 + lr;
        size_t idx  = ((size_t)b*CL + l)*CDI + d0 + lane;
        size_t idxr = ((size_t)b*CL + (CL-1-l))*CDI + d0 + lane;
        float yf = g_y[0][idx];
        float yb = g_y[1][idxr];
        float zv = zs[lane][lr];
        float s = zv / (1.f + __expf(-zv));
        float cv = (yf + yb) * s;
        g_cmb_h[idx] = __float2half_rn(cv);
    }
}

// ---------------------------------------------------------------------------
// Launcher
// ---------------------------------------------------------------------------
extern "C" void kernel_launch(void* const* d_in, const int* in_sizes, int n_in,
                              void* d_out, int out_size)
{
    (void)in_sizes; (void)n_in; (void)out_size;

    const float* hidden  = (const float*)d_in[0];
    const float* in_w    = (const float*)d_in[1];
    const float* conv_w  = (const float*)d_in[2];
    const float* conv_b  = (const float*)d_in[3];
    const float* xproj_w = (const float*)d_in[4];
    const float* dtw     = (const float*)d_in[5];
    const float* dtb     = (const float*)d_in[6];
    const float* A_log   = (const float*)d_in[7];
    const float* Dv      = (const float*)d_in[8];
    const float* conv_w2 = (const float*)d_in[9];
    const float* conv_b2 = (const float*)d_in[10];
    const float* xproj_w2= (const float*)d_in[11];
    const float* dtw2    = (const float*)d_in[12];
    const float* dtb2    = (const float*)d_in[13];
    const float* A_log2  = (const float*)d_in[14];
    const float* Dv2     = (const float*)d_in[15];
    const float* out_w   = (const float*)d_in[16];

    void *p_xz, *p_hid_h, *p_w1, *p_w2, *p_cmb_h;
    cudaGetSymbolAddress(&p_xz, g_xz);
    cudaGetSymbolAddress(&p_hid_h, g_hid_h);
    cudaGetSymbolAddress(&p_w1, g_w1);
    cudaGetSymbolAddress(&p_w2, g_w2);
    cudaGetSymbolAddress(&p_cmb_h, g_cmb_h);

    cudaFuncSetAttribute(gemm_f16_kernel<0>,
                         cudaFuncAttributeMaxDynamicSharedMemorySize, GF_SMEM);
    cudaFuncSetAttribute(gemm_f16_kernel<1>,
                         cudaFuncAttributeMaxDynamicSharedMemorySize, GF_SMEM);
    cudaFuncSetAttribute(xproj_kernel,
                         cudaFuncAttributeMaxDynamicSharedMemorySize, XP_SMEM);
    cudaFuncSetAttribute(dtgemm_kernel,
                         cudaFuncAttributeMaxDynamicSharedMemorySize, 65536);

    // 0) fused operand packing
    pack_kernel<<<2048, 256>>>(hidden, in_w, out_w, xproj_w, xproj_w2, dtw, dtw2);

    // 1) in_proj, 1-term, fp16 out: A = w1, B = hidden.  M=3072, N=4096, K=768
    gemm_f16_kernel<1><<<dim3(CL/128, (2*CDI)/128, CB), 256, GF_SMEM>>>(
        (const __half*)p_w1, (const __half*)p_hid_h,
        p_xz, CL, CDM,
        0, (long long)CL * CDM, (long long)(2*CDI) * CL, CDM / 64);

    // 2) conv + SiLU + transpose (both dirs per block) -> fp16 hi/lo xt
    conv_silu_kernel<<<dim3(CL/128, CDI/32, CB), 256>>>(
        conv_w, conv_b, conv_w2, conv_b2);

    // 3) xproj, M=64 tiles, 1-term: dt fp16 hi/lo + fp32 B|C
    xproj_kernel<<<dim3(1, (CB*CL)/64, 2), 256, XP_SMEM>>>();

    // 4) dtproj as tensor GEMM + softplus -> delta (fp16)
    dtgemm_kernel<<<dim3(CDI/128, (CB*CL)/128, 2), 256, 65536>>>(dtb, dtb2);

    // 5) selective scan
    scan_kernel<<<dim3(CDI/16, CB, 2), 128>>>(A_log, Dv, A_log2, Dv2);

    // 6) gate + direction merge -> single fp16 comb
    combine_kernel<<<dim3(CL/32, CDI/32, CB), 256>>>();

    // 7) out_proj, 1-term, fp32 out: A = comb, B = w2.  M=8192, N=768, K=1536
    gemm_f16_kernel<0><<<dim3(CDM/128, (CB*CL)/128, 1), 256, GF_SMEM>>>(
        (const __half*)p_cmb_h, (const __half*)p_w2,
        d_out, CDM, CDI,
        0, 0, 0, CDI / 64);
}

// round 16
// speedup vs baseline: 1.5677x; 1.0356x over previous
#include <cuda_runtime.h>
#include <cuda_fp16.h>
#include <cstdint>

// Problem constants
constexpr int CB  = 2;     // batch
constexpr int CL  = 4096;  // seq len
constexpr int CDM = 768;   // d_model
constexpr int CDI = 1536;  // d_inner
constexpr int CN  = 16;    // state dim
constexpr int CR  = 48;    // dt rank
constexpr int CK  = 4;     // conv width
constexpr int CPROJ = CR + 2*CN; // 80
constexpr int CRP = 64;    // dt rank padded for MMA K

// ---------------------------------------------------------------------------
// Scratch (device globals; no runtime allocation allowed)
// ---------------------------------------------------------------------------
__device__ __half g_xz[CB * 2 * CDI * CL];       // (b, e, l), fp16
__device__ float g_dbl[2][CB * CL * CPROJ];      // per dir, (b*L, 80): only B|C cols used
__device__ __half g_delta[2][CB * CL * CDI];     // per dir, post-softplus, fp16
__device__ __half g_y[2][CB * CL * CDI];         // per dir, scan out (+D*x), fp16

// fp16 operands for tensor GEMMs
__device__ __half g_hid_h[CB*CL*CDM];                       // hidden, single fp16
__device__ __half g_w1[2*CDI*CDM];                          // in_proj W (single)
__device__ __half g_w2[CDM*CDI];                            // out_proj W (single)
__device__ __half g_wx[2][128*CDI];                         // xproj W padded 80->128 (single)
__device__ __half g_xth[2][CB*CL*CDI];                      // conv out, single fp16
__device__ __half g_cmb_h[CB*CL*CDI];                       // gated sum, single fp16
__device__ __half g_dt_h[2][CB*CL*CRP], g_dt_l[2][CB*CL*CRP]; // dt rows padded 48->64, hi/lo
__device__ __half g_wdt_h[2][CDI*CRP],  g_wdt_l[2][CDI*CRP];  // dtproj W padded, hi/lo

// ---------------------------------------------------------------------------
// PTX helpers
// ---------------------------------------------------------------------------
__device__ __forceinline__ uint32_t smem_u32(const void* p) {
    uint32_t a;
    asm("{ .reg .u64 t; cvta.to.shared.u64 t, %1; cvt.u32.u64 %0, t; }" : "=r"(a) : "l"(p));
    return a;
}
__device__ __forceinline__ uint32_t sw128(uint32_t b) { return b ^ ((b >> 3) & 0x70); }

__device__ __forceinline__ void ldsm4(uint32_t addr, uint32_t r[4]) {
    asm volatile("ldmatrix.sync.aligned.m8n8.x4.shared.b16 {%0,%1,%2,%3}, [%4];"
        : "=r"(r[0]), "=r"(r[1]), "=r"(r[2]), "=r"(r[3]) : "r"(addr));
}
__device__ __forceinline__ void mma_f16(float* d, const uint32_t* a, uint32_t b0, uint32_t b1) {
    asm volatile("mma.sync.aligned.m16n8k16.row.col.f32.f16.f16.f32 "
        "{%0,%1,%2,%3}, {%4,%5,%6,%7}, {%8,%9}, {%0,%1,%2,%3};"
        : "+f"(d[0]), "+f"(d[1]), "+f"(d[2]), "+f"(d[3])
        : "r"(a[0]), "r"(a[1]), "r"(a[2]), "r"(a[3]), "r"(b0), "r"(b1));
}
__device__ __forceinline__ void cp16(uint32_t s, const void* g) {
    asm volatile("cp.async.ca.shared.global [%0], [%1], 16;" :: "r"(s), "l"(g));
}
__device__ __forceinline__ float ex2f(float x) {
    float r;
    asm("ex2.approx.f32 %0, %1;" : "=f"(r) : "f"(x));
    return r;
}

// ---------------------------------------------------------------------------
// fp16 tensor GEMM (M=128 tile), 1-term:  C[m,n] = sum_k A[m,k]*B[n,k]
// OUT16=1: store fp16 output; OUT16=0: fp32 output.
// ---------------------------------------------------------------------------
constexpr int GF_STAGE = 49152;
constexpr int GF_SMEM  = 2 * GF_STAGE;   // 98304 B

template <int OUT16>
__global__ void __launch_bounds__(256, 2) gemm_f16_kernel(
    const __half* __restrict__ Ah, const __half* __restrict__ Bh,
    void* __restrict__ Cv, int Nout, int Kd,
    long long strideA, long long strideB, long long strideC, int NC)
{
    extern __shared__ __align__(1024) char smem[];
    const uint32_t su = smem_u32(smem);
    Ah += (size_t)blockIdx.z * strideA;
    Bh += (size_t)blockIdx.z * strideB;
    const int bm = blockIdx.y * 128;
    const int bn = blockIdx.x * 128;
    const int tid  = threadIdx.x;
    const int wid  = tid >> 5;
    const int lane = tid & 31;

    const int prow = tid >> 3;
    const int pkc  = tid & 7;
    auto issue = [&](int c) {
        const uint32_t sb = su + (uint32_t)(c & 1) * GF_STAGE;
        const int k0 = c * 64;
#pragma unroll
        for (int i = 0; i < 4; ++i) {
            const int row = prow + i * 32;
            const uint32_t off = sw128((uint32_t)(row * 128 + pkc * 16));
            const size_t ga = (size_t)(bm + row) * Kd + k0 + pkc * 8;
            const size_t gb = (size_t)(bn + row) * Kd + k0 + pkc * 8;
            cp16(sb + off,         Ah + ga);
            cp16(sb + 32768 + off, Bh + gb);
        }
        asm volatile("cp.async.commit_group;" ::: "memory");
    };

    const int m0 = (wid & 3) * 32;
    const int n0 = (wid >> 2) * 64;
    const int g    = lane >> 3;
    const int lr   = lane & 7;
    const int lrow = (g & 1) * 8 + lr;
    const int lkb  = (g >> 1) * 16;

    float acc[2][8][4] = {};

    issue(0); issue(1);

    for (int c = 0; c < NC; ++c) {
        asm volatile("cp.async.wait_group 1;" ::: "memory");
        __syncthreads();
        const uint32_t sb = su + (uint32_t)(c & 1) * GF_STAGE;
#pragma unroll
        for (int kk = 0; kk < 4; ++kk) {
            uint32_t ah[2][4];
#pragma unroll
            for (int mt = 0; mt < 2; ++mt) {
                uint32_t off = sw128((uint32_t)((m0 + mt*16 + lrow) * 128 + kk*32 + lkb));
                ldsm4(sb + off, ah[mt]);
            }
#pragma unroll
            for (int np = 0; np < 4; ++np) {
                uint32_t boff = sw128((uint32_t)((n0 + np*16 + lrow) * 128 + kk*32 + lkb));
                uint32_t bh[4];
                ldsm4(sb + 32768 + boff, bh);
#pragma unroll
                for (int mt = 0; mt < 2; ++mt) {
                    mma_f16(acc[mt][2*np],   ah[mt], bh[0], bh[2]);
                    mma_f16(acc[mt][2*np+1], ah[mt], bh[1], bh[3]);
                }
            }
        }
        __syncthreads();
        if (c + 2 < NC) issue(c + 2);
        else asm volatile("cp.async.commit_group;" ::: "memory");
    }

    const int er = lane >> 2;
    const int ec = (lane & 3) * 2;
#pragma unroll
    for (int mt = 0; mt < 2; ++mt) {
#pragma unroll
        for (int nt = 0; nt < 8; ++nt) {
            const int row = bm + m0 + mt*16 + er;
            const int col = bn + n0 + nt*8 + ec;
            if (col < Nout) {
                if (OUT16) {
                    __half* C = (__half*)Cv + (size_t)blockIdx.z * strideC;
                    __half2 lo = __halves2half2(__float2half_rn(acc[mt][nt][0]),
                                                __float2half_rn(acc[mt][nt][1]));
                    __half2 hi = __halves2half2(__float2half_rn(acc[mt][nt][2]),
                                                __float2half_rn(acc[mt][nt][3]));
                    *(__half2*)(C + (size_t)row * Nout + col)       = lo;
                    *(__half2*)(C + (size_t)(row + 8) * Nout + col) = hi;
                } else {
                    float* C = (float*)Cv + (size_t)blockIdx.z * strideC;
                    float2 lo = { acc[mt][nt][0], acc[mt][nt][1] };
                    float2 hi = { acc[mt][nt][2], acc[mt][nt][3] };
                    *(float2*)(C + (size_t)row * Nout + col)       = lo;
                    *(float2*)(C + (size_t)(row + 8) * Nout + col) = hi;
                }
            }
        }
    }
}

// ---------------------------------------------------------------------------
// xproj tensor GEMM, M=64 CTA tile, 1-term (xt-hi only).
// ---------------------------------------------------------------------------
constexpr int XP_STAGE = 32768;
constexpr int XP_SMEM  = 2 * XP_STAGE;   // 65536 B

__global__ void __launch_bounds__(256, 2) xproj_kernel()
{
    extern __shared__ __align__(1024) char smem[];
    const uint32_t su = smem_u32(smem);
    const int dir = blockIdx.z;
    const __half* Ah = &g_xth[dir][0];
    const __half* Bh = &g_wx[dir][0];
    float* C   = &g_dbl[dir][0];
    __half* dH = &g_dt_h[dir][0];
    __half* dL = &g_dt_l[dir][0];

    const int bm = blockIdx.y * 64;
    const int tid  = threadIdx.x;
    const int wid  = tid >> 5;
    const int lane = tid & 31;

    const int prow = tid >> 3;
    const int pkc  = tid & 7;
    auto issue = [&](int c) {
        const uint32_t sb = su + (uint32_t)(c & 1) * XP_STAGE;
        const int k0 = c * 64;
#pragma unroll
        for (int i = 0; i < 2; ++i) {
            const int row = prow + i * 32;
            const uint32_t off = sw128((uint32_t)(row * 128 + pkc * 16));
            const size_t ga = (size_t)(bm + row) * CDI + k0 + pkc * 8;
            cp16(sb + off, Ah + ga);
        }
#pragma unroll
        for (int i = 0; i < 4; ++i) {
            const int row = prow + i * 32;
            const uint32_t off = sw128((uint32_t)(row * 128 + pkc * 16));
            const size_t gb = (size_t)row * CDI + k0 + pkc * 8;
            cp16(sb + 16384 + off, Bh + gb);
        }
        asm volatile("cp.async.commit_group;" ::: "memory");
    };

    const int m0 = (wid & 1) * 32;
    const int n0 = (wid >> 1) * 32;
    const int g    = lane >> 3;
    const int lr   = lane & 7;
    const int lrow = (g & 1) * 8 + lr;
    const int lkb  = (g >> 1) * 16;

    float acc[2][4][4] = {};

    issue(0); issue(1);

    const int NC = CDI / 64;
    for (int c = 0; c < NC; ++c) {
        asm volatile("cp.async.wait_group 1;" ::: "memory");
        __syncthreads();
        const uint32_t sb = su + (uint32_t)(c & 1) * XP_STAGE;
#pragma unroll
        for (int kk = 0; kk < 4; ++kk) {
            uint32_t ah[2][4];
#pragma unroll
            for (int mt = 0; mt < 2; ++mt) {
                uint32_t off = sw128((uint32_t)((m0 + mt*16 + lrow) * 128 + kk*32 + lkb));
                ldsm4(sb + off, ah[mt]);
            }
#pragma unroll
            for (int np = 0; np < 2; ++np) {
                uint32_t boff = sw128((uint32_t)((n0 + np*16 + lrow) * 128 + kk*32 + lkb));
                uint32_t bh[4];
                ldsm4(sb + 16384 + boff, bh);
#pragma unroll
                for (int mt = 0; mt < 2; ++mt) {
                    mma_f16(acc[mt][2*np],   ah[mt], bh[0], bh[2]);
                    mma_f16(acc[mt][2*np+1], ah[mt], bh[1], bh[3]);
                }
            }
        }
        __syncthreads();
        if (c + 2 < NC) issue(c + 2);
        else asm volatile("cp.async.commit_group;" ::: "memory");
    }

    const int er = lane >> 2;
    const int ec = (lane & 3) * 2;
#pragma unroll
    for (int mt = 0; mt < 2; ++mt) {
#pragma unroll
        for (int nt = 0; nt < 4; ++nt) {
            const int row0 = bm + m0 + mt*16 + er;
            const int col  = n0 + nt*8 + ec;
#pragma unroll
            for (int rr = 0; rr < 2; ++rr) {
                const int row = row0 + rr*8;
#pragma unroll
                for (int e = 0; e < 2; ++e) {
                    const int cc = col + e;
                    const float v = acc[mt][nt][rr*2+e];
                    if (cc < CRP) {
                        float dv = (cc < CR) ? v : 0.f;
                        __half hb = __float2half_rn(dv);
                        dH[(size_t)row * CRP + cc] = hb;
                        dL[(size_t)row * CRP + cc] =
                            __float2half_rn(dv - __half2float(hb));
                    }
                    if (cc >= CR && cc < CPROJ)
                        C[(size_t)row * CPROJ + cc] = v;
                }
            }
        }
    }
}

// ---------------------------------------------------------------------------
// dtproj tensor GEMM: delta[row,d] = softplus(sum_r dt[row,r]*W[d,r] + bias[d])
// Output stored fp16.
// ---------------------------------------------------------------------------
__device__ __forceinline__ float softplus_f(float v) {
    return (v > 20.f) ? v : log1pf(__expf(v));
}

__global__ void __launch_bounds__(256) dtgemm_kernel(
    const float* __restrict__ bias_f, const float* __restrict__ bias_b)
{
    extern __shared__ __align__(1024) char smem[];
    const uint32_t su = smem_u32(smem);
    const int dir = blockIdx.z;
    const __half* Ah = &g_dt_h[dir][0];
    const __half* Al = &g_dt_l[dir][0];
    const __half* Bh = &g_wdt_h[dir][0];
    const __half* Bl = &g_wdt_l[dir][0];
    const float* bias = dir ? bias_b : bias_f;
    __half* C = &g_delta[dir][0];

    const int bm = blockIdx.y * 128;
    const int bn = blockIdx.x * 128;
    const int tid  = threadIdx.x;
    const int wid  = tid >> 5;
    const int lane = tid & 31;

    const int prow = tid >> 3;
    const int pkc  = tid & 7;
#pragma unroll
    for (int i = 0; i < 4; ++i) {
        const int row = prow + i * 32;
        const uint32_t off = sw128((uint32_t)(row * 128 + pkc * 16));
        const size_t ga = (size_t)(bm + row) * CRP + pkc * 8;
        const size_t gb = (size_t)(bn + row) * CRP + pkc * 8;
        cp16(su + off,         Ah + ga);
        cp16(su + 16384 + off, Al + ga);
        cp16(su + 32768 + off, Bh + gb);
        cp16(su + 49152 + off, Bl + gb);
    }
    asm volatile("cp.async.commit_group;" ::: "memory");
    asm volatile("cp.async.wait_group 0;" ::: "memory");
    __syncthreads();

    const int m0 = (wid & 3) * 32;
    const int n0 = (wid >> 2) * 64;
    const int g    = lane >> 3;
    const int lr   = lane & 7;
    const int lrow = (g & 1) * 8 + lr;
    const int lkb  = (g >> 1) * 16;

    float acc[2][8][4] = {};
#pragma unroll
    for (int kk = 0; kk < 4; ++kk) {
        uint32_t ah[2][4], al[2][4];
#pragma unroll
        for (int mt = 0; mt < 2; ++mt) {
            uint32_t off = sw128((uint32_t)((m0 + mt*16 + lrow) * 128 + kk*32 + lkb));
            ldsm4(su + off,         ah[mt]);
            ldsm4(su + 16384 + off, al[mt]);
        }
#pragma unroll
        for (int np = 0; np < 4; ++np) {
            uint32_t boff = sw128((uint32_t)((n0 + np*16 + lrow) * 128 + kk*32 + lkb));
            uint32_t bh[4], bl[4];
            ldsm4(su + 32768 + boff, bh);
            ldsm4(su + 49152 + boff, bl);
#pragma unroll
            for (int mt = 0; mt < 2; ++mt) {
                mma_f16(acc[mt][2*np],   ah[mt], bh[0], bh[2]);
                mma_f16(acc[mt][2*np],   al[mt], bh[0], bh[2]);
                mma_f16(acc[mt][2*np],   ah[mt], bl[0], bl[2]);
                mma_f16(acc[mt][2*np+1], ah[mt], bh[1], bh[3]);
                mma_f16(acc[mt][2*np+1], al[mt], bh[1], bh[3]);
                mma_f16(acc[mt][2*np+1], ah[mt], bl[1], bl[3]);
            }
        }
    }

    const int er = lane >> 2;
    const int ec = (lane & 3) * 2;
#pragma unroll
    for (int mt = 0; mt < 2; ++mt) {
#pragma unroll
        for (int nt = 0; nt < 8; ++nt) {
            const int row = bm + m0 + mt*16 + er;
            const int col = bn + n0 + nt*8 + ec;
            const float b0 = bias[col], b1 = bias[col+1];
            __half2 lo = __halves2half2(
                __float2half_rn(softplus_f(acc[mt][nt][0] + b0)),
                __float2half_rn(softplus_f(acc[mt][nt][1] + b1)));
            __half2 hi = __halves2half2(
                __float2half_rn(softplus_f(acc[mt][nt][2] + b0)),
                __float2half_rn(softplus_f(acc[mt][nt][3] + b1)));
            *(__half2*)(C + (size_t)row * CDI + col)       = lo;
            *(__half2*)(C + (size_t)(row + 8) * CDI + col) = hi;
        }
    }
}

// ---------------------------------------------------------------------------
// Fused operand packer (single launch)
// ---------------------------------------------------------------------------
constexpr int PK_R0 = CB*CL*CDM/4;
constexpr int PK_R1 = PK_R0 + 2*CDI*CDM/4;
constexpr int PK_R2 = PK_R1 + CDM*CDI/4;
constexpr int PK_R3 = PK_R2 + 2*128*CDI/4;
constexpr int PK_R4 = PK_R3 + 2*CDI*CRP/4;

__device__ __forceinline__ uint2 pack4_f16(float4 v) {
    __half2 h01 = __halves2half2(__float2half_rn(v.x), __float2half_rn(v.y));
    __half2 h23 = __halves2half2(__float2half_rn(v.z), __float2half_rn(v.w));
    return make_uint2(*(uint32_t*)&h01, *(uint32_t*)&h23);
}

__global__ void pack_kernel(
    const float* __restrict__ hidden, const float* __restrict__ in_w,
    const float* __restrict__ out_w,
    const float* __restrict__ xw_f, const float* __restrict__ xw_b,
    const float* __restrict__ dw_f, const float* __restrict__ dw_b)
{
    for (int i = blockIdx.x * blockDim.x + threadIdx.x; i < PK_R4;
         i += gridDim.x * blockDim.x) {
        if (i < PK_R0) {
            ((uint2*)g_hid_h)[i] = pack4_f16(((const float4*)hidden)[i]);
        } else if (i < PK_R1) {
            int j = i - PK_R0;
            ((uint2*)g_w1)[j] = pack4_f16(((const float4*)in_w)[j]);
        } else if (i < PK_R2) {
            int j = i - PK_R1;
            ((uint2*)g_w2)[j] = pack4_f16(((const float4*)out_w)[j]);
        } else if (i < PK_R3) {
            int j = i - PK_R2;
            int e = j * 4;
            int dir = e / (128 * CDI);
            int rem = e - dir * 128 * CDI;
            int row = rem / CDI;
            int k   = rem - row * CDI;
            float4 v = {0.f, 0.f, 0.f, 0.f};
            const float* W = dir ? xw_b : xw_f;
            if (row < CPROJ) v = *(const float4*)(W + (size_t)row * CDI + k);
            ((uint2*)&g_wx[0][0])[j] = pack4_f16(v);
        } else {
            int j = i - PK_R3;
            int e = j * 4;
            int dir = e / (CDI * CRP);
            int rem = e - dir * CDI * CRP;
            int row = rem / CRP;
            int k   = rem - row * CRP;
            float4 v = {0.f, 0.f, 0.f, 0.f};
            const float* W = dir ? dw_b : dw_f;
            if (k < CR) v = *(const float4*)(W + (size_t)row * CR + k);
            __half hx = __float2half_rn(v.x), hy = __float2half_rn(v.y);
            __half hz = __float2half_rn(v.z), hw = __float2half_rn(v.w);
            __half lx = __float2half_rn(v.x - __half2float(hx));
            __half ly = __float2half_rn(v.y - __half2float(hy));
            __half lz = __float2half_rn(v.z - __half2float(hz));
            __half lw = __float2half_rn(v.w - __half2float(hw));
            __half2 h01 = __halves2half2(hx, hy), h23 = __halves2half2(hz, hw);
            __half2 l01 = __halves2half2(lx, ly), l23 = __halves2half2(lz, lw);
            ((uint2*)&g_wdt_h[0][0])[j] = make_uint2(*(uint32_t*)&h01, *(uint32_t*)&h23);
            ((uint2*)&g_wdt_l[0][0])[j] = make_uint2(*(uint32_t*)&l01, *(uint32_t*)&l23);
        }
    }
}

// ---------------------------------------------------------------------------
// Depthwise causal conv (K=4) + bias + SiLU, transpose to (b,t,d).
// MERGED DIRECTIONS; single-fp16 xt output (no lo residual).
// ---------------------------------------------------------------------------
__global__ void __launch_bounds__(256) conv_silu_kernel(
    const float* __restrict__ cw_f, const float* __restrict__ cb_f,
    const float* __restrict__ cw_b, const float* __restrict__ cb_b)
{
    const int t0 = blockIdx.x * 128;
    const int d0 = blockIdx.y * 32;
    const int b  = blockIdx.z;

    __shared__ float xs[32][135];

    const __half* xbase = g_xz + ((size_t)b * (2*CDI) + d0) * CL;
    const int base = t0 - 3;

    const int lane = threadIdx.x & 31;
    const int wy   = threadIdx.x >> 5;
    for (int d = wy; d < 32; d += 8) {
        const __half* row = xbase + (size_t)d * CL;
        for (int i = lane; i < 134; i += 32) {
            int u = base + i;
            xs[d][i] = (u >= 0 && u < CL) ? __half2float(row[u]) : 0.f;
        }
    }
    __syncthreads();

    const int d  = threadIdx.x & 31;
    const int sg = threadIdx.x >> 5;
    const float wf0 = cw_f[(d0+d)*CK + 0];
    const float wf1 = cw_f[(d0+d)*CK + 1];
    const float wf2 = cw_f[(d0+d)*CK + 2];
    const float wf3 = cw_f[(d0+d)*CK + 3];
    const float bf  = cb_f[d0+d];
    const float wb0 = cw_b[(d0+d)*CK + 0];
    const float wb1 = cw_b[(d0+d)*CK + 1];
    const float wb2 = cw_b[(d0+d)*CK + 2];
    const float wb3 = cw_b[(d0+d)*CK + 3];
    const float bb  = cb_b[d0+d];

    __half* ohf = g_xth[0] + (size_t)b * CL * CDI;
    __half* ohb = g_xth[1] + (size_t)b * CL * CDI;
    const int tb0 = CL - 128 - t0;
#pragma unroll
    for (int q = 0; q < 16; ++q) {
        int s = sg + 8*q;
        {
            float v = wf0*xs[d][s] + wf1*xs[d][s+1] + wf2*xs[d][s+2] + wf3*xs[d][s+3] + bf;
            float sv = v / (1.f + __expf(-v));
            ohf[(size_t)(t0 + s) * CDI + d0 + d] = __float2half_rn(sv);
        }
        {
            float v = wb3*xs[d][130-s] + wb2*xs[d][131-s] + wb1*xs[d][132-s]
                    + wb0*xs[d][133-s] + bb;
            float sv = v / (1.f + __expf(-v));
            ohb[(size_t)(tb0 + s) * CDI + d0 + d] = __float2half_rn(sv);
        }
    }
}

// ---------------------------------------------------------------------------
// Selective scan, 2-states-per-lane layout; x and delta read fp16; y out fp16.
// ---------------------------------------------------------------------------
__global__ void __launch_bounds__(128) scan_kernel(
    const float* __restrict__ Alog_f, const float* __restrict__ Dv_f,
    const float* __restrict__ Alog_b, const float* __restrict__ Dv_b)
{
    const int dir = blockIdx.z;
    const int b   = blockIdx.y;
    const int d0  = blockIdx.x * 16;

    const float* Alog = dir ? Alog_b : Alog_f;
    const float* Dvec = dir ? Dv_b   : Dv_f;
    const __half* delta = g_delta[dir] + (size_t)b * CL * CDI;
    const __half* xth  = g_xth[dir]   + (size_t)b * CL * CDI;
    const float* dbl   = g_dbl[dir]   + (size_t)b * CL * CPROJ;
    __half* yout       = g_y[dir]     + (size_t)b * CL * CDI;

    __shared__ __align__(16) float sd[64][16];   // dt
    __shared__ __align__(16) float sx[64][16];   // dt*x
    __shared__ __align__(16) float sB[64][16];
    __shared__ __align__(16) float sC[64][16];
    __shared__ __align__(16) float sxD[64][16];  // x*D

    const int tid  = threadIdx.x;
    const int lane = tid & 31;
    const int wid  = tid >> 5;
    const int ch   = wid*4 + (lane >> 3);
    const int n    = lane & 7;
    const int d    = d0 + ch;

    constexpr float LOG2E = 1.4426950408889634f;
    const float Aval0 = -__expf(Alog[d*CN + n])     * LOG2E;
    const float Aval1 = -__expf(Alog[d*CN + n + 8]) * LOG2E;
    float h0 = 0.f, h1 = 0.f;

    const int li = tid >> 1;
    const int lj = (tid & 1) * 8;

    float rDv[8];
#pragma unroll
    for (int j = 0; j < 8; ++j) rDv[j] = Dvec[d0 + lj + j];

    float rd[8], rx[8], rB[8], rC[8];
    auto LD = [&](int t0) {
        uint4 dv = *(const uint4*)(delta + (size_t)(t0+li)*CDI + d0 + lj);
        const uint32_t* dvp = &dv.x;
#pragma unroll
        for (int q = 0; q < 4; ++q) {
            float2 f = __half22float2(*(const __half2*)&dvp[q]);
            rd[2*q+0] = f.x; rd[2*q+1] = f.y;
        }
        uint4 xh = *(const uint4*)(xth + (size_t)(t0+li)*CDI + d0 + lj);
        const uint32_t* xhp = &xh.x;
#pragma unroll
        for (int q = 0; q < 4; ++q) {
            float2 fh = __half22float2(*(const __half2*)&xhp[q]);
            rx[2*q+0] = fh.x;
            rx[2*q+1] = fh.y;
        }
        float4 b0v = *(const float4*)(dbl + (size_t)(t0+li)*CPROJ + CR + lj);
        float4 b1v = *(const float4*)(dbl + (size_t)(t0+li)*CPROJ + CR + lj + 4);
        rB[0]=b0v.x; rB[1]=b0v.y; rB[2]=b0v.z; rB[3]=b0v.w;
        rB[4]=b1v.x; rB[5]=b1v.y; rB[6]=b1v.z; rB[7]=b1v.w;
        float4 c0v = *(const float4*)(dbl + (size_t)(t0+li)*CPROJ + CR + CN + lj);
        float4 c1v = *(const float4*)(dbl + (size_t)(t0+li)*CPROJ + CR + CN + lj + 4);
        rC[0]=c0v.x; rC[1]=c0v.y; rC[2]=c0v.z; rC[3]=c0v.w;
        rC[4]=c1v.x; rC[5]=c1v.y; rC[6]=c1v.z; rC[7]=c1v.w;
    };
    LD(0);

    const int NCH = CL / 64;
    for (int c = 0; c < NCH; ++c) {
        __syncthreads();
        {
            float4 v;
            v = make_float4(rd[0], rd[1], rd[2], rd[3]);            *(float4*)&sd[li][lj]   = v;
            v = make_float4(rd[4], rd[5], rd[6], rd[7]);            *(float4*)&sd[li][lj+4] = v;
            v = make_float4(rd[0]*rx[0], rd[1]*rx[1], rd[2]*rx[2], rd[3]*rx[3]); *(float4*)&sx[li][lj]   = v;
            v = make_float4(rd[4]*rx[4], rd[5]*rx[5], rd[6]*rx[6], rd[7]*rx[7]); *(float4*)&sx[li][lj+4] = v;
            v = make_float4(rB[0], rB[1], rB[2], rB[3]);            *(float4*)&sB[li][lj]   = v;
            v = make_float4(rB[4], rB[5], rB[6], rB[7]);            *(float4*)&sB[li][lj+4] = v;
            v = make_float4(rC[0], rC[1], rC[2], rC[3]);            *(float4*)&sC[li][lj]   = v;
            v = make_float4(rC[4], rC[5], rC[6], rC[7]);            *(float4*)&sC[li][lj+4] = v;
            v = make_float4(rx[0]*rDv[0], rx[1]*rDv[1], rx[2]*rDv[2], rx[3]*rDv[3]); *(float4*)&sxD[li][lj]   = v;
            v = make_float4(rx[4]*rDv[4], rx[5]*rDv[5], rx[6]*rDv[6], rx[7]*rDv[7]); *(float4*)&sxD[li][lj+4] = v;
        }
        __syncthreads();
        if (c + 1 < NCH) LD((c+1) * 64);

        const int tbase = c * 64;
#pragma unroll 8
        for (int s = 0; s < 64; ++s) {
            float dt  = sd[s][ch];
            float dtx = sx[s][ch];
            float B0 = sB[s][n],     C0 = sC[s][n];
            float B1 = sB[s][n + 8], C1 = sC[s][n + 8];
            float a0 = ex2f(dt * Aval0);
            float a1 = ex2f(dt * Aval1);
            h0 = fmaf(a0, h0, dtx * B0);
            h1 = fmaf(a1, h1, dtx * B1);
            float p = fmaf(h1, C1, h0 * C0);
            p += __shfl_xor_sync(0xffffffffu, p, 4);
            p += __shfl_xor_sync(0xffffffffu, p, 2);
            p += __shfl_xor_sync(0xffffffffu, p, 1);
            if (n == 0)
                yout[(size_t)(tbase + s)*CDI + d] = __float2half_rn(p + sxD[s][ch]);
        }
    }
}

// ---------------------------------------------------------------------------
// Gate + direction merge -> single fp16 comb (y read fp16)
// ---------------------------------------------------------------------------
__global__ void __launch_bounds__(256) combine_kernel()
{
    const int l0 = blockIdx.x * 32;
    const int d0 = blockIdx.y * 32;
    const int b  = blockIdx.z;

    __shared__ float zs[32][33];
    const int lane = threadIdx.x & 31;
    const int wy   = threadIdx.x >> 5;

    const __half* zbase = g_xz + ((size_t)b * (2*CDI) + CDI + d0) * CL;
    for (int dd = wy; dd < 32; dd += 8)
        zs[dd][lane] = __half2float(zbase[(size_t)dd * CL + l0 + lane]);
    __syncthreads();

#pragma unroll
    for (int q = 0; q < 4; ++q) {
        int lr = wy + 8*q;
        int l = l0 + lr;
        size_t idx  = ((size_t)b*CL + l)*CDI + d0 + lane;
        size_t idxr = ((size_t)b*CL + (CL-1-l))*CDI + d0 + lane;
        float yf = __half2float(g_y[0][idx]);
        float yb = __half2float(g_y[1][idxr]);
        float zv = zs[lane][lr];
        float s = zv / (1.f + __expf(-zv));
        float cv = (yf + yb) * s;
        g_cmb_h[idx] = __float2half_rn(cv);
    }
}

// ---------------------------------------------------------------------------
// Launcher
// ---------------------------------------------------------------------------
extern "C" void kernel_launch(void* const* d_in, const int* in_sizes, int n_in,
                              void* d_out, int out_size)
{
    (void)in_sizes; (void)n_in; (void)out_size;

    const float* hidden  = (const float*)d_in[0];
    const float* in_w    = (const float*)d_in[1];
    const float* conv_w  = (const float*)d_in[2];
    const float* conv_b  = (const float*)d_in[3];
    const float* xproj_w = (const float*)d_in[4];
    const float* dtw     = (const float*)d_in[5];
    const float* dtb     = (const float*)d_in[6];
    const float* A_log   = (const float*)d_in[7];
    const float* Dv      = (const float*)d_in[8];
    const float* conv_w2 = (const float*)d_in[9];
    const float* conv_b2 = (const float*)d_in[10];
    const float* xproj_w2= (const float*)d_in[11];
    const float* dtw2    = (const float*)d_in[12];
    const float* dtb2    = (const float*)d_in[13];
    const float* A_log2  = (const float*)d_in[14];
    const float* Dv2     = (const float*)d_in[15];
    const float* out_w   = (const float*)d_in[16];

    void *p_xz, *p_hid_h, *p_w1, *p_w2, *p_cmb_h;
    cudaGetSymbolAddress(&p_xz, g_xz);
    cudaGetSymbolAddress(&p_hid_h, g_hid_h);
    cudaGetSymbolAddress(&p_w1, g_w1);
    cudaGetSymbolAddress(&p_w2, g_w2);
    cudaGetSymbolAddress(&p_cmb_h, g_cmb_h);

    cudaFuncSetAttribute(gemm_f16_kernel<0>,
                         cudaFuncAttributeMaxDynamicSharedMemorySize, GF_SMEM);
    cudaFuncSetAttribute(gemm_f16_kernel<1>,
                         cudaFuncAttributeMaxDynamicSharedMemorySize, GF_SMEM);
    cudaFuncSetAttribute(xproj_kernel,
                         cudaFuncAttributeMaxDynamicSharedMemorySize, XP_SMEM);
    cudaFuncSetAttribute(dtgemm_kernel,
                         cudaFuncAttributeMaxDynamicSharedMemorySize, 65536);

    // 0) fused operand packing
    pack_kernel<<<2048, 256>>>(hidden, in_w, out_w, xproj_w, xproj_w2, dtw, dtw2);

    // 1) in_proj, 1-term, fp16 out: A = w1, B = hidden.  M=3072, N=4096, K=768
    gemm_f16_kernel<1><<<dim3(CL/128, (2*CDI)/128, CB), 256, GF_SMEM>>>(
        (const __half*)p_w1, (const __half*)p_hid_h,
        p_xz, CL, CDM,
        0, (long long)CL * CDM, (long long)(2*CDI) * CL, CDM / 64);

    // 2) conv + SiLU + transpose (both dirs per block) -> fp16 xt
    conv_silu_kernel<<<dim3(CL/128, CDI/32, CB), 256>>>(
        conv_w, conv_b, conv_w2, conv_b2);

    // 3) xproj, M=64 tiles, 1-term: dt fp16 hi/lo + fp32 B|C
    xproj_kernel<<<dim3(1, (CB*CL)/64, 2), 256, XP_SMEM>>>();

    // 4) dtproj as tensor GEMM + softplus -> delta (fp16)
    dtgemm_kernel<<<dim3(CDI/128, (CB*CL)/128, 2), 256, 65536>>>(dtb, dtb2);

    // 5) selective scan -> y (fp16)
    scan_kernel<<<dim3(CDI/16, CB, 2), 128>>>(A_log, Dv, A_log2, Dv2);

    // 6) gate + direction merge -> single fp16 comb
    combine_kernel<<<dim3(CL/32, CDI/32, CB), 256>>>();

    // 7) out_proj, 1-term, fp32 out: A = comb, B = w2.  M=8192, N=768, K=1536
    gemm_f16_kernel<0><<<dim3(CDM/128, (CB*CL)/128, 1), 256, GF_SMEM>>>(
        (const __half*)p_cmb_h, (const __half*)p_w2,
        d_out, CDM, CDI,
        0, 0, 0, CDI / 64);
}

// round 17
// speedup vs baseline: 1.7723x; 1.1305x over previous
#include <cuda_runtime.h>
#include <cuda_fp16.h>
#include <cstdint>

// Problem constants
constexpr int CB  = 2;     // batch
constexpr int CL  = 4096;  // seq len
constexpr int CDM = 768;   // d_model
constexpr int CDI = 1536;  // d_inner
constexpr int CN  = 16;    // state dim
constexpr int CR  = 48;    // dt rank
constexpr int CK  = 4;     // conv width
constexpr int CPROJ = CR + 2*CN; // 80
constexpr int CRP = 64;    // dt rank padded for MMA K

// ---------------------------------------------------------------------------
// Scratch (device globals; no runtime allocation allowed)
// ---------------------------------------------------------------------------
__device__ __half g_xz[CB * 2 * CDI * CL];       // (b, e, l), fp16
__device__ float g_dbl[2][CB * CL * CPROJ];      // per dir, (b*L, 80): only B|C cols used
__device__ __half g_delta[2][CB * CL * CDI];     // per dir, post-softplus, fp16
__device__ __half g_y[2][CB * CL * CDI];         // per dir, scan out (+D*x), fp16

// fp16 operands for tensor GEMMs
__device__ __half g_hid_h[CB*CL*CDM];                       // hidden, single fp16
__device__ __half g_w1[2*CDI*CDM];                          // in_proj W (single)
__device__ __half g_w2[CDM*CDI];                            // out_proj W (single)
__device__ __half g_wx[2][128*CDI];                         // xproj W padded 80->128 (single)
__device__ __half g_xth[2][CB*CL*CDI];                      // conv out, single fp16
__device__ __half g_cmb_h[CB*CL*CDI];                       // gated sum, single fp16
__device__ __half g_dt_h[2][CB*CL*CRP], g_dt_l[2][CB*CL*CRP]; // dt rows padded 48->64, hi/lo
__device__ __half g_wdt_h[2][CDI*CRP],  g_wdt_l[2][CDI*CRP];  // dtproj W padded, hi/lo

// ---------------------------------------------------------------------------
// PTX helpers
// ---------------------------------------------------------------------------
__device__ __forceinline__ uint32_t smem_u32(const void* p) {
    uint32_t a;
    asm("{ .reg .u64 t; cvta.to.shared.u64 t, %1; cvt.u32.u64 %0, t; }" : "=r"(a) : "l"(p));
    return a;
}
__device__ __forceinline__ uint32_t sw128(uint32_t b) { return b ^ ((b >> 3) & 0x70); }

__device__ __forceinline__ void ldsm4(uint32_t addr, uint32_t r[4]) {
    asm volatile("ldmatrix.sync.aligned.m8n8.x4.shared.b16 {%0,%1,%2,%3}, [%4];"
        : "=r"(r[0]), "=r"(r[1]), "=r"(r[2]), "=r"(r[3]) : "r"(addr));
}
__device__ __forceinline__ void mma_f16(float* d, const uint32_t* a, uint32_t b0, uint32_t b1) {
    asm volatile("mma.sync.aligned.m16n8k16.row.col.f32.f16.f16.f32 "
        "{%0,%1,%2,%3}, {%4,%5,%6,%7}, {%8,%9}, {%0,%1,%2,%3};"
        : "+f"(d[0]), "+f"(d[1]), "+f"(d[2]), "+f"(d[3])
        : "r"(a[0]), "r"(a[1]), "r"(a[2]), "r"(a[3]), "r"(b0), "r"(b1));
}
__device__ __forceinline__ void cp16(uint32_t s, const void* g) {
    asm volatile("cp.async.ca.shared.global [%0], [%1], 16;" :: "r"(s), "l"(g));
}
__device__ __forceinline__ float ex2f(float x) {
    float r;
    asm("ex2.approx.f32 %0, %1;" : "=f"(r) : "f"(x));
    return r;
}

// ---------------------------------------------------------------------------
// fp16 tensor GEMM (M=128 tile), 1-term:  C[m,n] = sum_k A[m,k]*B[n,k]
// OUT16=1: store fp16 output; OUT16=0: fp32 output.
// 3-stage cp.async ring (32KB/stage: A 16K | B 16K), 96KB smem, 2 CTA/SM.
// ---------------------------------------------------------------------------
constexpr int GF_STAGE = 32768;
constexpr int GF_SMEM  = 3 * GF_STAGE;   // 98304 B

template <int OUT16>
__global__ void __launch_bounds__(256, 2) gemm_f16_kernel(
    const __half* __restrict__ Ah, const __half* __restrict__ Bh,
    void* __restrict__ Cv, int Nout, int Kd,
    long long strideA, long long strideB, long long strideC, int NC)
{
    extern __shared__ __align__(1024) char smem[];
    const uint32_t su = smem_u32(smem);
    Ah += (size_t)blockIdx.z * strideA;
    Bh += (size_t)blockIdx.z * strideB;
    const int bm = blockIdx.y * 128;
    const int bn = blockIdx.x * 128;
    const int tid  = threadIdx.x;
    const int wid  = tid >> 5;
    const int lane = tid & 31;

    const int prow = tid >> 3;
    const int pkc  = tid & 7;
    auto issue = [&](int c) {
        const uint32_t sb = su + (uint32_t)(c % 3) * GF_STAGE;
        const int k0 = c * 64;
#pragma unroll
        for (int i = 0; i < 4; ++i) {
            const int row = prow + i * 32;
            const uint32_t off = sw128((uint32_t)(row * 128 + pkc * 16));
            const size_t ga = (size_t)(bm + row) * Kd + k0 + pkc * 8;
            const size_t gb = (size_t)(bn + row) * Kd + k0 + pkc * 8;
            cp16(sb + off,         Ah + ga);
            cp16(sb + 16384 + off, Bh + gb);
        }
        asm volatile("cp.async.commit_group;" ::: "memory");
    };

    const int m0 = (wid & 3) * 32;
    const int n0 = (wid >> 2) * 64;
    const int g    = lane >> 3;
    const int lr   = lane & 7;
    const int lrow = (g & 1) * 8 + lr;
    const int lkb  = (g >> 1) * 16;

    float acc[2][8][4] = {};

    issue(0); issue(1); issue(2);

    for (int c = 0; c < NC; ++c) {
        asm volatile("cp.async.wait_group 2;" ::: "memory");
        __syncthreads();
        const uint32_t sb = su + (uint32_t)(c % 3) * GF_STAGE;
#pragma unroll
        for (int kk = 0; kk < 4; ++kk) {
            uint32_t ah[2][4];
#pragma unroll
            for (int mt = 0; mt < 2; ++mt) {
                uint32_t off = sw128((uint32_t)((m0 + mt*16 + lrow) * 128 + kk*32 + lkb));
                ldsm4(sb + off, ah[mt]);
            }
#pragma unroll
            for (int np = 0; np < 4; ++np) {
                uint32_t boff = sw128((uint32_t)((n0 + np*16 + lrow) * 128 + kk*32 + lkb));
                uint32_t bh[4];
                ldsm4(sb + 16384 + boff, bh);
#pragma unroll
                for (int mt = 0; mt < 2; ++mt) {
                    mma_f16(acc[mt][2*np],   ah[mt], bh[0], bh[2]);
                    mma_f16(acc[mt][2*np+1], ah[mt], bh[1], bh[3]);
                }
            }
        }
        __syncthreads();
        if (c + 3 < NC) issue(c + 3);
        else asm volatile("cp.async.commit_group;" ::: "memory");
    }

    const int er = lane >> 2;
    const int ec = (lane & 3) * 2;
#pragma unroll
    for (int mt = 0; mt < 2; ++mt) {
#pragma unroll
        for (int nt = 0; nt < 8; ++nt) {
            const int row = bm + m0 + mt*16 + er;
            const int col = bn + n0 + nt*8 + ec;
            if (col < Nout) {
                if (OUT16) {
                    __half* C = (__half*)Cv + (size_t)blockIdx.z * strideC;
                    __half2 lo = __halves2half2(__float2half_rn(acc[mt][nt][0]),
                                                __float2half_rn(acc[mt][nt][1]));
                    __half2 hi = __halves2half2(__float2half_rn(acc[mt][nt][2]),
                                                __float2half_rn(acc[mt][nt][3]));
                    *(__half2*)(C + (size_t)row * Nout + col)       = lo;
                    *(__half2*)(C + (size_t)(row + 8) * Nout + col) = hi;
                } else {
                    float* C = (float*)Cv + (size_t)blockIdx.z * strideC;
                    float2 lo = { acc[mt][nt][0], acc[mt][nt][1] };
                    float2 hi = { acc[mt][nt][2], acc[mt][nt][3] };
                    *(float2*)(C + (size_t)row * Nout + col)       = lo;
                    *(float2*)(C + (size_t)(row + 8) * Nout + col) = hi;
                }
            }
        }
    }
}

// ---------------------------------------------------------------------------
// xproj tensor GEMM, M=64 CTA tile, 1-term. 3-stage ring (24KB/stage:
// A 8K | B 16K), 72KB smem, 2 CTA/SM.
// ---------------------------------------------------------------------------
constexpr int XP_STAGE = 24576;
constexpr int XP_SMEM  = 3 * XP_STAGE;   // 73728 B

__global__ void __launch_bounds__(256, 2) xproj_kernel()
{
    extern __shared__ __align__(1024) char smem[];
    const uint32_t su = smem_u32(smem);
    const int dir = blockIdx.z;
    const __half* Ah = &g_xth[dir][0];
    const __half* Bh = &g_wx[dir][0];
    float* C   = &g_dbl[dir][0];
    __half* dH = &g_dt_h[dir][0];
    __half* dL = &g_dt_l[dir][0];

    const int bm = blockIdx.y * 64;
    const int tid  = threadIdx.x;
    const int wid  = tid >> 5;
    const int lane = tid & 31;

    const int prow = tid >> 3;
    const int pkc  = tid & 7;
    auto issue = [&](int c) {
        const uint32_t sb = su + (uint32_t)(c % 3) * XP_STAGE;
        const int k0 = c * 64;
#pragma unroll
        for (int i = 0; i < 2; ++i) {
            const int row = prow + i * 32;
            const uint32_t off = sw128((uint32_t)(row * 128 + pkc * 16));
            const size_t ga = (size_t)(bm + row) * CDI + k0 + pkc * 8;
            cp16(sb + off, Ah + ga);
        }
#pragma unroll
        for (int i = 0; i < 4; ++i) {
            const int row = prow + i * 32;
            const uint32_t off = sw128((uint32_t)(row * 128 + pkc * 16));
            const size_t gb = (size_t)row * CDI + k0 + pkc * 8;
            cp16(sb + 8192 + off, Bh + gb);
        }
        asm volatile("cp.async.commit_group;" ::: "memory");
    };

    const int m0 = (wid & 1) * 32;
    const int n0 = (wid >> 1) * 32;
    const int g    = lane >> 3;
    const int lr   = lane & 7;
    const int lrow = (g & 1) * 8 + lr;
    const int lkb  = (g >> 1) * 16;

    float acc[2][4][4] = {};

    issue(0); issue(1); issue(2);

    const int NC = CDI / 64;
    for (int c = 0; c < NC; ++c) {
        asm volatile("cp.async.wait_group 2;" ::: "memory");
        __syncthreads();
        const uint32_t sb = su + (uint32_t)(c % 3) * XP_STAGE;
#pragma unroll
        for (int kk = 0; kk < 4; ++kk) {
            uint32_t ah[2][4];
#pragma unroll
            for (int mt = 0; mt < 2; ++mt) {
                uint32_t off = sw128((uint32_t)((m0 + mt*16 + lrow) * 128 + kk*32 + lkb));
                ldsm4(sb + off, ah[mt]);
            }
#pragma unroll
            for (int np = 0; np < 2; ++np) {
                uint32_t boff = sw128((uint32_t)((n0 + np*16 + lrow) * 128 + kk*32 + lkb));
                uint32_t bh[4];
                ldsm4(sb + 8192 + boff, bh);
#pragma unroll
                for (int mt = 0; mt < 2; ++mt) {
                    mma_f16(acc[mt][2*np],   ah[mt], bh[0], bh[2]);
                    mma_f16(acc[mt][2*np+1], ah[mt], bh[1], bh[3]);
                }
            }
        }
        __syncthreads();
        if (c + 3 < NC) issue(c + 3);
        else asm volatile("cp.async.commit_group;" ::: "memory");
    }

    const int er = lane >> 2;
    const int ec = (lane & 3) * 2;
#pragma unroll
    for (int mt = 0; mt < 2; ++mt) {
#pragma unroll
        for (int nt = 0; nt < 4; ++nt) {
            const int row0 = bm + m0 + mt*16 + er;
            const int col  = n0 + nt*8 + ec;
#pragma unroll
            for (int rr = 0; rr < 2; ++rr) {
                const int row = row0 + rr*8;
#pragma unroll
                for (int e = 0; e < 2; ++e) {
                    const int cc = col + e;
                    const float v = acc[mt][nt][rr*2+e];
                    if (cc < CRP) {
                        float dv = (cc < CR) ? v : 0.f;
                        __half hb = __float2half_rn(dv);
                        dH[(size_t)row * CRP + cc] = hb;
                        dL[(size_t)row * CRP + cc] =
                            __float2half_rn(dv - __half2float(hb));
                    }
                    if (cc >= CR && cc < CPROJ)
                        C[(size_t)row * CPROJ + cc] = v;
                }
            }
        }
    }
}

// ---------------------------------------------------------------------------
// dtproj tensor GEMM: delta[row,d] = softplus(sum_r dt[row,r]*W[d,r] + bias[d])
// Output stored fp16.
// ---------------------------------------------------------------------------
__device__ __forceinline__ float softplus_f(float v) {
    return (v > 20.f) ? v : log1pf(__expf(v));
}

__global__ void __launch_bounds__(256) dtgemm_kernel(
    const float* __restrict__ bias_f, const float* __restrict__ bias_b)
{
    extern __shared__ __align__(1024) char smem[];
    const uint32_t su = smem_u32(smem);
    const int dir = blockIdx.z;
    const __half* Ah = &g_dt_h[dir][0];
    const __half* Al = &g_dt_l[dir][0];
    const __half* Bh = &g_wdt_h[dir][0];
    const __half* Bl = &g_wdt_l[dir][0];
    const float* bias = dir ? bias_b : bias_f;
    __half* C = &g_delta[dir][0];

    const int bm = blockIdx.y * 128;
    const int bn = blockIdx.x * 128;
    const int tid  = threadIdx.x;
    const int wid  = tid >> 5;
    const int lane = tid & 31;

    const int prow = tid >> 3;
    const int pkc  = tid & 7;
#pragma unroll
    for (int i = 0; i < 4; ++i) {
        const int row = prow + i * 32;
        const uint32_t off = sw128((uint32_t)(row * 128 + pkc * 16));
        const size_t ga = (size_t)(bm + row) * CRP + pkc * 8;
        const size_t gb = (size_t)(bn + row) * CRP + pkc * 8;
        cp16(su + off,         Ah + ga);
        cp16(su + 16384 + off, Al + ga);
        cp16(su + 32768 + off, Bh + gb);
        cp16(su + 49152 + off, Bl + gb);
    }
    asm volatile("cp.async.commit_group;" ::: "memory");
    asm volatile("cp.async.wait_group 0;" ::: "memory");
    __syncthreads();

    const int m0 = (wid & 3) * 32;
    const int n0 = (wid >> 2) * 64;
    const int g    = lane >> 3;
    const int lr   = lane & 7;
    const int lrow = (g & 1) * 8 + lr;
    const int lkb  = (g >> 1) * 16;

    float acc[2][8][4] = {};
#pragma unroll
    for (int kk = 0; kk < 4; ++kk) {
        uint32_t ah[2][4], al[2][4];
#pragma unroll
        for (int mt = 0; mt < 2; ++mt) {
            uint32_t off = sw128((uint32_t)((m0 + mt*16 + lrow) * 128 + kk*32 + lkb));
            ldsm4(su + off,         ah[mt]);
            ldsm4(su + 16384 + off, al[mt]);
        }
#pragma unroll
        for (int np = 0; np < 4; ++np) {
            uint32_t boff = sw128((uint32_t)((n0 + np*16 + lrow) * 128 + kk*32 + lkb));
            uint32_t bh[4], bl[4];
            ldsm4(su + 32768 + boff, bh);
            ldsm4(su + 49152 + boff, bl);
#pragma unroll
            for (int mt = 0; mt < 2; ++mt) {
                mma_f16(acc[mt][2*np],   ah[mt], bh[0], bh[2]);
                mma_f16(acc[mt][2*np],   al[mt], bh[0], bh[2]);
                mma_f16(acc[mt][2*np],   ah[mt], bl[0], bl[2]);
                mma_f16(acc[mt][2*np+1], ah[mt], bh[1], bh[3]);
                mma_f16(acc[mt][2*np+1], al[mt], bh[1], bh[3]);
                mma_f16(acc[mt][2*np+1], ah[mt], bl[1], bl[3]);
            }
        }
    }

    const int er = lane >> 2;
    const int ec = (lane & 3) * 2;
#pragma unroll
    for (int mt = 0; mt < 2; ++mt) {
#pragma unroll
        for (int nt = 0; nt < 8; ++nt) {
            const int row = bm + m0 + mt*16 + er;
            const int col = bn + n0 + nt*8 + ec;
            const float b0 = bias[col], b1 = bias[col+1];
            __half2 lo = __halves2half2(
                __float2half_rn(softplus_f(acc[mt][nt][0] + b0)),
                __float2half_rn(softplus_f(acc[mt][nt][1] + b1)));
            __half2 hi = __halves2half2(
                __float2half_rn(softplus_f(acc[mt][nt][2] + b0)),
                __float2half_rn(softplus_f(acc[mt][nt][3] + b1)));
            *(__half2*)(C + (size_t)row * CDI + col)       = lo;
            *(__half2*)(C + (size_t)(row + 8) * CDI + col) = hi;
        }
    }
}

// ---------------------------------------------------------------------------
// Fused operand packer (single launch)
// ---------------------------------------------------------------------------
constexpr int PK_R0 = CB*CL*CDM/4;
constexpr int PK_R1 = PK_R0 + 2*CDI*CDM/4;
constexpr int PK_R2 = PK_R1 + CDM*CDI/4;
constexpr int PK_R3 = PK_R2 + 2*128*CDI/4;
constexpr int PK_R4 = PK_R3 + 2*CDI*CRP/4;

__device__ __forceinline__ uint2 pack4_f16(float4 v) {
    __half2 h01 = __halves2half2(__float2half_rn(v.x), __float2half_rn(v.y));
    __half2 h23 = __halves2half2(__float2half_rn(v.z), __float2half_rn(v.w));
    return make_uint2(*(uint32_t*)&h01, *(uint32_t*)&h23);
}

__global__ void pack_kernel(
    const float* __restrict__ hidden, const float* __restrict__ in_w,
    const float* __restrict__ out_w,
    const float* __restrict__ xw_f, const float* __restrict__ xw_b,
    const float* __restrict__ dw_f, const float* __restrict__ dw_b)
{
    for (int i = blockIdx.x * blockDim.x + threadIdx.x; i < PK_R4;
         i += gridDim.x * blockDim.x) {
        if (i < PK_R0) {
            ((uint2*)g_hid_h)[i] = pack4_f16(((const float4*)hidden)[i]);
        } else if (i < PK_R1) {
            int j = i - PK_R0;
            ((uint2*)g_w1)[j] = pack4_f16(((const float4*)in_w)[j]);
        } else if (i < PK_R2) {
            int j = i - PK_R1;
            ((uint2*)g_w2)[j] = pack4_f16(((const float4*)out_w)[j]);
        } else if (i < PK_R3) {
            int j = i - PK_R2;
            int e = j * 4;
            int dir = e / (128 * CDI);
            int rem = e - dir * 128 * CDI;
            int row = rem / CDI;
            int k   = rem - row * CDI;
            float4 v = {0.f, 0.f, 0.f, 0.f};
            const float* W = dir ? xw_b : xw_f;
            if (row < CPROJ) v = *(const float4*)(W + (size_t)row * CDI + k);
            ((uint2*)&g_wx[0][0])[j] = pack4_f16(v);
        } else {
            int j = i - PK_R3;
            int e = j * 4;
            int dir = e / (CDI * CRP);
            int rem = e - dir * CDI * CRP;
            int row = rem / CRP;
            int k   = rem - row * CRP;
            float4 v = {0.f, 0.f, 0.f, 0.f};
            const float* W = dir ? dw_b : dw_f;
            if (k < CR) v = *(const float4*)(W + (size_t)row * CR + k);
            __half hx = __float2half_rn(v.x), hy = __float2half_rn(v.y);
            __half hz = __float2half_rn(v.z), hw = __float2half_rn(v.w);
            __half lx = __float2half_rn(v.x - __half2float(hx));
            __half ly = __float2half_rn(v.y - __half2float(hy));
            __half lz = __float2half_rn(v.z - __half2float(hz));
            __half lw = __float2half_rn(v.w - __half2float(hw));
            __half2 h01 = __halves2half2(hx, hy), h23 = __halves2half2(hz, hw);
            __half2 l01 = __halves2half2(lx, ly), l23 = __halves2half2(lz, lw);
            ((uint2*)&g_wdt_h[0][0])[j] = make_uint2(*(uint32_t*)&h01, *(uint32_t*)&h23);
            ((uint2*)&g_wdt_l[0][0])[j] = make_uint2(*(uint32_t*)&l01, *(uint32_t*)&l23);
        }
    }
}

// ---------------------------------------------------------------------------
// Depthwise causal conv (K=4) + bias + SiLU, transpose to (b,t,d).
// MERGED DIRECTIONS; single-fp16 xt output.
// ---------------------------------------------------------------------------
__global__ void __launch_bounds__(256) conv_silu_kernel(
    const float* __restrict__ cw_f, const float* __restrict__ cb_f,
    const float* __restrict__ cw_b, const float* __restrict__ cb_b)
{
    const int t0 = blockIdx.x * 128;
    const int d0 = blockIdx.y * 32;
    const int b  = blockIdx.z;

    __shared__ float xs[32][135];

    const __half* xbase = g_xz + ((size_t)b * (2*CDI) + d0) * CL;
    const int base = t0 - 3;

    const int lane = threadIdx.x & 31;
    const int wy   = threadIdx.x >> 5;
    for (int d = wy; d < 32; d += 8) {
        const __half* row = xbase + (size_t)d * CL;
        for (int i = lane; i < 134; i += 32) {
            int u = base + i;
            xs[d][i] = (u >= 0 && u < CL) ? __half2float(row[u]) : 0.f;
        }
    }
    __syncthreads();

    const int d  = threadIdx.x & 31;
    const int sg = threadIdx.x >> 5;
    const float wf0 = cw_f[(d0+d)*CK + 0];
    const float wf1 = cw_f[(d0+d)*CK + 1];
    const float wf2 = cw_f[(d0+d)*CK + 2];
    const float wf3 = cw_f[(d0+d)*CK + 3];
    const float bf  = cb_f[d0+d];
    const float wb0 = cw_b[(d0+d)*CK + 0];
    const float wb1 = cw_b[(d0+d)*CK + 1];
    const float wb2 = cw_b[(d0+d)*CK + 2];
    const float wb3 = cw_b[(d0+d)*CK + 3];
    const float bb  = cb_b[d0+d];

    __half* ohf = g_xth[0] + (size_t)b * CL * CDI;
    __half* ohb = g_xth[1] + (size_t)b * CL * CDI;
    const int tb0 = CL - 128 - t0;
#pragma unroll
    for (int q = 0; q < 16; ++q) {
        int s = sg + 8*q;
        {
            float v = wf0*xs[d][s] + wf1*xs[d][s+1] + wf2*xs[d][s+2] + wf3*xs[d][s+3] + bf;
            float sv = v / (1.f + __expf(-v));
            ohf[(size_t)(t0 + s) * CDI + d0 + d] = __float2half_rn(sv);
        }
        {
            float v = wb3*xs[d][130-s] + wb2*xs[d][131-s] + wb1*xs[d][132-s]
                    + wb0*xs[d][133-s] + bb;
            float sv = v / (1.f + __expf(-v));
            ohb[(size_t)(tb0 + s) * CDI + d0 + d] = __float2half_rn(sv);
        }
    }
}

// ---------------------------------------------------------------------------
// Selective scan, 2-states-per-lane; B/C interleaved in one smem array so
// each step does 2x LDS.64 instead of 4x LDS.32. Values identical.
// ---------------------------------------------------------------------------
__global__ void __launch_bounds__(128) scan_kernel(
    const float* __restrict__ Alog_f, const float* __restrict__ Dv_f,
    const float* __restrict__ Alog_b, const float* __restrict__ Dv_b)
{
    const int dir = blockIdx.z;
    const int b   = blockIdx.y;
    const int d0  = blockIdx.x * 16;

    const float* Alog = dir ? Alog_b : Alog_f;
    const float* Dvec = dir ? Dv_b   : Dv_f;
    const __half* delta = g_delta[dir] + (size_t)b * CL * CDI;
    const __half* xth  = g_xth[dir]   + (size_t)b * CL * CDI;
    const float* dbl   = g_dbl[dir]   + (size_t)b * CL * CPROJ;
    __half* yout       = g_y[dir]     + (size_t)b * CL * CDI;

    __shared__ __align__(16) float sd[64][16];   // dt
    __shared__ __align__(16) float sx[64][16];   // dt*x
    __shared__ __align__(16) float sbc[64][32];  // interleaved (B,C) pairs
    __shared__ __align__(16) float sxD[64][16];  // x*D

    const int tid  = threadIdx.x;
    const int lane = tid & 31;
    const int wid  = tid >> 5;
    const int ch   = wid*4 + (lane >> 3);
    const int n    = lane & 7;
    const int d    = d0 + ch;

    constexpr float LOG2E = 1.4426950408889634f;
    const float Aval0 = -__expf(Alog[d*CN + n])     * LOG2E;
    const float Aval1 = -__expf(Alog[d*CN + n + 8]) * LOG2E;
    float h0 = 0.f, h1 = 0.f;

    const int li = tid >> 1;
    const int lj = (tid & 1) * 8;

    float rDv[8];
#pragma unroll
    for (int j = 0; j < 8; ++j) rDv[j] = Dvec[d0 + lj + j];

    float rd[8], rx[8], rB[8], rC[8];
    auto LD = [&](int t0) {
        uint4 dv = *(const uint4*)(delta + (size_t)(t0+li)*CDI + d0 + lj);
        const uint32_t* dvp = &dv.x;
#pragma unroll
        for (int q = 0; q < 4; ++q) {
            float2 f = __half22float2(*(const __half2*)&dvp[q]);
            rd[2*q+0] = f.x; rd[2*q+1] = f.y;
        }
        uint4 xh = *(const uint4*)(xth + (size_t)(t0+li)*CDI + d0 + lj);
        const uint32_t* xhp = &xh.x;
#pragma unroll
        for (int q = 0; q < 4; ++q) {
            float2 fh = __half22float2(*(const __half2*)&xhp[q]);
            rx[2*q+0] = fh.x;
            rx[2*q+1] = fh.y;
        }
        float4 b0v = *(const float4*)(dbl + (size_t)(t0+li)*CPROJ + CR + lj);
        float4 b1v = *(const float4*)(dbl + (size_t)(t0+li)*CPROJ + CR + lj + 4);
        rB[0]=b0v.x; rB[1]=b0v.y; rB[2]=b0v.z; rB[3]=b0v.w;
        rB[4]=b1v.x; rB[5]=b1v.y; rB[6]=b1v.z; rB[7]=b1v.w;
        float4 c0v = *(const float4*)(dbl + (size_t)(t0+li)*CPROJ + CR + CN + lj);
        float4 c1v = *(const float4*)(dbl + (size_t)(t0+li)*CPROJ + CR + CN + lj + 4);
        rC[0]=c0v.x; rC[1]=c0v.y; rC[2]=c0v.z; rC[3]=c0v.w;
        rC[4]=c1v.x; rC[5]=c1v.y; rC[6]=c1v.z; rC[7]=c1v.w;
    };
    LD(0);

    const int NCH = CL / 64;
    for (int c = 0; c < NCH; ++c) {
        __syncthreads();
        {
            float4 v;
            v = make_float4(rd[0], rd[1], rd[2], rd[3]);            *(float4*)&sd[li][lj]   = v;
            v = make_float4(rd[4], rd[5], rd[6], rd[7]);            *(float4*)&sd[li][lj+4] = v;
            v = make_float4(rd[0]*rx[0], rd[1]*rx[1], rd[2]*rx[2], rd[3]*rx[3]); *(float4*)&sx[li][lj]   = v;
            v = make_float4(rd[4]*rx[4], rd[5]*rx[5], rd[6]*rx[6], rd[7]*rx[7]); *(float4*)&sx[li][lj+4] = v;
            // interleaved (B,C): column 2j holds B[j], 2j+1 holds C[j]
            v = make_float4(rB[0], rC[0], rB[1], rC[1]); *(float4*)&sbc[li][2*lj]      = v;
            v = make_float4(rB[2], rC[2], rB[3], rC[3]); *(float4*)&sbc[li][2*lj + 4]  = v;
            v = make_float4(rB[4], rC[4], rB[5], rC[5]); *(float4*)&sbc[li][2*lj + 8]  = v;
            v = make_float4(rB[6], rC[6], rB[7], rC[7]); *(float4*)&sbc[li][2*lj + 12] = v;
            v = make_float4(rx[0]*rDv[0], rx[1]*rDv[1], rx[2]*rDv[2], rx[3]*rDv[3]); *(float4*)&sxD[li][lj]   = v;
            v = make_float4(rx[4]*rDv[4], rx[5]*rDv[5], rx[6]*rDv[6], rx[7]*rDv[7]); *(float4*)&sxD[li][lj+4] = v;
        }
        __syncthreads();
        if (c + 1 < NCH) LD((c+1) * 64);

        const int tbase = c * 64;
#pragma unroll 8
        for (int s = 0; s < 64; ++s) {
            float dt  = sd[s][ch];
            float dtx = sx[s][ch];
            float2 bc0 = *(const float2*)&sbc[s][2*n];
            float2 bc1 = *(const float2*)&sbc[s][2*(n + 8)];
            float a0 = ex2f(dt * Aval0);
            float a1 = ex2f(dt * Aval1);
            h0 = fmaf(a0, h0, dtx * bc0.x);
            h1 = fmaf(a1, h1, dtx * bc1.x);
            float p = fmaf(h1, bc1.y, h0 * bc0.y);
            p += __shfl_xor_sync(0xffffffffu, p, 4);
            p += __shfl_xor_sync(0xffffffffu, p, 2);
            p += __shfl_xor_sync(0xffffffffu, p, 1);
            if (n == 0)
                yout[(size_t)(tbase + s)*CDI + d] = __float2half_rn(p + sxD[s][ch]);
        }
    }
}

// ---------------------------------------------------------------------------
// Gate + direction merge -> single fp16 comb
// ---------------------------------------------------------------------------
__global__ void __launch_bounds__(256) combine_kernel()
{
    const int l0 = blockIdx.x * 32;
    const int d0 = blockIdx.y * 32;
    const int b  = blockIdx.z;

    __shared__ float zs[32][33];
    const int lane = threadIdx.x & 31;
    const int wy   = threadIdx.x >> 5;

    const __half* zbase = g_xz + ((size_t)b * (2*CDI) + CDI + d0) * CL;
    for (int dd = wy; dd < 32; dd += 8)
        zs[dd][lane] = __half2float(zbase[(size_t)dd * CL + l0 + lane]);
    __syncthreads();

#pragma unroll
    for (int q = 0; q < 4; ++q) {
        int lr = wy + 8*q;
        int l = l0 + lr;
        size_t idx  = ((size_t)b*CL + l)*CDI + d0 + lane;
        size_t idxr = ((size_t)b*CL + (CL-1-l))*CDI + d0 + lane;
        float yf = __half2float(g_y[0][idx]);
        float yb = __half2float(g_y[1][idxr]);
        float zv = zs[lane][lr];
        float s = zv / (1.f + __expf(-zv));
        float cv = (yf + yb) * s;
        g_cmb_h[idx] = __float2half_rn(cv);
    }
}

// ---------------------------------------------------------------------------
// Launcher
// ---------------------------------------------------------------------------
extern "C" void kernel_launch(void* const* d_in, const int* in_sizes, int n_in,
                              void* d_out, int out_size)
{
    (void)in_sizes; (void)n_in; (void)out_size;

    const float* hidden  = (const float*)d_in[0];
    const float* in_w    = (const float*)d_in[1];
    const float* conv_w  = (const float*)d_in[2];
    const float* conv_b  = (const float*)d_in[3];
    const float* xproj_w = (const float*)d_in[4];
    const float* dtw     = (const float*)d_in[5];
    const float* dtb     = (const float*)d_in[6];
    const float* A_log   = (const float*)d_in[7];
    const float* Dv      = (const float*)d_in[8];
    const float* conv_w2 = (const float*)d_in[9];
    const float* conv_b2 = (const float*)d_in[10];
    const float* xproj_w2= (const float*)d_in[11];
    const float* dtw2    = (const float*)d_in[12];
    const float* dtb2    = (const float*)d_in[13];
    const float* A_log2  = (const float*)d_in[14];
    const float* Dv2     = (const float*)d_in[15];
    const float* out_w   = (const float*)d_in[16];

    void *p_xz, *p_hid_h, *p_w1, *p_w2, *p_cmb_h;
    cudaGetSymbolAddress(&p_xz, g_xz);
    cudaGetSymbolAddress(&p_hid_h, g_hid_h);
    cudaGetSymbolAddress(&p_w1, g_w1);
    cudaGetSymbolAddress(&p_w2, g_w2);
    cudaGetSymbolAddress(&p_cmb_h, g_cmb_h);

    cudaFuncSetAttribute(gemm_f16_kernel<0>,
                         cudaFuncAttributeMaxDynamicSharedMemorySize, GF_SMEM);
    cudaFuncSetAttribute(gemm_f16_kernel<1>,
                         cudaFuncAttributeMaxDynamicSharedMemorySize, GF_SMEM);
    cudaFuncSetAttribute(xproj_kernel,
                         cudaFuncAttributeMaxDynamicSharedMemorySize, XP_SMEM);
    cudaFuncSetAttribute(dtgemm_kernel,
                         cudaFuncAttributeMaxDynamicSharedMemorySize, 65536);

    // 0) fused operand packing
    pack_kernel<<<2048, 256>>>(hidden, in_w, out_w, xproj_w, xproj_w2, dtw, dtw2);

    // 1) in_proj, 1-term, fp16 out: A = w1, B = hidden.  M=3072, N=4096, K=768
    gemm_f16_kernel<1><<<dim3(CL/128, (2*CDI)/128, CB), 256, GF_SMEM>>>(
        (const __half*)p_w1, (const __half*)p_hid_h,
        p_xz, CL, CDM,
        0, (long long)CL * CDM, (long long)(2*CDI) * CL, CDM / 64);

    // 2) conv + SiLU + transpose (both dirs per block) -> fp16 xt
    conv_silu_kernel<<<dim3(CL/128, CDI/32, CB), 256>>>(
        conv_w, conv_b, conv_w2, conv_b2);

    // 3) xproj, M=64 tiles, 1-term: dt fp16 hi/lo + fp32 B|C
    xproj_kernel<<<dim3(1, (CB*CL)/64, 2), 256, XP_SMEM>>>();

    // 4) dtproj as tensor GEMM + softplus -> delta (fp16)
    dtgemm_kernel<<<dim3(CDI/128, (CB*CL)/128, 2), 256, 65536>>>(dtb, dtb2);

    // 5) selective scan -> y (fp16)
    scan_kernel<<<dim3(CDI/16, CB, 2), 128>>>(A_log, Dv, A_log2, Dv2);

    // 6) gate + direction merge -> single fp16 comb
    combine_kernel<<<dim3(CL/32, CDI/32, CB), 256>>>();

    // 7) out_proj, 1-term, fp32 out: A = comb, B = w2.  M=8192, N=768, K=1536
    gemm_f16_kernel<0><<<dim3(CDM/128, (CB*CL)/128, 1), 256, GF_SMEM>>>(
        (const __half*)p_cmb_h, (const __half*)p_w2,
        d_out, CDM, CDI,
        0, 0, 0, CDI / 64);
}